// round 6
// baseline (speedup 1.0000x reference)
#include <cuda_runtime.h>
#include <cuda_bf16.h>
#include <stdint.h>
#include <math.h>

#define T_TOK 2048
#define H_DIM 2048
#define I_DIM 1024
#define N_EXP 16
#define TOPK  4
#define NGRP  4
#define GSZ   4
#define SCALING 2.5f

#define STAGE_BYTES 40960u
#define N_STAGES    3
#define SMEM_DYN    (N_STAGES * STAGE_BYTES)

// ---------------------------------------------------------------------------
// Scratch (device globals — no allocation allowed)
// ---------------------------------------------------------------------------
__device__ int   d_counts[N_EXP];
__device__ int   d_tok[N_EXP][T_TOK];
__device__ float d_wgt[N_EXP][T_TOK];
// SwiGLU hidden, bf16 hi/lo planes
__device__ __nv_bfloat16 d_h1_hi[N_EXP][T_TOK][I_DIM];
__device__ __nv_bfloat16 d_h1_lo[N_EXP][T_TOK][I_DIM];
__device__ __nv_bfloat16 d_h1s_hi[T_TOK][I_DIM];
__device__ __nv_bfloat16 d_h1s_lo[T_TOK][I_DIM];
// pre-split inputs/weights (hi/lo bf16 planes)
__device__ __nv_bfloat16 d_xh[T_TOK * H_DIM],          d_xl[T_TOK * H_DIM];
__device__ __nv_bfloat16 d_gph[N_EXP * I_DIM * H_DIM], d_gpl[N_EXP * I_DIM * H_DIM];
__device__ __nv_bfloat16 d_uph[N_EXP * I_DIM * H_DIM], d_upl[N_EXP * I_DIM * H_DIM];
__device__ __nv_bfloat16 d_dph[N_EXP * H_DIM * I_DIM], d_dpl[N_EXP * H_DIM * I_DIM];
__device__ __nv_bfloat16 d_sgh[I_DIM * H_DIM],         d_sgl[I_DIM * H_DIM];
__device__ __nv_bfloat16 d_suh[I_DIM * H_DIM],         d_sul[I_DIM * H_DIM];
__device__ __nv_bfloat16 d_sdh[H_DIM * I_DIM],         d_sdl[H_DIM * I_DIM];

// ---------------------------------------------------------------------------
// PTX helpers (baseline sm_80+ only — must compile under compute_103)
// ---------------------------------------------------------------------------
__device__ __forceinline__ uint32_t smem_u32(const void* p) {
    uint32_t a;
    asm("{ .reg .u64 t; cvta.to.shared.u64 t, %1; cvt.u32.u64 %0, t; }"
        : "=r"(a) : "l"(p));
    return a;
}

__device__ __forceinline__ void ldm_x4(uint32_t addr, uint32_t r[4]) {
    asm volatile("ldmatrix.sync.aligned.m8n8.x4.shared.b16 {%0,%1,%2,%3}, [%4];"
                 : "=r"(r[0]), "=r"(r[1]), "=r"(r[2]), "=r"(r[3]) : "r"(addr));
}

__device__ __forceinline__ void mma_bf16(float d[4], const uint32_t a[4],
                                         uint32_t b0, uint32_t b1) {
    asm volatile(
        "mma.sync.aligned.m16n8k16.row.col.f32.bf16.bf16.f32 "
        "{%0,%1,%2,%3}, {%4,%5,%6,%7}, {%8,%9}, {%0,%1,%2,%3};"
        : "+f"(d[0]), "+f"(d[1]), "+f"(d[2]), "+f"(d[3])
        : "r"(a[0]), "r"(a[1]), "r"(a[2]), "r"(a[3]), "r"(b0), "r"(b1));
}

#define CP_ASYNC16(dst, src) \
    asm volatile("cp.async.cg.shared.global [%0], [%1], 16;" \
                 :: "r"(dst), "l"(src) : "memory")
#define CP_COMMIT()  asm volatile("cp.async.commit_group;" ::: "memory")
#define CP_WAIT1()   asm volatile("cp.async.wait_group 1;" ::: "memory")

__device__ __forceinline__ void split2(float f0, float f1, uint32_t& hw, uint32_t& lw) {
    __nv_bfloat16 h0 = __float2bfloat16_rn(f0);
    __nv_bfloat16 h1 = __float2bfloat16_rn(f1);
    __nv_bfloat16 l0 = __float2bfloat16_rn(f0 - __bfloat162float(h0));
    __nv_bfloat16 l1 = __float2bfloat16_rn(f1 - __bfloat162float(h1));
    hw = (uint32_t)__bfloat16_as_ushort(h0) | ((uint32_t)__bfloat16_as_ushort(h1) << 16);
    lw = (uint32_t)__bfloat16_as_ushort(l0) | ((uint32_t)__bfloat16_as_ushort(l1) << 16);
}

__device__ __forceinline__ void split4(float4 f, uint2& hw, uint2& lw) {
    split2(f.x, f.y, hw.x, lw.x);
    split2(f.z, f.w, hw.y, lw.y);
}

// stage-relative ldmatrix offset within a padded [rows][40] bf16 plane
__device__ __forceinline__ uint32_t ldrel(uint32_t plane, int rbase, int lane) {
    int row = rbase + (lane & 15);
    int col = (lane >> 4) << 3;
    return plane + (uint32_t)((row * 40 + col) << 1);
}

// ---------------------------------------------------------------------------
// fp32 -> bf16 hi/lo split (grid-stride, memory bound)
// ---------------------------------------------------------------------------
__global__ __launch_bounds__(256) void split_kernel(
    const float4* __restrict__ src, uint2* __restrict__ hi,
    uint2* __restrict__ lo, int n4)
{
    int i = blockIdx.x * blockDim.x + threadIdx.x;
    int stride = gridDim.x * blockDim.x;
    for (; i < n4; i += stride) {
        float4 f = src[i];
        uint2 h, l; split4(f, h, l);
        hi[i] = h; lo[i] = l;
    }
}

// ---------------------------------------------------------------------------
// Routing (proven)
// ---------------------------------------------------------------------------
__global__ void zero_counts_kernel() {
    if (threadIdx.x < N_EXP) d_counts[threadIdx.x] = 0;
}

__global__ __launch_bounds__(256) void route_kernel(
    const float* __restrict__ x, const float* __restrict__ gw,
    const float* __restrict__ bias)
{
    __shared__ float xs[H_DIM];
    __shared__ float logits[N_EXP];
    const int t = blockIdx.x;
    const float* xr = x + (size_t)t * H_DIM;
    for (int i = threadIdx.x; i < H_DIM; i += blockDim.x) xs[i] = xr[i];
    __syncthreads();

    const int e = threadIdx.x >> 4, lane = threadIdx.x & 15;
    const float* g = gw + (size_t)e * H_DIM;
    float s = 0.f;
    for (int k = lane; k < H_DIM; k += 16) s += xs[k] * g[k];
    #pragma unroll
    for (int o = 8; o > 0; o >>= 1) s += __shfl_down_sync(0xffffffffu, s, o, 16);
    if (lane == 0) logits[e] = s;
    __syncthreads();

    if (threadIdx.x == 0) {
        float sc[N_EXP], bs[N_EXP];
        #pragma unroll
        for (int i = 0; i < N_EXP; i++) {
            sc[i] = 1.f / (1.f + expf(-logits[i]));
            bs[i] = sc[i] + bias[i];
        }
        float gsc[NGRP];
        #pragma unroll
        for (int gi = 0; gi < NGRP; gi++) {
            float m1 = -1e30f, m2 = -1e30f;
            #pragma unroll
            for (int j = 0; j < GSZ; j++) {
                float v = bs[gi * GSZ + j];
                if (v > m1) { m2 = m1; m1 = v; } else if (v > m2) { m2 = v; }
            }
            gsc[gi] = m1 + m2;
        }
        int g1 = 0;
        for (int gi = 1; gi < NGRP; gi++) if (gsc[gi] > gsc[g1]) g1 = gi;
        int g2 = -1;
        for (int gi = 0; gi < NGRP; gi++) {
            if (gi == g1) continue;
            if (g2 < 0 || gsc[gi] > gsc[g2]) g2 = gi;
        }
        bool allowed[N_EXP], used[N_EXP];
        #pragma unroll
        for (int i = 0; i < N_EXP; i++) {
            int gi = i / GSZ;
            allowed[i] = (gi == g1 || gi == g2);
            used[i] = false;
        }
        int sel[TOPK]; float wv[TOPK]; float wsum = 0.f;
        #pragma unroll
        for (int kk = 0; kk < TOPK; kk++) {
            int best = -1; float bv = -1e30f;
            for (int i = 0; i < N_EXP; i++) {
                if (!allowed[i] || used[i]) continue;
                if (best < 0 || bs[i] > bv) { best = i; bv = bs[i]; }
            }
            used[best] = true; sel[kk] = best; wv[kk] = sc[best]; wsum += sc[best];
        }
        const float inv = SCALING / (wsum + 1e-20f);
        #pragma unroll
        for (int kk = 0; kk < TOPK; kk++) {
            int ee = sel[kk];
            int slot = atomicAdd(&d_counts[ee], 1);
            d_tok[ee][slot] = t;
            d_wgt[ee][slot] = wv[kk] * inv;
        }
    }
}

// ---------------------------------------------------------------------------
// GEMM1: 512 threads (16 warps = 4m x 4n), CTA tile M=128 x N=64 x BK=32.
// 3-stage cp.async pipeline; operands pre-split bf16 hi/lo.
// Stage planes: AH 0, AL 10240, GH 20480, GL 25600, UH 30720, UL 35840.
// ---------------------------------------------------------------------------
template<bool SHARED>
__global__ __launch_bounds__(512) void gemm1_mma(int dummy)
{
    const int e  = SHARED ? 0 : blockIdx.z;
    const int ne = SHARED ? T_TOK : d_counts[e];
    const int m0 = blockIdx.y * 128;
    if (m0 >= ne) return;
    const int n0 = blockIdx.x * 64;

    extern __shared__ __align__(16) char dynsmem[];
    __shared__ int toks[128];

    const int tid = threadIdx.x, lane = tid & 31, wid = tid >> 5;
    const int wm = wid >> 2, wn = wid & 3;
    const uint32_t sb = smem_u32(dynsmem);

    if (tid < 128) {
        int r = m0 + tid;
        toks[tid] = SHARED ? r : (r < ne ? d_tok[e][r] : d_tok[e][0]);
    }
    __syncthreads();

    const size_t eoff = SHARED ? 0 : (size_t)e * I_DIM * H_DIM;
    const __nv_bfloat16* ghP = SHARED ? d_sgh : d_gph + eoff;
    const __nv_bfloat16* glP = SHARED ? d_sgl : d_gpl + eoff;
    const __nv_bfloat16* uhP = SHARED ? d_suh : d_uph + eoff;
    const __nv_bfloat16* ulP = SHARED ? d_sul : d_upl + eoff;

    // per-thread cp.async chunk decode (A: 1024 chunks, B: 1024 chunks)
    int aPl[2], aR[2], aCh[2], bPl[2], bR[2], bCh[2];
    uint32_t aDst[2], bDst[2];
    #pragma unroll
    for (int i = 0; i < 2; i++) {
        int c = tid + 512 * i;
        aPl[i] = c >> 9; aR[i] = (c & 511) >> 2; aCh[i] = c & 3;
        aDst[i] = (uint32_t)(aPl[i] * 10240 + aR[i] * 80 + aCh[i] * 16);
        bPl[i] = c >> 8; bR[i] = (c & 255) >> 2; bCh[i] = c & 3;
        bDst[i] = (uint32_t)(20480 + bPl[i] * 5120 + bR[i] * 80 + bCh[i] * 16);
    }

    // precomputed ldmatrix stage-relative offsets
    uint32_t rAh[2], rAl[2];
    #pragma unroll
    for (int mi = 0; mi < 2; mi++) {
        rAh[mi] = ldrel(0u,     wm * 32 + mi * 16, lane);
        rAl[mi] = ldrel(10240u, wm * 32 + mi * 16, lane);
    }
    const uint32_t rGh = ldrel(20480u, wn * 16, lane);
    const uint32_t rGl = ldrel(25600u, wn * 16, lane);
    const uint32_t rUh = ldrel(30720u, wn * 16, lane);
    const uint32_t rUl = ldrel(35840u, wn * 16, lane);

    // issue one stage's cp.asyncs
    auto issue = [&](int kt) {
        const uint32_t st = sb + (uint32_t)(kt % N_STAGES) * STAGE_BYTES;
        const int k0 = kt * 32;
        #pragma unroll
        for (int i = 0; i < 2; i++) {
            const __nv_bfloat16* src = (aPl[i] ? d_xl : d_xh)
                + (size_t)toks[aR[i]] * H_DIM + k0 + aCh[i] * 8;
            CP_ASYNC16(st + aDst[i], src);
        }
        #pragma unroll
        for (int i = 0; i < 2; i++) {
            const __nv_bfloat16* base =
                (bPl[i] == 0) ? ghP : (bPl[i] == 1) ? glP : (bPl[i] == 2) ? uhP : ulP;
            const __nv_bfloat16* src = base + (size_t)(n0 + bR[i]) * H_DIM + k0 + bCh[i] * 8;
            CP_ASYNC16(st + bDst[i], src);
        }
    };

    float cg[2][2][4] = {}, cu[2][2][4] = {};

    issue(0); CP_COMMIT();
    issue(1); CP_COMMIT();

    const int NK = H_DIM / 32;
    #pragma unroll 1
    for (int kt = 0; kt < NK; ++kt) {
        CP_WAIT1();
        __syncthreads();
        if (kt + 2 < NK) issue(kt + 2);
        CP_COMMIT();

        const uint32_t cur = sb + (uint32_t)(kt % N_STAGES) * STAGE_BYTES;
        #pragma unroll
        for (int kk = 0; kk < 2; ++kk) {
            const uint32_t kb = cur + (uint32_t)(kk * 32);
            uint32_t ah[2][4], al[2][4];
            #pragma unroll
            for (int mi = 0; mi < 2; mi++) {
                ldm_x4(kb + rAh[mi], ah[mi]);
                ldm_x4(kb + rAl[mi], al[mi]);
            }
            uint32_t gh[4], gl[4], uh[4], ul[4];
            ldm_x4(kb + rGh, gh);
            ldm_x4(kb + rGl, gl);
            ldm_x4(kb + rUh, uh);
            ldm_x4(kb + rUl, ul);

            #pragma unroll
            for (int mi = 0; mi < 2; mi++)
                #pragma unroll
                for (int ni = 0; ni < 2; ni++) {
                    mma_bf16(cg[mi][ni], ah[mi], gh[ni], gh[ni + 2]);
                    mma_bf16(cg[mi][ni], ah[mi], gl[ni], gl[ni + 2]);
                    mma_bf16(cg[mi][ni], al[mi], gh[ni], gh[ni + 2]);
                    mma_bf16(cu[mi][ni], ah[mi], uh[ni], uh[ni + 2]);
                    mma_bf16(cu[mi][ni], ah[mi], ul[ni], ul[ni + 2]);
                    mma_bf16(cu[mi][ni], al[mi], uh[ni], uh[ni + 2]);
                }
        }
        __syncthreads();
    }

    // epilogue: silu(g)*u -> bf16 hi/lo planes
    const int gr = lane >> 2, tc = (lane & 3) * 2;
    __nv_bfloat16* phi = SHARED ? &d_h1s_hi[0][0] : &d_h1_hi[e][0][0];
    __nv_bfloat16* plo = SHARED ? &d_h1s_lo[0][0] : &d_h1_lo[e][0][0];

    #pragma unroll
    for (int mi = 0; mi < 2; mi++)
        #pragma unroll
        for (int ni = 0; ni < 2; ni++) {
            int ncol = n0 + wn * 16 + ni * 8 + tc;
            #pragma unroll
            for (int half = 0; half < 2; half++) {
                int m = m0 + wm * 32 + mi * 16 + gr + half * 8;
                float g0 = cg[mi][ni][half * 2],     u0 = cu[mi][ni][half * 2];
                float g1 = cg[mi][ni][half * 2 + 1], u1 = cu[mi][ni][half * 2 + 1];
                float o0 = (g0 / (1.f + expf(-g0))) * u0;
                float o1 = (g1 / (1.f + expf(-g1))) * u1;
                uint32_t hw, lw; split2(o0, o1, hw, lw);
                *(uint32_t*)(phi + (size_t)m * I_DIM + ncol) = hw;
                *(uint32_t*)(plo + (size_t)m * I_DIM + ncol) = lw;
            }
        }
}

// ---------------------------------------------------------------------------
// GEMM2: 512 threads (16 warps = 4m x 4n), CTA tile M=128 x N=128 x BK=32.
// Stage planes: AH 0, AL 10240, BH 20480, BL 30720.
// ---------------------------------------------------------------------------
template<bool SHARED>
__global__ __launch_bounds__(512) void gemm2_mma(float* __restrict__ out)
{
    const int e  = SHARED ? 0 : blockIdx.z;
    const int ne = SHARED ? T_TOK : d_counts[e];
    const int m0 = blockIdx.y * 128;
    if (m0 >= ne) return;
    const int n0 = blockIdx.x * 128;

    extern __shared__ __align__(16) char dynsmem[];
    __shared__ int   toks[128];
    __shared__ float wgts[128];

    const int tid = threadIdx.x, lane = tid & 31, wid = tid >> 5;
    const int wm = wid >> 2, wn = wid & 3;
    const uint32_t sb = smem_u32(dynsmem);

    if (!SHARED && tid < 128) {
        int r = m0 + tid;
        toks[tid] = (r < ne) ? d_tok[e][r] : 0;
        wgts[tid] = (r < ne) ? d_wgt[e][r] : 0.f;
    }
    __syncthreads();

    const __nv_bfloat16* ahi = SHARED ? &d_h1s_hi[0][0] : &d_h1_hi[e][0][0];
    const __nv_bfloat16* alo = SHARED ? &d_h1s_lo[0][0] : &d_h1_lo[e][0][0];
    const size_t eoff = SHARED ? 0 : (size_t)e * H_DIM * I_DIM;
    const __nv_bfloat16* dwh = SHARED ? d_sdh : d_dph + eoff;
    const __nv_bfloat16* dwl = SHARED ? d_sdl : d_dpl + eoff;

    int cPl[2], cR[2], cCh[2];
    uint32_t aDst[2], bDst[2];
    #pragma unroll
    for (int i = 0; i < 2; i++) {
        int c = tid + 512 * i;
        cPl[i] = c >> 9; cR[i] = (c & 511) >> 2; cCh[i] = c & 3;
        aDst[i] = (uint32_t)(cPl[i] * 10240 + cR[i] * 80 + cCh[i] * 16);
        bDst[i] = (uint32_t)(20480 + cPl[i] * 10240 + cR[i] * 80 + cCh[i] * 16);
    }

    uint32_t rAh[2], rAl[2];
    #pragma unroll
    for (int mi = 0; mi < 2; mi++) {
        rAh[mi] = ldrel(0u,     wm * 32 + mi * 16, lane);
        rAl[mi] = ldrel(10240u, wm * 32 + mi * 16, lane);
    }
    const uint32_t rBh0 = ldrel(20480u, wn * 32,      lane);
    const uint32_t rBh1 = ldrel(20480u, wn * 32 + 16, lane);
    const uint32_t rBl0 = ldrel(30720u, wn * 32,      lane);
    const uint32_t rBl1 = ldrel(30720u, wn * 32 + 16, lane);

    auto issue = [&](int kt) {
        const uint32_t st = sb + (uint32_t)(kt % N_STAGES) * STAGE_BYTES;
        const int k0 = kt * 32;
        #pragma unroll
        for (int i = 0; i < 2; i++) {
            const __nv_bfloat16* src = (cPl[i] ? alo : ahi)
                + (size_t)(m0 + cR[i]) * I_DIM + k0 + cCh[i] * 8;
            CP_ASYNC16(st + aDst[i], src);
        }
        #pragma unroll
        for (int i = 0; i < 2; i++) {
            const __nv_bfloat16* src = (cPl[i] ? dwl : dwh)
                + (size_t)(n0 + cR[i]) * I_DIM + k0 + cCh[i] * 8;
            CP_ASYNC16(st + bDst[i], src);
        }
    };

    float cd[2][4][4] = {};

    issue(0); CP_COMMIT();
    issue(1); CP_COMMIT();

    const int NK = I_DIM / 32;
    #pragma unroll 1
    for (int kt = 0; kt < NK; ++kt) {
        CP_WAIT1();
        __syncthreads();
        if (kt + 2 < NK) issue(kt + 2);
        CP_COMMIT();

        const uint32_t cur = sb + (uint32_t)(kt % N_STAGES) * STAGE_BYTES;
        #pragma unroll
        for (int kk = 0; kk < 2; ++kk) {
            const uint32_t kb = cur + (uint32_t)(kk * 32);
            uint32_t ah[2][4], al[2][4];
            #pragma unroll
            for (int mi = 0; mi < 2; mi++) {
                ldm_x4(kb + rAh[mi], ah[mi]);
                ldm_x4(kb + rAl[mi], al[mi]);
            }
            uint32_t bh0[4], bh1[4], bl0[4], bl1[4];
            ldm_x4(kb + rBh0, bh0);
            ldm_x4(kb + rBh1, bh1);
            ldm_x4(kb + rBl0, bl0);
            ldm_x4(kb + rBl1, bl1);
            uint32_t bhs[4][2] = {{bh0[0],bh0[2]},{bh0[1],bh0[3]},{bh1[0],bh1[2]},{bh1[1],bh1[3]}};
            uint32_t bls[4][2] = {{bl0[0],bl0[2]},{bl0[1],bl0[3]},{bl1[0],bl1[2]},{bl1[1],bl1[3]}};

            #pragma unroll
            for (int mi = 0; mi < 2; mi++)
                #pragma unroll
                for (int ni = 0; ni < 4; ni++) {
                    mma_bf16(cd[mi][ni], ah[mi], bhs[ni][0], bhs[ni][1]);
                    mma_bf16(cd[mi][ni], ah[mi], bls[ni][0], bls[ni][1]);
                    mma_bf16(cd[mi][ni], al[mi], bhs[ni][0], bhs[ni][1]);
                }
        }
        __syncthreads();
    }

    // epilogue
    const int gr = lane >> 2, tc = (lane & 3) * 2;
    #pragma unroll
    for (int mi = 0; mi < 2; mi++)
        #pragma unroll
        for (int ni = 0; ni < 4; ni++) {
            int ncol = n0 + wn * 32 + ni * 8 + tc;
            #pragma unroll
            for (int half = 0; half < 2; half++) {
                int mloc = wm * 32 + mi * 16 + gr + half * 8;
                float v0 = cd[mi][ni][half * 2];
                float v1 = cd[mi][ni][half * 2 + 1];
                if (SHARED) {
                    int t = m0 + mloc;
                    float2 v = {v0, v1};
                    *(float2*)(out + (size_t)t * H_DIM + ncol) = v;
                } else {
                    if (m0 + mloc < ne) {
                        int   t = toks[mloc];
                        float w = wgts[mloc];
                        float* op = out + (size_t)t * H_DIM + ncol;
                        atomicAdd(op,     w * v0);
                        atomicAdd(op + 1, w * v1);
                    }
                }
            }
        }
}

// ---------------------------------------------------------------------------
// Launch
// ---------------------------------------------------------------------------
extern "C" void kernel_launch(void* const* d_in, const int* in_sizes, int n_in,
                              void* d_out, int out_size)
{
    const float* x  = (const float*)d_in[0];
    const float* gw = (const float*)d_in[1];
    const float* eb = (const float*)d_in[2];
    const float* gp = (const float*)d_in[3];
    const float* up = (const float*)d_in[4];
    const float* dp = (const float*)d_in[5];
    const float* sg = (const float*)d_in[6];
    const float* su = (const float*)d_in[7];
    const float* sd = (const float*)d_in[8];
    float* out = (float*)d_out;

    static bool attr_set = false;
    if (!attr_set) {
        cudaFuncSetAttribute((const void*)gemm1_mma<false>, cudaFuncAttributeMaxDynamicSharedMemorySize, SMEM_DYN);
        cudaFuncSetAttribute((const void*)gemm1_mma<true>,  cudaFuncAttributeMaxDynamicSharedMemorySize, SMEM_DYN);
        cudaFuncSetAttribute((const void*)gemm2_mma<false>, cudaFuncAttributeMaxDynamicSharedMemorySize, SMEM_DYN);
        cudaFuncSetAttribute((const void*)gemm2_mma<true>,  cudaFuncAttributeMaxDynamicSharedMemorySize, SMEM_DYN);
        attr_set = true;
    }

    zero_counts_kernel<<<1, 32>>>();
    route_kernel<<<T_TOK, 256>>>(x, gw, eb);

    // pre-split everything into bf16 hi/lo planes (device-symbol addresses are
    // host-resolvable via unified addressing on GB300; use cudaGetSymbolAddress
    // to stay portable)
    void *xh, *xl, *gph, *gpl, *uph, *upl, *dph, *dpl, *sgh, *sgl, *suh, *sul, *sdh, *sdl;
    cudaGetSymbolAddress(&xh,  d_xh);  cudaGetSymbolAddress(&xl,  d_xl);
    cudaGetSymbolAddress(&gph, d_gph); cudaGetSymbolAddress(&gpl, d_gpl);
    cudaGetSymbolAddress(&uph, d_uph); cudaGetSymbolAddress(&upl, d_upl);
    cudaGetSymbolAddress(&dph, d_dph); cudaGetSymbolAddress(&dpl, d_dpl);
    cudaGetSymbolAddress(&sgh, d_sgh); cudaGetSymbolAddress(&sgl, d_sgl);
    cudaGetSymbolAddress(&suh, d_suh); cudaGetSymbolAddress(&sul, d_sul);
    cudaGetSymbolAddress(&sdh, d_sdh); cudaGetSymbolAddress(&sdl, d_sdl);

    const int SPLIT_BLKS = 2048, SPLIT_THR = 256;
    split_kernel<<<SPLIT_BLKS, SPLIT_THR>>>((const float4*)x,
        (uint2*)xh, (uint2*)xl, T_TOK * H_DIM / 4);
    split_kernel<<<SPLIT_BLKS, SPLIT_THR>>>((const float4*)gp,
        (uint2*)gph, (uint2*)gpl, N_EXP * I_DIM * H_DIM / 4);
    split_kernel<<<SPLIT_BLKS, SPLIT_THR>>>((const float4*)up,
        (uint2*)uph, (uint2*)upl, N_EXP * I_DIM * H_DIM / 4);
    split_kernel<<<SPLIT_BLKS, SPLIT_THR>>>((const float4*)dp,
        (uint2*)dph, (uint2*)dpl, N_EXP * H_DIM * I_DIM / 4);
    split_kernel<<<SPLIT_BLKS, SPLIT_THR>>>((const float4*)sg,
        (uint2*)sgh, (uint2*)sgl, I_DIM * H_DIM / 4);
    split_kernel<<<SPLIT_BLKS, SPLIT_THR>>>((const float4*)su,
        (uint2*)suh, (uint2*)sul, I_DIM * H_DIM / 4);
    split_kernel<<<SPLIT_BLKS, SPLIT_THR>>>((const float4*)sd,
        (uint2*)sdh, (uint2*)sdl, H_DIM * I_DIM / 4);

    gemm1_mma<false><<<dim3(I_DIM / 64, T_TOK / 128, N_EXP), 512, SMEM_DYN>>>(0);
    gemm1_mma<true> <<<dim3(I_DIM / 64, T_TOK / 128, 1),     512, SMEM_DYN>>>(0);

    gemm2_mma<true> <<<dim3(H_DIM / 128, T_TOK / 128, 1),     512, SMEM_DYN>>>(out);
    gemm2_mma<false><<<dim3(H_DIM / 128, T_TOK / 128, N_EXP), 512, SMEM_DYN>>>(out);
}

// round 7
// speedup vs baseline: 1.0739x; 1.0739x over previous
#include <cuda_runtime.h>
#include <cuda_bf16.h>
#include <stdint.h>
#include <math.h>

#define T_TOK 2048
#define H_DIM 2048
#define I_DIM 1024
#define N_EXP 16
#define TOPK  4
#define NGRP  4
#define GSZ   4
#define SCALING 2.5f

// stage = 6 planes x (rows*80B). GEMM1: A(2x10240) G(2x10240) U(2x10240).
// GEMM2: A(2x10240) B(2x20480). Both 61440 bytes.
#define STAGE_BYTES 61440u
#define N_STAGES    3
#define SMEM_DYN    (N_STAGES * STAGE_BYTES)   // 184320

// ---------------------------------------------------------------------------
// Scratch (device globals — no allocation allowed)
// ---------------------------------------------------------------------------
__device__ int   d_counts[N_EXP];
__device__ int   d_tok[N_EXP][T_TOK];
__device__ float d_wgt[N_EXP][T_TOK];
__device__ __nv_bfloat16 d_h1_hi[N_EXP][T_TOK][I_DIM];
__device__ __nv_bfloat16 d_h1_lo[N_EXP][T_TOK][I_DIM];
__device__ __nv_bfloat16 d_h1s_hi[T_TOK][I_DIM];
__device__ __nv_bfloat16 d_h1s_lo[T_TOK][I_DIM];
__device__ __nv_bfloat16 d_xh[T_TOK * H_DIM],          d_xl[T_TOK * H_DIM];
__device__ __nv_bfloat16 d_gph[N_EXP * I_DIM * H_DIM], d_gpl[N_EXP * I_DIM * H_DIM];
__device__ __nv_bfloat16 d_uph[N_EXP * I_DIM * H_DIM], d_upl[N_EXP * I_DIM * H_DIM];
__device__ __nv_bfloat16 d_dph[N_EXP * H_DIM * I_DIM], d_dpl[N_EXP * H_DIM * I_DIM];
__device__ __nv_bfloat16 d_sgh[I_DIM * H_DIM],         d_sgl[I_DIM * H_DIM];
__device__ __nv_bfloat16 d_suh[I_DIM * H_DIM],         d_sul[I_DIM * H_DIM];
__device__ __nv_bfloat16 d_sdh[H_DIM * I_DIM],         d_sdl[H_DIM * I_DIM];

// ---------------------------------------------------------------------------
// PTX helpers (baseline sm_80+ only — must compile under compute_103)
// ---------------------------------------------------------------------------
__device__ __forceinline__ uint32_t smem_u32(const void* p) {
    uint32_t a;
    asm("{ .reg .u64 t; cvta.to.shared.u64 t, %1; cvt.u32.u64 %0, t; }"
        : "=r"(a) : "l"(p));
    return a;
}

__device__ __forceinline__ void ldm_x4(uint32_t addr, uint32_t r[4]) {
    asm volatile("ldmatrix.sync.aligned.m8n8.x4.shared.b16 {%0,%1,%2,%3}, [%4];"
                 : "=r"(r[0]), "=r"(r[1]), "=r"(r[2]), "=r"(r[3]) : "r"(addr));
}

__device__ __forceinline__ void mma_bf16(float d[4], const uint32_t a[4],
                                         uint32_t b0, uint32_t b1) {
    asm volatile(
        "mma.sync.aligned.m16n8k16.row.col.f32.bf16.bf16.f32 "
        "{%0,%1,%2,%3}, {%4,%5,%6,%7}, {%8,%9}, {%0,%1,%2,%3};"
        : "+f"(d[0]), "+f"(d[1]), "+f"(d[2]), "+f"(d[3])
        : "r"(a[0]), "r"(a[1]), "r"(a[2]), "r"(a[3]), "r"(b0), "r"(b1));
}

#define CP_ASYNC16(dst, src) \
    asm volatile("cp.async.cg.shared.global [%0], [%1], 16;" \
                 :: "r"(dst), "l"(src) : "memory")
#define CP_COMMIT()  asm volatile("cp.async.commit_group;" ::: "memory")
#define CP_WAIT1()   asm volatile("cp.async.wait_group 1;" ::: "memory")

__device__ __forceinline__ void split2(float f0, float f1, uint32_t& hw, uint32_t& lw) {
    __nv_bfloat16 h0 = __float2bfloat16_rn(f0);
    __nv_bfloat16 h1 = __float2bfloat16_rn(f1);
    __nv_bfloat16 l0 = __float2bfloat16_rn(f0 - __bfloat162float(h0));
    __nv_bfloat16 l1 = __float2bfloat16_rn(f1 - __bfloat162float(h1));
    hw = (uint32_t)__bfloat16_as_ushort(h0) | ((uint32_t)__bfloat16_as_ushort(h1) << 16);
    lw = (uint32_t)__bfloat16_as_ushort(l0) | ((uint32_t)__bfloat16_as_ushort(l1) << 16);
}

__device__ __forceinline__ void split4(float4 f, uint2& hw, uint2& lw) {
    split2(f.x, f.y, hw.x, lw.x);
    split2(f.z, f.w, hw.y, lw.y);
}

// stage-relative ldmatrix offset within a padded [rows][40] bf16 plane
__device__ __forceinline__ uint32_t ldrel(uint32_t plane, int rbase, int lane) {
    int row = rbase + (lane & 15);
    int col = (lane >> 4) << 3;
    return plane + (uint32_t)((row * 40 + col) << 1);
}

// ---------------------------------------------------------------------------
// Utility kernels
// ---------------------------------------------------------------------------
__global__ __launch_bounds__(256) void split_kernel(
    const float4* __restrict__ src, uint2* __restrict__ hi,
    uint2* __restrict__ lo, int n4)
{
    int i = blockIdx.x * blockDim.x + threadIdx.x;
    int stride = gridDim.x * blockDim.x;
    for (; i < n4; i += stride) {
        float4 f = src[i];
        uint2 h, l; split4(f, h, l);
        hi[i] = h; lo[i] = l;
    }
}

__global__ __launch_bounds__(256) void zero_out_kernel(float4* __restrict__ out, int n4)
{
    int i = blockIdx.x * blockDim.x + threadIdx.x;
    int stride = gridDim.x * blockDim.x;
    float4 z = {0.f, 0.f, 0.f, 0.f};
    for (; i < n4; i += stride) out[i] = z;
}

__global__ void zero_counts_kernel() {
    if (threadIdx.x < N_EXP) d_counts[threadIdx.x] = 0;
}

// ---------------------------------------------------------------------------
// Routing (proven)
// ---------------------------------------------------------------------------
__global__ __launch_bounds__(256) void route_kernel(
    const float* __restrict__ x, const float* __restrict__ gw,
    const float* __restrict__ bias)
{
    __shared__ float xs[H_DIM];
    __shared__ float logits[N_EXP];
    const int t = blockIdx.x;
    const float* xr = x + (size_t)t * H_DIM;
    for (int i = threadIdx.x; i < H_DIM; i += blockDim.x) xs[i] = xr[i];
    __syncthreads();

    const int e = threadIdx.x >> 4, lane = threadIdx.x & 15;
    const float* g = gw + (size_t)e * H_DIM;
    float s = 0.f;
    for (int k = lane; k < H_DIM; k += 16) s += xs[k] * g[k];
    #pragma unroll
    for (int o = 8; o > 0; o >>= 1) s += __shfl_down_sync(0xffffffffu, s, o, 16);
    if (lane == 0) logits[e] = s;
    __syncthreads();

    if (threadIdx.x == 0) {
        float sc[N_EXP], bs[N_EXP];
        #pragma unroll
        for (int i = 0; i < N_EXP; i++) {
            sc[i] = 1.f / (1.f + expf(-logits[i]));
            bs[i] = sc[i] + bias[i];
        }
        float gsc[NGRP];
        #pragma unroll
        for (int gi = 0; gi < NGRP; gi++) {
            float m1 = -1e30f, m2 = -1e30f;
            #pragma unroll
            for (int j = 0; j < GSZ; j++) {
                float v = bs[gi * GSZ + j];
                if (v > m1) { m2 = m1; m1 = v; } else if (v > m2) { m2 = v; }
            }
            gsc[gi] = m1 + m2;
        }
        int g1 = 0;
        for (int gi = 1; gi < NGRP; gi++) if (gsc[gi] > gsc[g1]) g1 = gi;
        int g2 = -1;
        for (int gi = 0; gi < NGRP; gi++) {
            if (gi == g1) continue;
            if (g2 < 0 || gsc[gi] > gsc[g2]) g2 = gi;
        }
        bool allowed[N_EXP], used[N_EXP];
        #pragma unroll
        for (int i = 0; i < N_EXP; i++) {
            int gi = i / GSZ;
            allowed[i] = (gi == g1 || gi == g2);
            used[i] = false;
        }
        int sel[TOPK]; float wv[TOPK]; float wsum = 0.f;
        #pragma unroll
        for (int kk = 0; kk < TOPK; kk++) {
            int best = -1; float bv = -1e30f;
            for (int i = 0; i < N_EXP; i++) {
                if (!allowed[i] || used[i]) continue;
                if (best < 0 || bs[i] > bv) { best = i; bv = bs[i]; }
            }
            used[best] = true; sel[kk] = best; wv[kk] = sc[best]; wsum += sc[best];
        }
        const float inv = SCALING / (wsum + 1e-20f);
        #pragma unroll
        for (int kk = 0; kk < TOPK; kk++) {
            int ee = sel[kk];
            int slot = atomicAdd(&d_counts[ee], 1);
            d_tok[ee][slot] = t;
            d_wgt[ee][slot] = wv[kk] * inv;
        }
    }
}

// ---------------------------------------------------------------------------
// GEMM1: 256 threads (8 warps = 2m x 4n), CTA tile M=128 x N=128 x BK=32.
// Warp tile 64m x 32n, dual output (gate & up). z==N_EXP => shared expert.
// Stage planes: AH 0, AL 10240, GH 20480, GL 30720, UH 40960, UL 51200.
// ---------------------------------------------------------------------------
__global__ __launch_bounds__(256) void gemm1_mma()
{
    const int e = blockIdx.z;
    const bool shared = (e == N_EXP);
    const int ne = shared ? T_TOK : d_counts[e];
    const int m0 = blockIdx.y * 128;
    if (m0 >= ne) return;
    const int n0 = blockIdx.x * 128;

    extern __shared__ __align__(16) char dynsmem[];
    __shared__ int toks[128];

    const int tid = threadIdx.x, lane = tid & 31, wid = tid >> 5;
    const int wm = wid >> 2, wn = wid & 3;
    const uint32_t sb = smem_u32(dynsmem);

    if (tid < 128) {
        int r = m0 + tid;
        toks[tid] = shared ? r : (r < ne ? d_tok[e][r] : d_tok[e][0]);
    }
    __syncthreads();

    const size_t eoff = shared ? 0 : (size_t)e * I_DIM * H_DIM;
    const __nv_bfloat16* ghP = shared ? d_sgh : d_gph + eoff;
    const __nv_bfloat16* glP = shared ? d_sgl : d_gpl + eoff;
    const __nv_bfloat16* uhP = shared ? d_suh : d_uph + eoff;
    const __nv_bfloat16* ulP = shared ? d_sul : d_upl + eoff;

    // chunk decode: A 1024 chunks (4/thr), B 2048 chunks (8/thr)
    int aPl[4], aR[4], aCh[4];
    uint32_t aDst[4];
    #pragma unroll
    for (int i = 0; i < 4; i++) {
        int c = tid + 256 * i;
        aPl[i] = c >> 9; aR[i] = (c >> 2) & 127; aCh[i] = c & 3;
        aDst[i] = (uint32_t)(aPl[i] * 10240 + aR[i] * 80 + aCh[i] * 16);
    }
    int bW[8], bR[8], bCh[8];
    uint32_t bDst[8];
    #pragma unroll
    for (int i = 0; i < 8; i++) {
        int c = tid + 256 * i;
        bW[i] = c >> 9; bR[i] = (c >> 2) & 127; bCh[i] = c & 3;
        bDst[i] = (uint32_t)(20480 + bW[i] * 10240 + bR[i] * 80 + bCh[i] * 16);
    }

    // ldmatrix stage-relative offsets
    uint32_t rAh[4], rAl[4];
    #pragma unroll
    for (int mi = 0; mi < 4; mi++) {
        rAh[mi] = ldrel(0u,     wm * 64 + mi * 16, lane);
        rAl[mi] = ldrel(10240u, wm * 64 + mi * 16, lane);
    }
    const uint32_t rGh0 = ldrel(20480u, wn * 32,      lane);
    const uint32_t rGh1 = ldrel(20480u, wn * 32 + 16, lane);
    const uint32_t rGl0 = ldrel(30720u, wn * 32,      lane);
    const uint32_t rGl1 = ldrel(30720u, wn * 32 + 16, lane);
    const uint32_t rUh0 = ldrel(40960u, wn * 32,      lane);
    const uint32_t rUh1 = ldrel(40960u, wn * 32 + 16, lane);
    const uint32_t rUl0 = ldrel(51200u, wn * 32,      lane);
    const uint32_t rUl1 = ldrel(51200u, wn * 32 + 16, lane);

    auto issue = [&](int kt) {
        const uint32_t st = sb + (uint32_t)(kt % N_STAGES) * STAGE_BYTES;
        const int k0 = kt * 32;
        #pragma unroll
        for (int i = 0; i < 4; i++) {
            const __nv_bfloat16* src = (aPl[i] ? d_xl : d_xh)
                + (size_t)toks[aR[i]] * H_DIM + k0 + aCh[i] * 8;
            CP_ASYNC16(st + aDst[i], src);
        }
        #pragma unroll
        for (int i = 0; i < 8; i++) {
            const __nv_bfloat16* base =
                (bW[i] == 0) ? ghP : (bW[i] == 1) ? glP : (bW[i] == 2) ? uhP : ulP;
            const __nv_bfloat16* src = base + (size_t)(n0 + bR[i]) * H_DIM + k0 + bCh[i] * 8;
            CP_ASYNC16(st + bDst[i], src);
        }
    };

    float cg[4][4][4] = {}, cu[4][4][4] = {};

    issue(0); CP_COMMIT();
    issue(1); CP_COMMIT();

    const int NK = H_DIM / 32;
    #pragma unroll 1
    for (int kt = 0; kt < NK; ++kt) {
        CP_WAIT1();
        __syncthreads();
        if (kt + 2 < NK) issue(kt + 2);
        CP_COMMIT();

        const uint32_t cur = sb + (uint32_t)(kt % N_STAGES) * STAGE_BYTES;
        #pragma unroll
        for (int kk = 0; kk < 2; ++kk) {
            const uint32_t kb = cur + (uint32_t)(kk * 32);
            uint32_t ah[4][4], al[4][4];
            #pragma unroll
            for (int mi = 0; mi < 4; mi++) {
                ldm_x4(kb + rAh[mi], ah[mi]);
                ldm_x4(kb + rAl[mi], al[mi]);
            }
            {   // gate
                uint32_t h0[4], h1[4], l0[4], l1[4];
                ldm_x4(kb + rGh0, h0); ldm_x4(kb + rGh1, h1);
                ldm_x4(kb + rGl0, l0); ldm_x4(kb + rGl1, l1);
                uint32_t bh[4][2] = {{h0[0],h0[2]},{h0[1],h0[3]},{h1[0],h1[2]},{h1[1],h1[3]}};
                uint32_t bl[4][2] = {{l0[0],l0[2]},{l0[1],l0[3]},{l1[0],l1[2]},{l1[1],l1[3]}};
                #pragma unroll
                for (int mi = 0; mi < 4; mi++)
                    #pragma unroll
                    for (int ni = 0; ni < 4; ni++) {
                        mma_bf16(cg[mi][ni], ah[mi], bh[ni][0], bh[ni][1]);
                        mma_bf16(cg[mi][ni], ah[mi], bl[ni][0], bl[ni][1]);
                        mma_bf16(cg[mi][ni], al[mi], bh[ni][0], bh[ni][1]);
                    }
            }
            {   // up
                uint32_t h0[4], h1[4], l0[4], l1[4];
                ldm_x4(kb + rUh0, h0); ldm_x4(kb + rUh1, h1);
                ldm_x4(kb + rUl0, l0); ldm_x4(kb + rUl1, l1);
                uint32_t bh[4][2] = {{h0[0],h0[2]},{h0[1],h0[3]},{h1[0],h1[2]},{h1[1],h1[3]}};
                uint32_t bl[4][2] = {{l0[0],l0[2]},{l0[1],l0[3]},{l1[0],l1[2]},{l1[1],l1[3]}};
                #pragma unroll
                for (int mi = 0; mi < 4; mi++)
                    #pragma unroll
                    for (int ni = 0; ni < 4; ni++) {
                        mma_bf16(cu[mi][ni], ah[mi], bh[ni][0], bh[ni][1]);
                        mma_bf16(cu[mi][ni], ah[mi], bl[ni][0], bl[ni][1]);
                        mma_bf16(cu[mi][ni], al[mi], bh[ni][0], bh[ni][1]);
                    }
            }
        }
    }

    // epilogue: silu(g)*u -> bf16 hi/lo planes
    const int gr = lane >> 2, tc = (lane & 3) * 2;
    __nv_bfloat16* phi = shared ? &d_h1s_hi[0][0] : &d_h1_hi[e][0][0];
    __nv_bfloat16* plo = shared ? &d_h1s_lo[0][0] : &d_h1_lo[e][0][0];

    #pragma unroll
    for (int mi = 0; mi < 4; mi++)
        #pragma unroll
        for (int ni = 0; ni < 4; ni++) {
            int ncol = n0 + wn * 32 + ni * 8 + tc;
            #pragma unroll
            for (int half = 0; half < 2; half++) {
                int m = m0 + wm * 64 + mi * 16 + gr + half * 8;
                float g0 = cg[mi][ni][half * 2],     u0 = cu[mi][ni][half * 2];
                float g1 = cg[mi][ni][half * 2 + 1], u1 = cu[mi][ni][half * 2 + 1];
                float o0 = (g0 / (1.f + expf(-g0))) * u0;
                float o1 = (g1 / (1.f + expf(-g1))) * u1;
                uint32_t hw, lw; split2(o0, o1, hw, lw);
                *(uint32_t*)(phi + (size_t)m * I_DIM + ncol) = hw;
                *(uint32_t*)(plo + (size_t)m * I_DIM + ncol) = lw;
            }
        }
}

// ---------------------------------------------------------------------------
// GEMM2: 256 threads (8 warps = 2m x 4n), CTA tile M=128 x N=256 x BK=32.
// Warp tile 64m x 64n. z==N_EXP => shared expert (w=1). All-atomic epilogue.
// Stage planes: AH 0, AL 10240, BH 20480, BL 40960.
// ---------------------------------------------------------------------------
__global__ __launch_bounds__(256) void gemm2_mma(float* __restrict__ out)
{
    const int e = blockIdx.z;
    const bool shared = (e == N_EXP);
    const int ne = shared ? T_TOK : d_counts[e];
    const int m0 = blockIdx.y * 128;
    if (m0 >= ne) return;
    const int n0 = blockIdx.x * 256;

    extern __shared__ __align__(16) char dynsmem[];
    __shared__ int   toks[128];
    __shared__ float wgts[128];

    const int tid = threadIdx.x, lane = tid & 31, wid = tid >> 5;
    const int wm = wid >> 2, wn = wid & 3;
    const uint32_t sb = smem_u32(dynsmem);

    if (tid < 128) {
        int r = m0 + tid;
        if (shared) { toks[tid] = r; wgts[tid] = 1.f; }
        else {
            toks[tid] = (r < ne) ? d_tok[e][r] : 0;
            wgts[tid] = (r < ne) ? d_wgt[e][r] : 0.f;
        }
    }
    __syncthreads();

    const __nv_bfloat16* ahi = shared ? &d_h1s_hi[0][0] : &d_h1_hi[e][0][0];
    const __nv_bfloat16* alo = shared ? &d_h1s_lo[0][0] : &d_h1_lo[e][0][0];
    const size_t eoff = shared ? 0 : (size_t)e * H_DIM * I_DIM;
    const __nv_bfloat16* dwh = shared ? d_sdh : d_dph + eoff;
    const __nv_bfloat16* dwl = shared ? d_sdl : d_dpl + eoff;

    int aPl[4], aR[4], aCh[4];
    uint32_t aDst[4];
    #pragma unroll
    for (int i = 0; i < 4; i++) {
        int c = tid + 256 * i;
        aPl[i] = c >> 9; aR[i] = (c >> 2) & 127; aCh[i] = c & 3;
        aDst[i] = (uint32_t)(aPl[i] * 10240 + aR[i] * 80 + aCh[i] * 16);
    }
    int bPl[8], bR[8], bCh[8];
    uint32_t bDst[8];
    #pragma unroll
    for (int i = 0; i < 8; i++) {
        int c = tid + 256 * i;
        bPl[i] = c >> 10; bR[i] = (c >> 2) & 255; bCh[i] = c & 3;
        bDst[i] = (uint32_t)(20480 + bPl[i] * 20480 + bR[i] * 80 + bCh[i] * 16);
    }

    uint32_t rAh[4], rAl[4];
    #pragma unroll
    for (int mi = 0; mi < 4; mi++) {
        rAh[mi] = ldrel(0u,     wm * 64 + mi * 16, lane);
        rAl[mi] = ldrel(10240u, wm * 64 + mi * 16, lane);
    }
    uint32_t rBh[4], rBl[4];
    #pragma unroll
    for (int j = 0; j < 4; j++) {
        rBh[j] = ldrel(20480u, wn * 64 + j * 16, lane);
        rBl[j] = ldrel(40960u, wn * 64 + j * 16, lane);
    }

    auto issue = [&](int kt) {
        const uint32_t st = sb + (uint32_t)(kt % N_STAGES) * STAGE_BYTES;
        const int k0 = kt * 32;
        #pragma unroll
        for (int i = 0; i < 4; i++) {
            const __nv_bfloat16* src = (aPl[i] ? alo : ahi)
                + (size_t)(m0 + aR[i]) * I_DIM + k0 + aCh[i] * 8;
            CP_ASYNC16(st + aDst[i], src);
        }
        #pragma unroll
        for (int i = 0; i < 8; i++) {
            const __nv_bfloat16* src = (bPl[i] ? dwl : dwh)
                + (size_t)(n0 + bR[i]) * I_DIM + k0 + bCh[i] * 8;
            CP_ASYNC16(st + bDst[i], src);
        }
    };

    float cd[4][8][4] = {};

    issue(0); CP_COMMIT();
    issue(1); CP_COMMIT();

    const int NK = I_DIM / 32;
    #pragma unroll 1
    for (int kt = 0; kt < NK; ++kt) {
        CP_WAIT1();
        __syncthreads();
        if (kt + 2 < NK) issue(kt + 2);
        CP_COMMIT();

        const uint32_t cur = sb + (uint32_t)(kt % N_STAGES) * STAGE_BYTES;
        #pragma unroll
        for (int kk = 0; kk < 2; ++kk) {
            const uint32_t kb = cur + (uint32_t)(kk * 32);
            uint32_t ah[4][4], al[4][4];
            #pragma unroll
            for (int mi = 0; mi < 4; mi++) {
                ldm_x4(kb + rAh[mi], ah[mi]);
                ldm_x4(kb + rAl[mi], al[mi]);
            }
            uint32_t h[4][4], l[4][4];
            #pragma unroll
            for (int j = 0; j < 4; j++) {
                ldm_x4(kb + rBh[j], h[j]);
                ldm_x4(kb + rBl[j], l[j]);
            }
            uint32_t bh[8][2], bl[8][2];
            #pragma unroll
            for (int j = 0; j < 4; j++) {
                bh[j*2][0]   = h[j][0]; bh[j*2][1]   = h[j][2];
                bh[j*2+1][0] = h[j][1]; bh[j*2+1][1] = h[j][3];
                bl[j*2][0]   = l[j][0]; bl[j*2][1]   = l[j][2];
                bl[j*2+1][0] = l[j][1]; bl[j*2+1][1] = l[j][3];
            }
            #pragma unroll
            for (int mi = 0; mi < 4; mi++)
                #pragma unroll
                for (int ni = 0; ni < 8; ni++) {
                    mma_bf16(cd[mi][ni], ah[mi], bh[ni][0], bh[ni][1]);
                    mma_bf16(cd[mi][ni], ah[mi], bl[ni][0], bl[ni][1]);
                    mma_bf16(cd[mi][ni], al[mi], bh[ni][0], bh[ni][1]);
                }
        }
    }

    // epilogue: weighted atomic scatter (out pre-zeroed)
    const int gr = lane >> 2, tc = (lane & 3) * 2;
    #pragma unroll
    for (int mi = 0; mi < 4; mi++) {
        #pragma unroll
        for (int half = 0; half < 2; half++) {
            int mloc = wm * 64 + mi * 16 + gr + half * 8;
            if (m0 + mloc >= ne) continue;
            int   t = toks[mloc];
            float w = wgts[mloc];
            float* orow = out + (size_t)t * H_DIM;
            #pragma unroll
            for (int ni = 0; ni < 8; ni++) {
                int ncol = n0 + wn * 64 + ni * 8 + tc;
                atomicAdd(orow + ncol,     w * cd[mi][ni][half * 2]);
                atomicAdd(orow + ncol + 1, w * cd[mi][ni][half * 2 + 1]);
            }
        }
    }
}

// ---------------------------------------------------------------------------
// Launch
// ---------------------------------------------------------------------------
extern "C" void kernel_launch(void* const* d_in, const int* in_sizes, int n_in,
                              void* d_out, int out_size)
{
    const float* x  = (const float*)d_in[0];
    const float* gw = (const float*)d_in[1];
    const float* eb = (const float*)d_in[2];
    const float* gp = (const float*)d_in[3];
    const float* up = (const float*)d_in[4];
    const float* dp = (const float*)d_in[5];
    const float* sg = (const float*)d_in[6];
    const float* su = (const float*)d_in[7];
    const float* sd = (const float*)d_in[8];
    float* out = (float*)d_out;

    cudaFuncSetAttribute((const void*)gemm1_mma, cudaFuncAttributeMaxDynamicSharedMemorySize, SMEM_DYN);
    cudaFuncSetAttribute((const void*)gemm2_mma, cudaFuncAttributeMaxDynamicSharedMemorySize, SMEM_DYN);

    zero_counts_kernel<<<1, 32>>>();
    zero_out_kernel<<<1024, 256>>>((float4*)out, out_size / 4);
    route_kernel<<<T_TOK, 256>>>(x, gw, eb);

    void *xh, *xl, *gph, *gpl, *uph, *upl, *dph, *dpl, *sgh, *sgl, *suh, *sul, *sdh, *sdl;
    cudaGetSymbolAddress(&xh,  d_xh);  cudaGetSymbolAddress(&xl,  d_xl);
    cudaGetSymbolAddress(&gph, d_gph); cudaGetSymbolAddress(&gpl, d_gpl);
    cudaGetSymbolAddress(&uph, d_uph); cudaGetSymbolAddress(&upl, d_upl);
    cudaGetSymbolAddress(&dph, d_dph); cudaGetSymbolAddress(&dpl, d_dpl);
    cudaGetSymbolAddress(&sgh, d_sgh); cudaGetSymbolAddress(&sgl, d_sgl);
    cudaGetSymbolAddress(&suh, d_suh); cudaGetSymbolAddress(&sul, d_sul);
    cudaGetSymbolAddress(&sdh, d_sdh); cudaGetSymbolAddress(&sdl, d_sdl);

    const int SPLIT_BLKS = 2048, SPLIT_THR = 256;
    split_kernel<<<SPLIT_BLKS, SPLIT_THR>>>((const float4*)x,
        (uint2*)xh, (uint2*)xl, T_TOK * H_DIM / 4);
    split_kernel<<<SPLIT_BLKS, SPLIT_THR>>>((const float4*)gp,
        (uint2*)gph, (uint2*)gpl, N_EXP * I_DIM * H_DIM / 4);
    split_kernel<<<SPLIT_BLKS, SPLIT_THR>>>((const float4*)up,
        (uint2*)uph, (uint2*)upl, N_EXP * I_DIM * H_DIM / 4);
    split_kernel<<<SPLIT_BLKS, SPLIT_THR>>>((const float4*)dp,
        (uint2*)dph, (uint2*)dpl, N_EXP * H_DIM * I_DIM / 4);
    split_kernel<<<SPLIT_BLKS, SPLIT_THR>>>((const float4*)sg,
        (uint2*)sgh, (uint2*)sgl, I_DIM * H_DIM / 4);
    split_kernel<<<SPLIT_BLKS, SPLIT_THR>>>((const float4*)su,
        (uint2*)suh, (uint2*)sul, I_DIM * H_DIM / 4);
    split_kernel<<<SPLIT_BLKS, SPLIT_THR>>>((const float4*)sd,
        (uint2*)sdh, (uint2*)sdl, H_DIM * I_DIM / 4);

    // GEMM1: z = 17 (16 experts + shared), M tiles 16, N tiles 8
    gemm1_mma<<<dim3(I_DIM / 128, T_TOK / 128, N_EXP + 1), 256, SMEM_DYN>>>();
    // GEMM2: z = 17, N tiles 8 (N=256), M tiles 16
    gemm2_mma<<<dim3(H_DIM / 256, T_TOK / 128, N_EXP + 1), 256, SMEM_DYN>>>(out);
}

// round 8
// speedup vs baseline: 1.0884x; 1.0135x over previous
#include <cuda_runtime.h>
#include <cuda_fp16.h>
#include <stdint.h>
#include <math.h>

#define T_TOK 2048
#define H_DIM 2048
#define I_DIM 1024
#define N_EXP 16
#define TOPK  4
#define NGRP  4
#define GSZ   4
#define SCALING 2.5f

#define STAGE_BYTES 61440u
#define N_STAGES    3
#define SMEM_DYN    (N_STAGES * STAGE_BYTES)   // 184320

// ---------------------------------------------------------------------------
// Scratch (device globals — no allocation allowed). All planes are fp16 hi/lo.
// ---------------------------------------------------------------------------
__device__ int   d_counts[N_EXP];
__device__ int   d_tok[N_EXP][T_TOK];
__device__ float d_wgt[N_EXP][T_TOK];
__device__ __half d_h1_hi[N_EXP][T_TOK][I_DIM];
__device__ __half d_h1_lo[N_EXP][T_TOK][I_DIM];
__device__ __half d_h1s_hi[T_TOK][I_DIM];
__device__ __half d_h1s_lo[T_TOK][I_DIM];
__device__ __half d_xh[T_TOK * H_DIM],          d_xl[T_TOK * H_DIM];
__device__ __half d_gph[N_EXP * I_DIM * H_DIM], d_gpl[N_EXP * I_DIM * H_DIM];
__device__ __half d_uph[N_EXP * I_DIM * H_DIM], d_upl[N_EXP * I_DIM * H_DIM];
__device__ __half d_dph[N_EXP * H_DIM * I_DIM], d_dpl[N_EXP * H_DIM * I_DIM];
__device__ __half d_sgh[I_DIM * H_DIM],         d_sgl[I_DIM * H_DIM];
__device__ __half d_suh[I_DIM * H_DIM],         d_sul[I_DIM * H_DIM];
__device__ __half d_sdh[H_DIM * I_DIM],         d_sdl[H_DIM * I_DIM];

// ---------------------------------------------------------------------------
// PTX helpers (baseline sm_80+ only — must compile under compute_103)
// ---------------------------------------------------------------------------
__device__ __forceinline__ uint32_t smem_u32(const void* p) {
    uint32_t a;
    asm("{ .reg .u64 t; cvta.to.shared.u64 t, %1; cvt.u32.u64 %0, t; }"
        : "=r"(a) : "l"(p));
    return a;
}

__device__ __forceinline__ void ldm_x4(uint32_t addr, uint32_t r[4]) {
    asm volatile("ldmatrix.sync.aligned.m8n8.x4.shared.b16 {%0,%1,%2,%3}, [%4];"
                 : "=r"(r[0]), "=r"(r[1]), "=r"(r[2]), "=r"(r[3]) : "r"(addr));
}

__device__ __forceinline__ void mma_f16(float d[4], const uint32_t a[4],
                                        uint32_t b0, uint32_t b1) {
    asm volatile(
        "mma.sync.aligned.m16n8k16.row.col.f32.f16.f16.f32 "
        "{%0,%1,%2,%3}, {%4,%5,%6,%7}, {%8,%9}, {%0,%1,%2,%3};"
        : "+f"(d[0]), "+f"(d[1]), "+f"(d[2]), "+f"(d[3])
        : "r"(a[0]), "r"(a[1]), "r"(a[2]), "r"(a[3]), "r"(b0), "r"(b1));
}

#define CP_ASYNC16(dst, src) \
    asm volatile("cp.async.cg.shared.global [%0], [%1], 16;" \
                 :: "r"(dst), "l"(src) : "memory")
#define CP_COMMIT()  asm volatile("cp.async.commit_group;" ::: "memory")
#define CP_WAIT1()   asm volatile("cp.async.wait_group 1;" ::: "memory")

// fp16 residual split: x = hi + lo, |lo| <= 2^-11 |x|
__device__ __forceinline__ void split2(float f0, float f1, uint32_t& hw, uint32_t& lw) {
    __half h0 = __float2half_rn(f0);
    __half h1 = __float2half_rn(f1);
    __half l0 = __float2half_rn(f0 - __half2float(h0));
    __half l1 = __float2half_rn(f1 - __half2float(h1));
    hw = (uint32_t)__half_as_ushort(h0) | ((uint32_t)__half_as_ushort(h1) << 16);
    lw = (uint32_t)__half_as_ushort(l0) | ((uint32_t)__half_as_ushort(l1) << 16);
}

__device__ __forceinline__ void split4(float4 f, uint2& hw, uint2& lw) {
    split2(f.x, f.y, hw.x, lw.x);
    split2(f.z, f.w, hw.y, lw.y);
}

// stage-relative ldmatrix offset within a padded [rows][40] fp16 plane
__device__ __forceinline__ uint32_t ldrel(uint32_t plane, int rbase, int lane) {
    int row = rbase + (lane & 15);
    int col = (lane >> 4) << 3;
    return plane + (uint32_t)((row * 40 + col) << 1);
}

// ---------------------------------------------------------------------------
// Fused split kernels (fp32 -> fp16 hi/lo planes)
// ---------------------------------------------------------------------------
#define SEG_GP 8388608
#define SEG_UP 16777216
#define SEG_DP 25165824
#define SEG_SG 25690112
#define SEG_SU 26214400
#define SEG_SD 26738688

__global__ __launch_bounds__(256) void split_weights_kernel(
    const float4* __restrict__ gp, const float4* __restrict__ up,
    const float4* __restrict__ dp, const float4* __restrict__ sg,
    const float4* __restrict__ su, const float4* __restrict__ sd)
{
    int i = blockIdx.x * blockDim.x + threadIdx.x;
    const int stride = gridDim.x * blockDim.x;
    for (; i < SEG_SD; i += stride) {
        const float4* src; uint2 *hi, *lo; int off;
        if (i < SEG_GP)      { src = gp; off = i;            hi = (uint2*)d_gph; lo = (uint2*)d_gpl; }
        else if (i < SEG_UP) { src = up; off = i - SEG_GP;   hi = (uint2*)d_uph; lo = (uint2*)d_upl; }
        else if (i < SEG_DP) { src = dp; off = i - SEG_UP;   hi = (uint2*)d_dph; lo = (uint2*)d_dpl; }
        else if (i < SEG_SG) { src = sg; off = i - SEG_DP;   hi = (uint2*)d_sgh; lo = (uint2*)d_sgl; }
        else if (i < SEG_SU) { src = su; off = i - SEG_SG;   hi = (uint2*)d_suh; lo = (uint2*)d_sul; }
        else                 { src = sd; off = i - SEG_SU;   hi = (uint2*)d_sdh; lo = (uint2*)d_sdl; }
        float4 f = src[off];
        uint2 h, l; split4(f, h, l);
        hi[off] = h; lo[off] = l;
    }
}

__global__ __launch_bounds__(256) void split_x_kernel(const float4* __restrict__ x)
{
    int i = blockIdx.x * blockDim.x + threadIdx.x;
    const int stride = gridDim.x * blockDim.x;
    const int n4 = T_TOK * H_DIM / 4;
    for (; i < n4; i += stride) {
        float4 f = x[i];
        uint2 h, l; split4(f, h, l);
        ((uint2*)d_xh)[i] = h; ((uint2*)d_xl)[i] = l;
    }
}

__global__ __launch_bounds__(256) void zero_out_kernel(float4* __restrict__ out, int n4)
{
    int i = blockIdx.x * blockDim.x + threadIdx.x;
    int stride = gridDim.x * blockDim.x;
    float4 z = {0.f, 0.f, 0.f, 0.f};
    for (; i < n4; i += stride) out[i] = z;
}

__global__ void zero_counts_kernel() {
    if (threadIdx.x < N_EXP) d_counts[threadIdx.x] = 0;
}

// ---------------------------------------------------------------------------
// Routing (proven)
// ---------------------------------------------------------------------------
__global__ __launch_bounds__(256) void route_kernel(
    const float* __restrict__ x, const float* __restrict__ gw,
    const float* __restrict__ bias)
{
    __shared__ float xs[H_DIM];
    __shared__ float logits[N_EXP];
    const int t = blockIdx.x;
    const float* xr = x + (size_t)t * H_DIM;
    for (int i = threadIdx.x; i < H_DIM; i += blockDim.x) xs[i] = xr[i];
    __syncthreads();

    const int e = threadIdx.x >> 4, lane = threadIdx.x & 15;
    const float* g = gw + (size_t)e * H_DIM;
    float s = 0.f;
    for (int k = lane; k < H_DIM; k += 16) s += xs[k] * g[k];
    #pragma unroll
    for (int o = 8; o > 0; o >>= 1) s += __shfl_down_sync(0xffffffffu, s, o, 16);
    if (lane == 0) logits[e] = s;
    __syncthreads();

    if (threadIdx.x == 0) {
        float sc[N_EXP], bs[N_EXP];
        #pragma unroll
        for (int i = 0; i < N_EXP; i++) {
            sc[i] = 1.f / (1.f + expf(-logits[i]));
            bs[i] = sc[i] + bias[i];
        }
        float gsc[NGRP];
        #pragma unroll
        for (int gi = 0; gi < NGRP; gi++) {
            float m1 = -1e30f, m2 = -1e30f;
            #pragma unroll
            for (int j = 0; j < GSZ; j++) {
                float v = bs[gi * GSZ + j];
                if (v > m1) { m2 = m1; m1 = v; } else if (v > m2) { m2 = v; }
            }
            gsc[gi] = m1 + m2;
        }
        int g1 = 0;
        for (int gi = 1; gi < NGRP; gi++) if (gsc[gi] > gsc[g1]) g1 = gi;
        int g2 = -1;
        for (int gi = 0; gi < NGRP; gi++) {
            if (gi == g1) continue;
            if (g2 < 0 || gsc[gi] > gsc[g2]) g2 = gi;
        }
        bool allowed[N_EXP], used[N_EXP];
        #pragma unroll
        for (int i = 0; i < N_EXP; i++) {
            int gi = i / GSZ;
            allowed[i] = (gi == g1 || gi == g2);
            used[i] = false;
        }
        int sel[TOPK]; float wv[TOPK]; float wsum = 0.f;
        #pragma unroll
        for (int kk = 0; kk < TOPK; kk++) {
            int best = -1; float bv = -1e30f;
            for (int i = 0; i < N_EXP; i++) {
                if (!allowed[i] || used[i]) continue;
                if (best < 0 || bs[i] > bv) { best = i; bv = bs[i]; }
            }
            used[best] = true; sel[kk] = best; wv[kk] = sc[best]; wsum += sc[best];
        }
        const float inv = SCALING / (wsum + 1e-20f);
        #pragma unroll
        for (int kk = 0; kk < TOPK; kk++) {
            int ee = sel[kk];
            int slot = atomicAdd(&d_counts[ee], 1);
            d_tok[ee][slot] = t;
            d_wgt[ee][slot] = wv[kk] * inv;
        }
    }
}

// ---------------------------------------------------------------------------
// GEMM1: 256 threads (8 warps = 2m x 4n), CTA tile M=128 x N=128 x BK=32.
// Warp tile 64m x 32n, dual output (gate & up). z==N_EXP => shared expert.
// Stage planes: AH 0, AL 10240, GH 20480, GL 30720, UH 40960, UL 51200.
// ---------------------------------------------------------------------------
__global__ __launch_bounds__(256) void gemm1_mma()
{
    const int e = blockIdx.z;
    const bool shared = (e == N_EXP);
    const int ne = shared ? T_TOK : d_counts[e];
    const int m0 = blockIdx.y * 128;
    if (m0 >= ne) return;
    const int n0 = blockIdx.x * 128;

    extern __shared__ __align__(16) char dynsmem[];
    __shared__ int toks[128];

    const int tid = threadIdx.x, lane = tid & 31, wid = tid >> 5;
    const int wm = wid >> 2, wn = wid & 3;
    const uint32_t sb = smem_u32(dynsmem);

    if (tid < 128) {
        int r = m0 + tid;
        toks[tid] = shared ? r : (r < ne ? d_tok[e][r] : d_tok[e][0]);
    }
    __syncthreads();

    const size_t eoff = shared ? 0 : (size_t)e * I_DIM * H_DIM;
    const __half* ghP = shared ? d_sgh : d_gph + eoff;
    const __half* glP = shared ? d_sgl : d_gpl + eoff;
    const __half* uhP = shared ? d_suh : d_uph + eoff;
    const __half* ulP = shared ? d_sul : d_upl + eoff;

    int aPl[4], aR[4], aCh[4];
    uint32_t aDst[4];
    #pragma unroll
    for (int i = 0; i < 4; i++) {
        int c = tid + 256 * i;
        aPl[i] = c >> 9; aR[i] = (c >> 2) & 127; aCh[i] = c & 3;
        aDst[i] = (uint32_t)(aPl[i] * 10240 + aR[i] * 80 + aCh[i] * 16);
    }
    int bW[8], bR[8], bCh[8];
    uint32_t bDst[8];
    #pragma unroll
    for (int i = 0; i < 8; i++) {
        int c = tid + 256 * i;
        bW[i] = c >> 9; bR[i] = (c >> 2) & 127; bCh[i] = c & 3;
        bDst[i] = (uint32_t)(20480 + bW[i] * 10240 + bR[i] * 80 + bCh[i] * 16);
    }

    uint32_t rAh[4], rAl[4];
    #pragma unroll
    for (int mi = 0; mi < 4; mi++) {
        rAh[mi] = ldrel(0u,     wm * 64 + mi * 16, lane);
        rAl[mi] = ldrel(10240u, wm * 64 + mi * 16, lane);
    }
    const uint32_t rGh0 = ldrel(20480u, wn * 32,      lane);
    const uint32_t rGh1 = ldrel(20480u, wn * 32 + 16, lane);
    const uint32_t rGl0 = ldrel(30720u, wn * 32,      lane);
    const uint32_t rGl1 = ldrel(30720u, wn * 32 + 16, lane);
    const uint32_t rUh0 = ldrel(40960u, wn * 32,      lane);
    const uint32_t rUh1 = ldrel(40960u, wn * 32 + 16, lane);
    const uint32_t rUl0 = ldrel(51200u, wn * 32,      lane);
    const uint32_t rUl1 = ldrel(51200u, wn * 32 + 16, lane);

    auto issue = [&](int kt) {
        const uint32_t st = sb + (uint32_t)(kt % N_STAGES) * STAGE_BYTES;
        const int k0 = kt * 32;
        #pragma unroll
        for (int i = 0; i < 4; i++) {
            const __half* src = (aPl[i] ? d_xl : d_xh)
                + (size_t)toks[aR[i]] * H_DIM + k0 + aCh[i] * 8;
            CP_ASYNC16(st + aDst[i], src);
        }
        #pragma unroll
        for (int i = 0; i < 8; i++) {
            const __half* base =
                (bW[i] == 0) ? ghP : (bW[i] == 1) ? glP : (bW[i] == 2) ? uhP : ulP;
            const __half* src = base + (size_t)(n0 + bR[i]) * H_DIM + k0 + bCh[i] * 8;
            CP_ASYNC16(st + bDst[i], src);
        }
    };

    float cg[4][4][4] = {}, cu[4][4][4] = {};

    issue(0); CP_COMMIT();
    issue(1); CP_COMMIT();

    const int NK = H_DIM / 32;
    #pragma unroll 1
    for (int kt = 0; kt < NK; ++kt) {
        CP_WAIT1();
        __syncthreads();
        if (kt + 2 < NK) issue(kt + 2);
        CP_COMMIT();

        const uint32_t cur = sb + (uint32_t)(kt % N_STAGES) * STAGE_BYTES;
        #pragma unroll
        for (int kk = 0; kk < 2; ++kk) {
            const uint32_t kb = cur + (uint32_t)(kk * 32);
            uint32_t ah[4][4], al[4][4];
            #pragma unroll
            for (int mi = 0; mi < 4; mi++) {
                ldm_x4(kb + rAh[mi], ah[mi]);
                ldm_x4(kb + rAl[mi], al[mi]);
            }
            {   // gate
                uint32_t h0[4], h1[4], l0[4], l1[4];
                ldm_x4(kb + rGh0, h0); ldm_x4(kb + rGh1, h1);
                ldm_x4(kb + rGl0, l0); ldm_x4(kb + rGl1, l1);
                uint32_t bh[4][2] = {{h0[0],h0[2]},{h0[1],h0[3]},{h1[0],h1[2]},{h1[1],h1[3]}};
                uint32_t bl[4][2] = {{l0[0],l0[2]},{l0[1],l0[3]},{l1[0],l1[2]},{l1[1],l1[3]}};
                #pragma unroll
                for (int mi = 0; mi < 4; mi++)
                    #pragma unroll
                    for (int ni = 0; ni < 4; ni++) {
                        mma_f16(cg[mi][ni], ah[mi], bh[ni][0], bh[ni][1]);
                        mma_f16(cg[mi][ni], ah[mi], bl[ni][0], bl[ni][1]);
                        mma_f16(cg[mi][ni], al[mi], bh[ni][0], bh[ni][1]);
                    }
            }
            {   // up
                uint32_t h0[4], h1[4], l0[4], l1[4];
                ldm_x4(kb + rUh0, h0); ldm_x4(kb + rUh1, h1);
                ldm_x4(kb + rUl0, l0); ldm_x4(kb + rUl1, l1);
                uint32_t bh[4][2] = {{h0[0],h0[2]},{h0[1],h0[3]},{h1[0],h1[2]},{h1[1],h1[3]}};
                uint32_t bl[4][2] = {{l0[0],l0[2]},{l0[1],l0[3]},{l1[0],l1[2]},{l1[1],l1[3]}};
                #pragma unroll
                for (int mi = 0; mi < 4; mi++)
                    #pragma unroll
                    for (int ni = 0; ni < 4; ni++) {
                        mma_f16(cu[mi][ni], ah[mi], bh[ni][0], bh[ni][1]);
                        mma_f16(cu[mi][ni], ah[mi], bl[ni][0], bl[ni][1]);
                        mma_f16(cu[mi][ni], al[mi], bh[ni][0], bh[ni][1]);
                    }
            }
        }
    }

    // epilogue: silu(g)*u -> fp16 hi/lo planes
    const int gr = lane >> 2, tc = (lane & 3) * 2;
    __half* phi = shared ? &d_h1s_hi[0][0] : &d_h1_hi[e][0][0];
    __half* plo = shared ? &d_h1s_lo[0][0] : &d_h1_lo[e][0][0];

    #pragma unroll
    for (int mi = 0; mi < 4; mi++)
        #pragma unroll
        for (int ni = 0; ni < 4; ni++) {
            int ncol = n0 + wn * 32 + ni * 8 + tc;
            #pragma unroll
            for (int half = 0; half < 2; half++) {
                int m = m0 + wm * 64 + mi * 16 + gr + half * 8;
                float g0 = cg[mi][ni][half * 2],     u0 = cu[mi][ni][half * 2];
                float g1 = cg[mi][ni][half * 2 + 1], u1 = cu[mi][ni][half * 2 + 1];
                float o0 = (g0 / (1.f + expf(-g0))) * u0;
                float o1 = (g1 / (1.f + expf(-g1))) * u1;
                uint32_t hw, lw; split2(o0, o1, hw, lw);
                *(uint32_t*)(phi + (size_t)m * I_DIM + ncol) = hw;
                *(uint32_t*)(plo + (size_t)m * I_DIM + ncol) = lw;
            }
        }
}

// ---------------------------------------------------------------------------
// GEMM2: 256 threads (8 warps = 2m x 4n), CTA tile M=128 x N=256 x BK=32.
// Warp tile 64m x 64n. z==N_EXP => shared expert (w=1). All-atomic epilogue.
// Stage planes: AH 0, AL 10240, BH 20480, BL 40960.
// ---------------------------------------------------------------------------
__global__ __launch_bounds__(256) void gemm2_mma(float* __restrict__ out)
{
    const int e = blockIdx.z;
    const bool shared = (e == N_EXP);
    const int ne = shared ? T_TOK : d_counts[e];
    const int m0 = blockIdx.y * 128;
    if (m0 >= ne) return;
    const int n0 = blockIdx.x * 256;

    extern __shared__ __align__(16) char dynsmem[];
    __shared__ int   toks[128];
    __shared__ float wgts[128];

    const int tid = threadIdx.x, lane = tid & 31, wid = tid >> 5;
    const int wm = wid >> 2, wn = wid & 3;
    const uint32_t sb = smem_u32(dynsmem);

    if (tid < 128) {
        int r = m0 + tid;
        if (shared) { toks[tid] = r; wgts[tid] = 1.f; }
        else {
            toks[tid] = (r < ne) ? d_tok[e][r] : 0;
            wgts[tid] = (r < ne) ? d_wgt[e][r] : 0.f;
        }
    }
    __syncthreads();

    const __half* ahi = shared ? &d_h1s_hi[0][0] : &d_h1_hi[e][0][0];
    const __half* alo = shared ? &d_h1s_lo[0][0] : &d_h1_lo[e][0][0];
    const size_t eoff = shared ? 0 : (size_t)e * H_DIM * I_DIM;
    const __half* dwh = shared ? d_sdh : d_dph + eoff;
    const __half* dwl = shared ? d_sdl : d_dpl + eoff;

    int aPl[4], aR[4], aCh[4];
    uint32_t aDst[4];
    #pragma unroll
    for (int i = 0; i < 4; i++) {
        int c = tid + 256 * i;
        aPl[i] = c >> 9; aR[i] = (c >> 2) & 127; aCh[i] = c & 3;
        aDst[i] = (uint32_t)(aPl[i] * 10240 + aR[i] * 80 + aCh[i] * 16);
    }
    int bPl[8], bR[8], bCh[8];
    uint32_t bDst[8];
    #pragma unroll
    for (int i = 0; i < 8; i++) {
        int c = tid + 256 * i;
        bPl[i] = c >> 10; bR[i] = (c >> 2) & 255; bCh[i] = c & 3;
        bDst[i] = (uint32_t)(20480 + bPl[i] * 20480 + bR[i] * 80 + bCh[i] * 16);
    }

    uint32_t rAh[4], rAl[4];
    #pragma unroll
    for (int mi = 0; mi < 4; mi++) {
        rAh[mi] = ldrel(0u,     wm * 64 + mi * 16, lane);
        rAl[mi] = ldrel(10240u, wm * 64 + mi * 16, lane);
    }
    uint32_t rBh[4], rBl[4];
    #pragma unroll
    for (int j = 0; j < 4; j++) {
        rBh[j] = ldrel(20480u, wn * 64 + j * 16, lane);
        rBl[j] = ldrel(40960u, wn * 64 + j * 16, lane);
    }

    auto issue = [&](int kt) {
        const uint32_t st = sb + (uint32_t)(kt % N_STAGES) * STAGE_BYTES;
        const int k0 = kt * 32;
        #pragma unroll
        for (int i = 0; i < 4; i++) {
            const __half* src = (aPl[i] ? alo : ahi)
                + (size_t)(m0 + aR[i]) * I_DIM + k0 + aCh[i] * 8;
            CP_ASYNC16(st + aDst[i], src);
        }
        #pragma unroll
        for (int i = 0; i < 8; i++) {
            const __half* src = (bPl[i] ? dwl : dwh)
                + (size_t)(n0 + bR[i]) * I_DIM + k0 + bCh[i] * 8;
            CP_ASYNC16(st + bDst[i], src);
        }
    };

    float cd[4][8][4] = {};

    issue(0); CP_COMMIT();
    issue(1); CP_COMMIT();

    const int NK = I_DIM / 32;
    #pragma unroll 1
    for (int kt = 0; kt < NK; ++kt) {
        CP_WAIT1();
        __syncthreads();
        if (kt + 2 < NK) issue(kt + 2);
        CP_COMMIT();

        const uint32_t cur = sb + (uint32_t)(kt % N_STAGES) * STAGE_BYTES;
        #pragma unroll
        for (int kk = 0; kk < 2; ++kk) {
            const uint32_t kb = cur + (uint32_t)(kk * 32);
            uint32_t ah[4][4], al[4][4];
            #pragma unroll
            for (int mi = 0; mi < 4; mi++) {
                ldm_x4(kb + rAh[mi], ah[mi]);
                ldm_x4(kb + rAl[mi], al[mi]);
            }
            uint32_t h[4][4], l[4][4];
            #pragma unroll
            for (int j = 0; j < 4; j++) {
                ldm_x4(kb + rBh[j], h[j]);
                ldm_x4(kb + rBl[j], l[j]);
            }
            uint32_t bh[8][2], bl[8][2];
            #pragma unroll
            for (int j = 0; j < 4; j++) {
                bh[j*2][0]   = h[j][0]; bh[j*2][1]   = h[j][2];
                bh[j*2+1][0] = h[j][1]; bh[j*2+1][1] = h[j][3];
                bl[j*2][0]   = l[j][0]; bl[j*2][1]   = l[j][2];
                bl[j*2+1][0] = l[j][1]; bl[j*2+1][1] = l[j][3];
            }
            #pragma unroll
            for (int mi = 0; mi < 4; mi++)
                #pragma unroll
                for (int ni = 0; ni < 8; ni++) {
                    mma_f16(cd[mi][ni], ah[mi], bh[ni][0], bh[ni][1]);
                    mma_f16(cd[mi][ni], ah[mi], bl[ni][0], bl[ni][1]);
                    mma_f16(cd[mi][ni], al[mi], bh[ni][0], bh[ni][1]);
                }
        }
    }

    // epilogue: weighted atomic scatter (out pre-zeroed)
    const int gr = lane >> 2, tc = (lane & 3) * 2;
    #pragma unroll
    for (int mi = 0; mi < 4; mi++) {
        #pragma unroll
        for (int half = 0; half < 2; half++) {
            int mloc = wm * 64 + mi * 16 + gr + half * 8;
            if (m0 + mloc >= ne) continue;
            int   t = toks[mloc];
            float w = wgts[mloc];
            float* orow = out + (size_t)t * H_DIM;
            #pragma unroll
            for (int ni = 0; ni < 8; ni++) {
                int ncol = n0 + wn * 64 + ni * 8 + tc;
                atomicAdd(orow + ncol,     w * cd[mi][ni][half * 2]);
                atomicAdd(orow + ncol + 1, w * cd[mi][ni][half * 2 + 1]);
            }
        }
    }
}

// ---------------------------------------------------------------------------
// Launch (order chosen so ncu -s 5 -c 1 captures gemm1_mma)
// ---------------------------------------------------------------------------
extern "C" void kernel_launch(void* const* d_in, const int* in_sizes, int n_in,
                              void* d_out, int out_size)
{
    const float* x  = (const float*)d_in[0];
    const float* gw = (const float*)d_in[1];
    const float* eb = (const float*)d_in[2];
    const float* gp = (const float*)d_in[3];
    const float* up = (const float*)d_in[4];
    const float* dp = (const float*)d_in[5];
    const float* sg = (const float*)d_in[6];
    const float* su = (const float*)d_in[7];
    const float* sd = (const float*)d_in[8];
    float* out = (float*)d_out;

    cudaFuncSetAttribute((const void*)gemm1_mma, cudaFuncAttributeMaxDynamicSharedMemorySize, SMEM_DYN);
    cudaFuncSetAttribute((const void*)gemm2_mma, cudaFuncAttributeMaxDynamicSharedMemorySize, SMEM_DYN);

    // 1-2: splits (independent of routing)
    split_weights_kernel<<<4096, 256>>>((const float4*)gp, (const float4*)up,
                                        (const float4*)dp, (const float4*)sg,
                                        (const float4*)su, (const float4*)sd);
    split_x_kernel<<<1024, 256>>>((const float4*)x);
    // 3-4: zeroing
    zero_counts_kernel<<<1, 32>>>();
    zero_out_kernel<<<1024, 256>>>((float4*)out, out_size / 4);
    // 5: routing
    route_kernel<<<T_TOK, 256>>>(x, gw, eb);
    // 6: GEMM1 (profiled by ncu -s 5 -c 1)
    gemm1_mma<<<dim3(I_DIM / 128, T_TOK / 128, N_EXP + 1), 256, SMEM_DYN>>>();
    // 7: GEMM2
    gemm2_mma<<<dim3(H_DIM / 256, T_TOK / 128, N_EXP + 1), 256, SMEM_DYN>>>(out);
}

// round 9
// speedup vs baseline: 1.4635x; 1.3447x over previous
#include <cuda_runtime.h>
#include <cuda_fp16.h>
#include <stdint.h>
#include <math.h>

#define T_TOK 2048
#define H_DIM 2048
#define I_DIM 1024
#define N_EXP 16
#define TOPK  4
#define NGRP  4
#define GSZ   4
#define SCALING 2.5f

// GEMM1 stage: AH(10240) GH(10240) GL(10240) UH(10240) UL(10240) = 51200
// GEMM2 stage: AH(10240) BH(20480) BL(20480) = 51200
#define STAGE_BYTES 51200u
#define N_STAGES    3
#define SMEM_DYN    (N_STAGES * STAGE_BYTES)   // 153600

// ---------------------------------------------------------------------------
// Scratch (device globals — no allocation allowed)
// A-side operands quantized fp16 (single plane); B-side weights exact hi+lo.
// ---------------------------------------------------------------------------
__device__ int   d_counts[N_EXP];
__device__ int   d_tok[N_EXP][T_TOK];
__device__ float d_wgt[N_EXP][T_TOK];
__device__ __half d_h1 [N_EXP][T_TOK][I_DIM];
__device__ __half d_h1s[T_TOK][I_DIM];
__device__ __half d_xh[T_TOK * H_DIM];
__device__ __half d_gph[N_EXP * I_DIM * H_DIM], d_gpl[N_EXP * I_DIM * H_DIM];
__device__ __half d_uph[N_EXP * I_DIM * H_DIM], d_upl[N_EXP * I_DIM * H_DIM];
__device__ __half d_dph[N_EXP * H_DIM * I_DIM], d_dpl[N_EXP * H_DIM * I_DIM];
__device__ __half d_sgh[I_DIM * H_DIM],         d_sgl[I_DIM * H_DIM];
__device__ __half d_suh[I_DIM * H_DIM],         d_sul[I_DIM * H_DIM];
__device__ __half d_sdh[H_DIM * I_DIM],         d_sdl[H_DIM * I_DIM];

// ---------------------------------------------------------------------------
// PTX helpers (baseline sm_80+ only — must compile under compute_103)
// ---------------------------------------------------------------------------
__device__ __forceinline__ uint32_t smem_u32(const void* p) {
    uint32_t a;
    asm("{ .reg .u64 t; cvta.to.shared.u64 t, %1; cvt.u32.u64 %0, t; }"
        : "=r"(a) : "l"(p));
    return a;
}

__device__ __forceinline__ void ldm_x4(uint32_t addr, uint32_t r[4]) {
    asm volatile("ldmatrix.sync.aligned.m8n8.x4.shared.b16 {%0,%1,%2,%3}, [%4];"
                 : "=r"(r[0]), "=r"(r[1]), "=r"(r[2]), "=r"(r[3]) : "r"(addr));
}

__device__ __forceinline__ void mma_f16(float d[4], const uint32_t a[4],
                                        uint32_t b0, uint32_t b1) {
    asm volatile(
        "mma.sync.aligned.m16n8k16.row.col.f32.f16.f16.f32 "
        "{%0,%1,%2,%3}, {%4,%5,%6,%7}, {%8,%9}, {%0,%1,%2,%3};"
        : "+f"(d[0]), "+f"(d[1]), "+f"(d[2]), "+f"(d[3])
        : "r"(a[0]), "r"(a[1]), "r"(a[2]), "r"(a[3]), "r"(b0), "r"(b1));
}

#define CP_ASYNC16(dst, src) \
    asm volatile("cp.async.cg.shared.global [%0], [%1], 16;" \
                 :: "r"(dst), "l"(src) : "memory")
#define CP_COMMIT()  asm volatile("cp.async.commit_group;" ::: "memory")
#define CP_WAIT1()   asm volatile("cp.async.wait_group 1;" ::: "memory")

// pack two floats into fp16x2 word (quantize)
__device__ __forceinline__ uint32_t pack2(float f0, float f1) {
    __half h0 = __float2half_rn(f0);
    __half h1 = __float2half_rn(f1);
    return (uint32_t)__half_as_ushort(h0) | ((uint32_t)__half_as_ushort(h1) << 16);
}

// fp16 residual split (exact B representation)
__device__ __forceinline__ void split2(float f0, float f1, uint32_t& hw, uint32_t& lw) {
    __half h0 = __float2half_rn(f0);
    __half h1 = __float2half_rn(f1);
    __half l0 = __float2half_rn(f0 - __half2float(h0));
    __half l1 = __float2half_rn(f1 - __half2float(h1));
    hw = (uint32_t)__half_as_ushort(h0) | ((uint32_t)__half_as_ushort(h1) << 16);
    lw = (uint32_t)__half_as_ushort(l0) | ((uint32_t)__half_as_ushort(l1) << 16);
}

__device__ __forceinline__ void split4(float4 f, uint2& hw, uint2& lw) {
    split2(f.x, f.y, hw.x, lw.x);
    split2(f.z, f.w, hw.y, lw.y);
}

// stage-relative ldmatrix offset within a padded [rows][40] fp16 plane
__device__ __forceinline__ uint32_t ldrel(uint32_t plane, int rbase, int lane) {
    int row = rbase + (lane & 15);
    int col = (lane >> 4) << 3;
    return plane + (uint32_t)((row * 40 + col) << 1);
}

// ---------------------------------------------------------------------------
// Split / quantize kernels
// ---------------------------------------------------------------------------
#define SEG_GP 8388608
#define SEG_UP 16777216
#define SEG_DP 25165824
#define SEG_SG 25690112
#define SEG_SU 26214400
#define SEG_SD 26738688

__global__ __launch_bounds__(256) void split_weights_kernel(
    const float4* __restrict__ gp, const float4* __restrict__ up,
    const float4* __restrict__ dp, const float4* __restrict__ sg,
    const float4* __restrict__ su, const float4* __restrict__ sd)
{
    int i = blockIdx.x * blockDim.x + threadIdx.x;
    const int stride = gridDim.x * blockDim.x;
    for (; i < SEG_SD; i += stride) {
        const float4* src; uint2 *hi, *lo; int off;
        if (i < SEG_GP)      { src = gp; off = i;            hi = (uint2*)d_gph; lo = (uint2*)d_gpl; }
        else if (i < SEG_UP) { src = up; off = i - SEG_GP;   hi = (uint2*)d_uph; lo = (uint2*)d_upl; }
        else if (i < SEG_DP) { src = dp; off = i - SEG_UP;   hi = (uint2*)d_dph; lo = (uint2*)d_dpl; }
        else if (i < SEG_SG) { src = sg; off = i - SEG_DP;   hi = (uint2*)d_sgh; lo = (uint2*)d_sgl; }
        else if (i < SEG_SU) { src = su; off = i - SEG_SG;   hi = (uint2*)d_suh; lo = (uint2*)d_sul; }
        else                 { src = sd; off = i - SEG_SU;   hi = (uint2*)d_sdh; lo = (uint2*)d_sdl; }
        float4 f = src[off];
        uint2 h, l; split4(f, h, l);
        hi[off] = h; lo[off] = l;
    }
}

__global__ __launch_bounds__(256) void split_x_kernel(const float4* __restrict__ x)
{
    int i = blockIdx.x * blockDim.x + threadIdx.x;
    const int stride = gridDim.x * blockDim.x;
    const int n4 = T_TOK * H_DIM / 4;
    for (; i < n4; i += stride) {
        float4 f = x[i];
        uint2 h;
        h.x = pack2(f.x, f.y);
        h.y = pack2(f.z, f.w);
        ((uint2*)d_xh)[i] = h;
    }
}

__global__ __launch_bounds__(256) void zero_out_kernel(float4* __restrict__ out, int n4)
{
    int i = blockIdx.x * blockDim.x + threadIdx.x;
    int stride = gridDim.x * blockDim.x;
    float4 z = {0.f, 0.f, 0.f, 0.f};
    for (; i < n4; i += stride) out[i] = z;
}

__global__ void zero_counts_kernel() {
    if (threadIdx.x < N_EXP) d_counts[threadIdx.x] = 0;
}

// ---------------------------------------------------------------------------
// Routing (proven)
// ---------------------------------------------------------------------------
__global__ __launch_bounds__(256) void route_kernel(
    const float* __restrict__ x, const float* __restrict__ gw,
    const float* __restrict__ bias)
{
    __shared__ float xs[H_DIM];
    __shared__ float logits[N_EXP];
    const int t = blockIdx.x;
    const float* xr = x + (size_t)t * H_DIM;
    for (int i = threadIdx.x; i < H_DIM; i += blockDim.x) xs[i] = xr[i];
    __syncthreads();

    const int e = threadIdx.x >> 4, lane = threadIdx.x & 15;
    const float* g = gw + (size_t)e * H_DIM;
    float s = 0.f;
    for (int k = lane; k < H_DIM; k += 16) s += xs[k] * g[k];
    #pragma unroll
    for (int o = 8; o > 0; o >>= 1) s += __shfl_down_sync(0xffffffffu, s, o, 16);
    if (lane == 0) logits[e] = s;
    __syncthreads();

    if (threadIdx.x == 0) {
        float sc[N_EXP], bs[N_EXP];
        #pragma unroll
        for (int i = 0; i < N_EXP; i++) {
            sc[i] = 1.f / (1.f + expf(-logits[i]));
            bs[i] = sc[i] + bias[i];
        }
        float gsc[NGRP];
        #pragma unroll
        for (int gi = 0; gi < NGRP; gi++) {
            float m1 = -1e30f, m2 = -1e30f;
            #pragma unroll
            for (int j = 0; j < GSZ; j++) {
                float v = bs[gi * GSZ + j];
                if (v > m1) { m2 = m1; m1 = v; } else if (v > m2) { m2 = v; }
            }
            gsc[gi] = m1 + m2;
        }
        int g1 = 0;
        for (int gi = 1; gi < NGRP; gi++) if (gsc[gi] > gsc[g1]) g1 = gi;
        int g2 = -1;
        for (int gi = 0; gi < NGRP; gi++) {
            if (gi == g1) continue;
            if (g2 < 0 || gsc[gi] > gsc[g2]) g2 = gi;
        }
        bool allowed[N_EXP], used[N_EXP];
        #pragma unroll
        for (int i = 0; i < N_EXP; i++) {
            int gi = i / GSZ;
            allowed[i] = (gi == g1 || gi == g2);
            used[i] = false;
        }
        int sel[TOPK]; float wv[TOPK]; float wsum = 0.f;
        #pragma unroll
        for (int kk = 0; kk < TOPK; kk++) {
            int best = -1; float bv = -1e30f;
            for (int i = 0; i < N_EXP; i++) {
                if (!allowed[i] || used[i]) continue;
                if (best < 0 || bs[i] > bv) { best = i; bv = bs[i]; }
            }
            used[best] = true; sel[kk] = best; wv[kk] = sc[best]; wsum += sc[best];
        }
        const float inv = SCALING / (wsum + 1e-20f);
        #pragma unroll
        for (int kk = 0; kk < TOPK; kk++) {
            int ee = sel[kk];
            int slot = atomicAdd(&d_counts[ee], 1);
            d_tok[ee][slot] = t;
            d_wgt[ee][slot] = wv[kk] * inv;
        }
    }
}

// ---------------------------------------------------------------------------
// GEMM1: 256 threads (8 warps = 2m x 4n), CTA tile M=128 x N=128 x BK=32.
// Warp tile 64m x 32n, dual output (gate & up). z==N_EXP => shared expert.
// D = Ah*Bh + Ah*Bl (A quantized fp16, B exact hi+lo). Two-pass MMA for ILP.
// Stage planes: AH 0, GH 10240, GL 20480, UH 30720, UL 40960.
// ---------------------------------------------------------------------------
__global__ __launch_bounds__(256) void gemm1_mma()
{
    const int e = blockIdx.z;
    const bool shared = (e == N_EXP);
    const int ne = shared ? T_TOK : d_counts[e];
    const int m0 = blockIdx.y * 128;
    if (m0 >= ne) return;
    const int n0 = blockIdx.x * 128;

    extern __shared__ __align__(16) char dynsmem[];
    __shared__ int toks[128];

    const int tid = threadIdx.x, lane = tid & 31, wid = tid >> 5;
    const int wm = wid >> 2, wn = wid & 3;
    const uint32_t sb = smem_u32(dynsmem);

    if (tid < 128) {
        int r = m0 + tid;
        toks[tid] = shared ? r : (r < ne ? d_tok[e][r] : d_tok[e][0]);
    }
    __syncthreads();

    const size_t eoff = shared ? 0 : (size_t)e * I_DIM * H_DIM;
    const __half* ghP = shared ? d_sgh : d_gph + eoff;
    const __half* glP = shared ? d_sgl : d_gpl + eoff;
    const __half* uhP = shared ? d_suh : d_uph + eoff;
    const __half* ulP = shared ? d_sul : d_upl + eoff;

    // A: 512 chunks (2/thr); B: 4 planes x 512 = 2048 chunks (8/thr)
    int aR[2], aCh[2];
    uint32_t aDst[2];
    #pragma unroll
    for (int i = 0; i < 2; i++) {
        int c = tid + 256 * i;
        aR[i] = c >> 2; aCh[i] = c & 3;
        aDst[i] = (uint32_t)(aR[i] * 80 + aCh[i] * 16);
    }
    int bW[8], bR[8], bCh[8];
    uint32_t bDst[8];
    #pragma unroll
    for (int i = 0; i < 8; i++) {
        int c = tid + 256 * i;
        bW[i] = c >> 9; bR[i] = (c >> 2) & 127; bCh[i] = c & 3;
        bDst[i] = (uint32_t)(10240 + bW[i] * 10240 + bR[i] * 80 + bCh[i] * 16);
    }

    uint32_t rA[4];
    #pragma unroll
    for (int mi = 0; mi < 4; mi++)
        rA[mi] = ldrel(0u, wm * 64 + mi * 16, lane);
    const uint32_t rGh0 = ldrel(10240u, wn * 32,      lane);
    const uint32_t rGh1 = ldrel(10240u, wn * 32 + 16, lane);
    const uint32_t rGl0 = ldrel(20480u, wn * 32,      lane);
    const uint32_t rGl1 = ldrel(20480u, wn * 32 + 16, lane);
    const uint32_t rUh0 = ldrel(30720u, wn * 32,      lane);
    const uint32_t rUh1 = ldrel(30720u, wn * 32 + 16, lane);
    const uint32_t rUl0 = ldrel(40960u, wn * 32,      lane);
    const uint32_t rUl1 = ldrel(40960u, wn * 32 + 16, lane);

    auto issue = [&](int kt) {
        const uint32_t st = sb + (uint32_t)(kt % N_STAGES) * STAGE_BYTES;
        const int k0 = kt * 32;
        #pragma unroll
        for (int i = 0; i < 2; i++) {
            const __half* src = d_xh + (size_t)toks[aR[i]] * H_DIM + k0 + aCh[i] * 8;
            CP_ASYNC16(st + aDst[i], src);
        }
        #pragma unroll
        for (int i = 0; i < 8; i++) {
            const __half* base =
                (bW[i] == 0) ? ghP : (bW[i] == 1) ? glP : (bW[i] == 2) ? uhP : ulP;
            const __half* src = base + (size_t)(n0 + bR[i]) * H_DIM + k0 + bCh[i] * 8;
            CP_ASYNC16(st + bDst[i], src);
        }
    };

    float cg[4][4][4] = {}, cu[4][4][4] = {};

    issue(0); CP_COMMIT();
    issue(1); CP_COMMIT();

    const int NK = H_DIM / 32;
    #pragma unroll 1
    for (int kt = 0; kt < NK; ++kt) {
        CP_WAIT1();
        __syncthreads();
        if (kt + 2 < NK) issue(kt + 2);
        CP_COMMIT();

        const uint32_t cur = sb + (uint32_t)(kt % N_STAGES) * STAGE_BYTES;
        #pragma unroll
        for (int kk = 0; kk < 2; ++kk) {
            const uint32_t kb = cur + (uint32_t)(kk * 32);
            uint32_t a[4][4];
            #pragma unroll
            for (int mi = 0; mi < 4; mi++)
                ldm_x4(kb + rA[mi], a[mi]);
            {   // gate: pass1 hh, pass2 hl (32-apart same-acc writes)
                uint32_t h0[4], h1[4], l0[4], l1[4];
                ldm_x4(kb + rGh0, h0); ldm_x4(kb + rGh1, h1);
                ldm_x4(kb + rGl0, l0); ldm_x4(kb + rGl1, l1);
                uint32_t bh[4][2] = {{h0[0],h0[2]},{h0[1],h0[3]},{h1[0],h1[2]},{h1[1],h1[3]}};
                uint32_t bl[4][2] = {{l0[0],l0[2]},{l0[1],l0[3]},{l1[0],l1[2]},{l1[1],l1[3]}};
                #pragma unroll
                for (int mi = 0; mi < 4; mi++)
                    #pragma unroll
                    for (int ni = 0; ni < 4; ni++)
                        mma_f16(cg[mi][ni], a[mi], bh[ni][0], bh[ni][1]);
                #pragma unroll
                for (int mi = 0; mi < 4; mi++)
                    #pragma unroll
                    for (int ni = 0; ni < 4; ni++)
                        mma_f16(cg[mi][ni], a[mi], bl[ni][0], bl[ni][1]);
            }
            {   // up
                uint32_t h0[4], h1[4], l0[4], l1[4];
                ldm_x4(kb + rUh0, h0); ldm_x4(kb + rUh1, h1);
                ldm_x4(kb + rUl0, l0); ldm_x4(kb + rUl1, l1);
                uint32_t bh[4][2] = {{h0[0],h0[2]},{h0[1],h0[3]},{h1[0],h1[2]},{h1[1],h1[3]}};
                uint32_t bl[4][2] = {{l0[0],l0[2]},{l0[1],l0[3]},{l1[0],l1[2]},{l1[1],l1[3]}};
                #pragma unroll
                for (int mi = 0; mi < 4; mi++)
                    #pragma unroll
                    for (int ni = 0; ni < 4; ni++)
                        mma_f16(cu[mi][ni], a[mi], bh[ni][0], bh[ni][1]);
                #pragma unroll
                for (int mi = 0; mi < 4; mi++)
                    #pragma unroll
                    for (int ni = 0; ni < 4; ni++)
                        mma_f16(cu[mi][ni], a[mi], bl[ni][0], bl[ni][1]);
            }
        }
    }

    // epilogue: silu(g)*u -> single fp16 plane
    const int gr = lane >> 2, tc = (lane & 3) * 2;
    __half* ph = shared ? &d_h1s[0][0] : &d_h1[e][0][0];

    #pragma unroll
    for (int mi = 0; mi < 4; mi++)
        #pragma unroll
        for (int ni = 0; ni < 4; ni++) {
            int ncol = n0 + wn * 32 + ni * 8 + tc;
            #pragma unroll
            for (int half = 0; half < 2; half++) {
                int m = m0 + wm * 64 + mi * 16 + gr + half * 8;
                float g0 = cg[mi][ni][half * 2],     u0 = cu[mi][ni][half * 2];
                float g1 = cg[mi][ni][half * 2 + 1], u1 = cu[mi][ni][half * 2 + 1];
                float o0 = (g0 / (1.f + expf(-g0))) * u0;
                float o1 = (g1 / (1.f + expf(-g1))) * u1;
                *(uint32_t*)(ph + (size_t)m * I_DIM + ncol) = pack2(o0, o1);
            }
        }
}

// ---------------------------------------------------------------------------
// GEMM2: 256 threads (8 warps = 2m x 4n), CTA tile M=128 x N=256 x BK=32.
// Warp tile 64m x 64n. A = h1 fp16 single plane; B = down exact hi+lo.
// Stage planes: AH 0, BH 10240 (20480B), BL 30720 (20480B).
// ---------------------------------------------------------------------------
__global__ __launch_bounds__(256) void gemm2_mma(float* __restrict__ out)
{
    const int e = blockIdx.z;
    const bool shared = (e == N_EXP);
    const int ne = shared ? T_TOK : d_counts[e];
    const int m0 = blockIdx.y * 128;
    if (m0 >= ne) return;
    const int n0 = blockIdx.x * 256;

    extern __shared__ __align__(16) char dynsmem[];
    __shared__ int   toks[128];
    __shared__ float wgts[128];

    const int tid = threadIdx.x, lane = tid & 31, wid = tid >> 5;
    const int wm = wid >> 2, wn = wid & 3;
    const uint32_t sb = smem_u32(dynsmem);

    if (tid < 128) {
        int r = m0 + tid;
        if (shared) { toks[tid] = r; wgts[tid] = 1.f; }
        else {
            toks[tid] = (r < ne) ? d_tok[e][r] : 0;
            wgts[tid] = (r < ne) ? d_wgt[e][r] : 0.f;
        }
    }
    __syncthreads();

    const __half* ah1 = shared ? &d_h1s[0][0] : &d_h1[e][0][0];
    const size_t eoff = shared ? 0 : (size_t)e * H_DIM * I_DIM;
    const __half* dwh = shared ? d_sdh : d_dph + eoff;
    const __half* dwl = shared ? d_sdl : d_dpl + eoff;

    // A: 512 chunks (2/thr); B: 2 planes x 1024 = 2048 chunks (8/thr)
    int aR[2], aCh[2];
    uint32_t aDst[2];
    #pragma unroll
    for (int i = 0; i < 2; i++) {
        int c = tid + 256 * i;
        aR[i] = c >> 2; aCh[i] = c & 3;
        aDst[i] = (uint32_t)(aR[i] * 80 + aCh[i] * 16);
    }
    int bPl[8], bR[8], bCh[8];
    uint32_t bDst[8];
    #pragma unroll
    for (int i = 0; i < 8; i++) {
        int c = tid + 256 * i;
        bPl[i] = c >> 10; bR[i] = (c >> 2) & 255; bCh[i] = c & 3;
        bDst[i] = (uint32_t)(10240 + bPl[i] * 20480 + bR[i] * 80 + bCh[i] * 16);
    }

    uint32_t rA[4];
    #pragma unroll
    for (int mi = 0; mi < 4; mi++)
        rA[mi] = ldrel(0u, wm * 64 + mi * 16, lane);
    uint32_t rBh[4], rBl[4];
    #pragma unroll
    for (int j = 0; j < 4; j++) {
        rBh[j] = ldrel(10240u, wn * 64 + j * 16, lane);
        rBl[j] = ldrel(30720u, wn * 64 + j * 16, lane);
    }

    auto issue = [&](int kt) {
        const uint32_t st = sb + (uint32_t)(kt % N_STAGES) * STAGE_BYTES;
        const int k0 = kt * 32;
        #pragma unroll
        for (int i = 0; i < 2; i++) {
            const __half* src = ah1 + (size_t)(m0 + aR[i]) * I_DIM + k0 + aCh[i] * 8;
            CP_ASYNC16(st + aDst[i], src);
        }
        #pragma unroll
        for (int i = 0; i < 8; i++) {
            const __half* src = (bPl[i] ? dwl : dwh)
                + (size_t)(n0 + bR[i]) * I_DIM + k0 + bCh[i] * 8;
            CP_ASYNC16(st + bDst[i], src);
        }
    };

    float cd[4][8][4] = {};

    issue(0); CP_COMMIT();
    issue(1); CP_COMMIT();

    const int NK = I_DIM / 32;
    #pragma unroll 1
    for (int kt = 0; kt < NK; ++kt) {
        CP_WAIT1();
        __syncthreads();
        if (kt + 2 < NK) issue(kt + 2);
        CP_COMMIT();

        const uint32_t cur = sb + (uint32_t)(kt % N_STAGES) * STAGE_BYTES;
        #pragma unroll
        for (int kk = 0; kk < 2; ++kk) {
            const uint32_t kb = cur + (uint32_t)(kk * 32);
            uint32_t a[4][4];
            #pragma unroll
            for (int mi = 0; mi < 4; mi++)
                ldm_x4(kb + rA[mi], a[mi]);
            uint32_t h[4][4], l[4][4];
            #pragma unroll
            for (int j = 0; j < 4; j++) {
                ldm_x4(kb + rBh[j], h[j]);
                ldm_x4(kb + rBl[j], l[j]);
            }
            uint32_t bh[8][2], bl[8][2];
            #pragma unroll
            for (int j = 0; j < 4; j++) {
                bh[j*2][0]   = h[j][0]; bh[j*2][1]   = h[j][2];
                bh[j*2+1][0] = h[j][1]; bh[j*2+1][1] = h[j][3];
                bl[j*2][0]   = l[j][0]; bl[j*2][1]   = l[j][2];
                bl[j*2+1][0] = l[j][1]; bl[j*2+1][1] = l[j][3];
            }
            // pass1: hh, pass2: hl (32-apart same-acc writes)
            #pragma unroll
            for (int mi = 0; mi < 4; mi++)
                #pragma unroll
                for (int ni = 0; ni < 8; ni++)
                    mma_f16(cd[mi][ni], a[mi], bh[ni][0], bh[ni][1]);
            #pragma unroll
            for (int mi = 0; mi < 4; mi++)
                #pragma unroll
                for (int ni = 0; ni < 8; ni++)
                    mma_f16(cd[mi][ni], a[mi], bl[ni][0], bl[ni][1]);
        }
    }

    // epilogue: weighted atomic scatter (out pre-zeroed)
    const int gr = lane >> 2, tc = (lane & 3) * 2;
    #pragma unroll
    for (int mi = 0; mi < 4; mi++) {
        #pragma unroll
        for (int half = 0; half < 2; half++) {
            int mloc = wm * 64 + mi * 16 + gr + half * 8;
            if (m0 + mloc >= ne) continue;
            int   t = toks[mloc];
            float w = wgts[mloc];
            float* orow = out + (size_t)t * H_DIM;
            #pragma unroll
            for (int ni = 0; ni < 8; ni++) {
                int ncol = n0 + wn * 64 + ni * 8 + tc;
                atomicAdd(orow + ncol,     w * cd[mi][ni][half * 2]);
                atomicAdd(orow + ncol + 1, w * cd[mi][ni][half * 2 + 1]);
            }
        }
    }
}

// ---------------------------------------------------------------------------
// Launch
// ---------------------------------------------------------------------------
extern "C" void kernel_launch(void* const* d_in, const int* in_sizes, int n_in,
                              void* d_out, int out_size)
{
    const float* x  = (const float*)d_in[0];
    const float* gw = (const float*)d_in[1];
    const float* eb = (const float*)d_in[2];
    const float* gp = (const float*)d_in[3];
    const float* up = (const float*)d_in[4];
    const float* dp = (const float*)d_in[5];
    const float* sg = (const float*)d_in[6];
    const float* su = (const float*)d_in[7];
    const float* sd = (const float*)d_in[8];
    float* out = (float*)d_out;

    cudaFuncSetAttribute((const void*)gemm1_mma, cudaFuncAttributeMaxDynamicSharedMemorySize, SMEM_DYN);
    cudaFuncSetAttribute((const void*)gemm2_mma, cudaFuncAttributeMaxDynamicSharedMemorySize, SMEM_DYN);

    split_weights_kernel<<<4096, 256>>>((const float4*)gp, (const float4*)up,
                                        (const float4*)dp, (const float4*)sg,
                                        (const float4*)su, (const float4*)sd);
    split_x_kernel<<<1024, 256>>>((const float4*)x);
    zero_counts_kernel<<<1, 32>>>();
    zero_out_kernel<<<1024, 256>>>((float4*)out, out_size / 4);
    route_kernel<<<T_TOK, 256>>>(x, gw, eb);

    gemm1_mma<<<dim3(I_DIM / 128, T_TOK / 128, N_EXP + 1), 256, SMEM_DYN>>>();
    gemm2_mma<<<dim3(H_DIM / 256, T_TOK / 128, N_EXP + 1), 256, SMEM_DYN>>>(out);
}

// round 10
// speedup vs baseline: 2.3861x; 1.6304x over previous
#include <cuda_runtime.h>
#include <cuda_fp16.h>
#include <stdint.h>
#include <math.h>

#define T_TOK 2048
#define H_DIM 2048
#define I_DIM 1024
#define N_EXP 16
#define TOPK  4
#define NGRP  4
#define GSZ   4
#define SCALING 2.5f

// GEMM1 stage: A(10240) G(10240) U(10240) = 30720
// GEMM2 stage: A(10240) B(20480)          = 30720
#define STAGE_BYTES 30720u
#define N_STAGES    4
#define SMEM_DYN    (N_STAGES * STAGE_BYTES)   // 122880

// ---------------------------------------------------------------------------
// Scratch (device globals — no allocation allowed). Everything plain fp16.
// ---------------------------------------------------------------------------
__device__ int   d_counts[N_EXP];
__device__ int   d_tok[N_EXP][T_TOK];
__device__ float d_wgt[N_EXP][T_TOK];
__device__ __half d_h1 [N_EXP][T_TOK][I_DIM];
__device__ __half d_h1s[T_TOK][I_DIM];
__device__ __half d_x16[T_TOK * H_DIM];
__device__ __half d_gp16[N_EXP * I_DIM * H_DIM];
__device__ __half d_up16[N_EXP * I_DIM * H_DIM];
__device__ __half d_dp16[N_EXP * H_DIM * I_DIM];
__device__ __half d_sg16[I_DIM * H_DIM];
__device__ __half d_su16[I_DIM * H_DIM];
__device__ __half d_sd16[H_DIM * I_DIM];

// ---------------------------------------------------------------------------
// PTX helpers (baseline sm_80+ only — must compile under compute_103)
// ---------------------------------------------------------------------------
__device__ __forceinline__ uint32_t smem_u32(const void* p) {
    uint32_t a;
    asm("{ .reg .u64 t; cvta.to.shared.u64 t, %1; cvt.u32.u64 %0, t; }"
        : "=r"(a) : "l"(p));
    return a;
}

__device__ __forceinline__ void ldm_x4(uint32_t addr, uint32_t r[4]) {
    asm volatile("ldmatrix.sync.aligned.m8n8.x4.shared.b16 {%0,%1,%2,%3}, [%4];"
                 : "=r"(r[0]), "=r"(r[1]), "=r"(r[2]), "=r"(r[3]) : "r"(addr));
}

__device__ __forceinline__ void mma_f16(float d[4], const uint32_t a[4],
                                        uint32_t b0, uint32_t b1) {
    asm volatile(
        "mma.sync.aligned.m16n8k16.row.col.f32.f16.f16.f32 "
        "{%0,%1,%2,%3}, {%4,%5,%6,%7}, {%8,%9}, {%0,%1,%2,%3};"
        : "+f"(d[0]), "+f"(d[1]), "+f"(d[2]), "+f"(d[3])
        : "r"(a[0]), "r"(a[1]), "r"(a[2]), "r"(a[3]), "r"(b0), "r"(b1));
}

#define CP_ASYNC16(dst, src) \
    asm volatile("cp.async.cg.shared.global [%0], [%1], 16;" \
                 :: "r"(dst), "l"(src) : "memory")
#define CP_COMMIT()  asm volatile("cp.async.commit_group;" ::: "memory")
#define CP_WAIT2()   asm volatile("cp.async.wait_group 2;" ::: "memory")

__device__ __forceinline__ uint32_t pack2(float f0, float f1) {
    __half h0 = __float2half_rn(f0);
    __half h1 = __float2half_rn(f1);
    return (uint32_t)__half_as_ushort(h0) | ((uint32_t)__half_as_ushort(h1) << 16);
}

// stage-relative ldmatrix offset within a padded [rows][40] fp16 plane
__device__ __forceinline__ uint32_t ldrel(uint32_t plane, int rbase, int lane) {
    int row = rbase + (lane & 15);
    int col = (lane >> 4) << 3;
    return plane + (uint32_t)((row * 40 + col) << 1);
}

// ---------------------------------------------------------------------------
// Convert kernels (fp32 -> fp16)
// ---------------------------------------------------------------------------
#define SEG_GP 8388608
#define SEG_UP 16777216
#define SEG_DP 25165824
#define SEG_SG 25690112
#define SEG_SU 26214400
#define SEG_SD 26738688

__global__ __launch_bounds__(256) void split_weights_kernel(
    const float4* __restrict__ gp, const float4* __restrict__ up,
    const float4* __restrict__ dp, const float4* __restrict__ sg,
    const float4* __restrict__ su, const float4* __restrict__ sd)
{
    int i = blockIdx.x * blockDim.x + threadIdx.x;
    const int stride = gridDim.x * blockDim.x;
    for (; i < SEG_SD; i += stride) {
        const float4* src; uint2* h16; int off;
        if (i < SEG_GP)      { src = gp; off = i;            h16 = (uint2*)d_gp16; }
        else if (i < SEG_UP) { src = up; off = i - SEG_GP;   h16 = (uint2*)d_up16; }
        else if (i < SEG_DP) { src = dp; off = i - SEG_UP;   h16 = (uint2*)d_dp16; }
        else if (i < SEG_SG) { src = sg; off = i - SEG_DP;   h16 = (uint2*)d_sg16; }
        else if (i < SEG_SU) { src = su; off = i - SEG_SG;   h16 = (uint2*)d_su16; }
        else                 { src = sd; off = i - SEG_SU;   h16 = (uint2*)d_sd16; }
        float4 f = src[off];
        uint2 h; h.x = pack2(f.x, f.y); h.y = pack2(f.z, f.w);
        h16[off] = h;
    }
}

// also zeroes the routing counters (one thread)
__global__ __launch_bounds__(256) void split_x_kernel(const float4* __restrict__ x)
{
    if (blockIdx.x == 0 && threadIdx.x < N_EXP) d_counts[threadIdx.x] = 0;
    int i = blockIdx.x * blockDim.x + threadIdx.x;
    const int stride = gridDim.x * blockDim.x;
    const int n4 = T_TOK * H_DIM / 4;
    for (; i < n4; i += stride) {
        float4 f = x[i];
        uint2 h; h.x = pack2(f.x, f.y); h.y = pack2(f.z, f.w);
        ((uint2*)d_x16)[i] = h;
    }
}

__global__ __launch_bounds__(256) void zero_out_kernel(float4* __restrict__ out, int n4)
{
    int i = blockIdx.x * blockDim.x + threadIdx.x;
    int stride = gridDim.x * blockDim.x;
    float4 z = {0.f, 0.f, 0.f, 0.f};
    for (; i < n4; i += stride) out[i] = z;
}

// ---------------------------------------------------------------------------
// Routing (proven)
// ---------------------------------------------------------------------------
__global__ __launch_bounds__(256) void route_kernel(
    const float* __restrict__ x, const float* __restrict__ gw,
    const float* __restrict__ bias)
{
    __shared__ float xs[H_DIM];
    __shared__ float logits[N_EXP];
    const int t = blockIdx.x;
    const float* xr = x + (size_t)t * H_DIM;
    for (int i = threadIdx.x; i < H_DIM; i += blockDim.x) xs[i] = xr[i];
    __syncthreads();

    const int e = threadIdx.x >> 4, lane = threadIdx.x & 15;
    const float* g = gw + (size_t)e * H_DIM;
    float s = 0.f;
    for (int k = lane; k < H_DIM; k += 16) s += xs[k] * g[k];
    #pragma unroll
    for (int o = 8; o > 0; o >>= 1) s += __shfl_down_sync(0xffffffffu, s, o, 16);
    if (lane == 0) logits[e] = s;
    __syncthreads();

    if (threadIdx.x == 0) {
        float sc[N_EXP], bs[N_EXP];
        #pragma unroll
        for (int i = 0; i < N_EXP; i++) {
            sc[i] = 1.f / (1.f + expf(-logits[i]));
            bs[i] = sc[i] + bias[i];
        }
        float gsc[NGRP];
        #pragma unroll
        for (int gi = 0; gi < NGRP; gi++) {
            float m1 = -1e30f, m2 = -1e30f;
            #pragma unroll
            for (int j = 0; j < GSZ; j++) {
                float v = bs[gi * GSZ + j];
                if (v > m1) { m2 = m1; m1 = v; } else if (v > m2) { m2 = v; }
            }
            gsc[gi] = m1 + m2;
        }
        int g1 = 0;
        for (int gi = 1; gi < NGRP; gi++) if (gsc[gi] > gsc[g1]) g1 = gi;
        int g2 = -1;
        for (int gi = 0; gi < NGRP; gi++) {
            if (gi == g1) continue;
            if (g2 < 0 || gsc[gi] > gsc[g2]) g2 = gi;
        }
        bool allowed[N_EXP], used[N_EXP];
        #pragma unroll
        for (int i = 0; i < N_EXP; i++) {
            int gi = i / GSZ;
            allowed[i] = (gi == g1 || gi == g2);
            used[i] = false;
        }
        int sel[TOPK]; float wv[TOPK]; float wsum = 0.f;
        #pragma unroll
        for (int kk = 0; kk < TOPK; kk++) {
            int best = -1; float bv = -1e30f;
            for (int i = 0; i < N_EXP; i++) {
                if (!allowed[i] || used[i]) continue;
                if (best < 0 || bs[i] > bv) { best = i; bv = bs[i]; }
            }
            used[best] = true; sel[kk] = best; wv[kk] = sc[best]; wsum += sc[best];
        }
        const float inv = SCALING / (wsum + 1e-20f);
        #pragma unroll
        for (int kk = 0; kk < TOPK; kk++) {
            int ee = sel[kk];
            int slot = atomicAdd(&d_counts[ee], 1);
            d_tok[ee][slot] = t;
            d_wgt[ee][slot] = wv[kk] * inv;
        }
    }
}

// ---------------------------------------------------------------------------
// GEMM1: 256 threads (8 warps = 2m x 4n), CTA tile M=128 x N=128 x BK=32.
// Warp tile 64m x 32n, dual output (gate & up). Pure fp16 single-pass.
// Stage planes: A 0, G 10240, U 20480.
// ---------------------------------------------------------------------------
__global__ __launch_bounds__(256) void gemm1_mma()
{
    const int e = blockIdx.z;
    const bool shared = (e == N_EXP);
    const int ne = shared ? T_TOK : d_counts[e];
    const int m0 = blockIdx.y * 128;
    if (m0 >= ne) return;
    const int n0 = blockIdx.x * 128;

    extern __shared__ __align__(16) char dynsmem[];
    __shared__ int toks[128];

    const int tid = threadIdx.x, lane = tid & 31, wid = tid >> 5;
    const int wm = wid >> 2, wn = wid & 3;
    const uint32_t sb = smem_u32(dynsmem);

    if (tid < 128) {
        int r = m0 + tid;
        toks[tid] = shared ? r : (r < ne ? d_tok[e][r] : d_tok[e][0]);
    }
    __syncthreads();

    const size_t eoff = shared ? 0 : (size_t)e * I_DIM * H_DIM;
    const __half* gP = shared ? d_sg16 : d_gp16 + eoff;
    const __half* uP = shared ? d_su16 : d_up16 + eoff;

    // A: 512 chunks (2/thr); G/U: 1024 chunks (4/thr)
    int aR[2], aCh[2];
    uint32_t aDst[2];
    #pragma unroll
    for (int i = 0; i < 2; i++) {
        int c = tid + 256 * i;
        aR[i] = c >> 2; aCh[i] = c & 3;
        aDst[i] = (uint32_t)(aR[i] * 80 + aCh[i] * 16);
    }
    int bW[4], bR[4], bCh[4];
    uint32_t bDst[4];
    #pragma unroll
    for (int i = 0; i < 4; i++) {
        int c = tid + 256 * i;
        bW[i] = c >> 9; bR[i] = (c >> 2) & 127; bCh[i] = c & 3;
        bDst[i] = (uint32_t)(10240 + bW[i] * 10240 + bR[i] * 80 + bCh[i] * 16);
    }

    uint32_t rA[4];
    #pragma unroll
    for (int mi = 0; mi < 4; mi++)
        rA[mi] = ldrel(0u, wm * 64 + mi * 16, lane);
    const uint32_t rG0 = ldrel(10240u, wn * 32,      lane);
    const uint32_t rG1 = ldrel(10240u, wn * 32 + 16, lane);
    const uint32_t rU0 = ldrel(20480u, wn * 32,      lane);
    const uint32_t rU1 = ldrel(20480u, wn * 32 + 16, lane);

    auto issue = [&](int kt) {
        const uint32_t st = sb + (uint32_t)(kt % N_STAGES) * STAGE_BYTES;
        const int k0 = kt * 32;
        #pragma unroll
        for (int i = 0; i < 2; i++) {
            const __half* src = d_x16 + (size_t)toks[aR[i]] * H_DIM + k0 + aCh[i] * 8;
            CP_ASYNC16(st + aDst[i], src);
        }
        #pragma unroll
        for (int i = 0; i < 4; i++) {
            const __half* base = bW[i] ? uP : gP;
            const __half* src = base + (size_t)(n0 + bR[i]) * H_DIM + k0 + bCh[i] * 8;
            CP_ASYNC16(st + bDst[i], src);
        }
    };

    float cg[4][4][4] = {}, cu[4][4][4] = {};

    issue(0); CP_COMMIT();
    issue(1); CP_COMMIT();
    issue(2); CP_COMMIT();

    const int NK = H_DIM / 32;
    #pragma unroll 1
    for (int kt = 0; kt < NK; ++kt) {
        CP_WAIT2();
        __syncthreads();
        if (kt + 3 < NK) issue(kt + 3);
        CP_COMMIT();

        const uint32_t cur = sb + (uint32_t)(kt % N_STAGES) * STAGE_BYTES;
        #pragma unroll
        for (int kk = 0; kk < 2; ++kk) {
            const uint32_t kb = cur + (uint32_t)(kk * 32);
            uint32_t a[4][4];
            #pragma unroll
            for (int mi = 0; mi < 4; mi++)
                ldm_x4(kb + rA[mi], a[mi]);
            uint32_t g0[4], g1[4], u0[4], u1[4];
            ldm_x4(kb + rG0, g0); ldm_x4(kb + rG1, g1);
            ldm_x4(kb + rU0, u0); ldm_x4(kb + rU1, u1);
            uint32_t bg[4][2] = {{g0[0],g0[2]},{g0[1],g0[3]},{g1[0],g1[2]},{g1[1],g1[3]}};
            uint32_t bu[4][2] = {{u0[0],u0[2]},{u0[1],u0[3]},{u1[0],u1[2]},{u1[1],u1[3]}};

            #pragma unroll
            for (int mi = 0; mi < 4; mi++)
                #pragma unroll
                for (int ni = 0; ni < 4; ni++)
                    mma_f16(cg[mi][ni], a[mi], bg[ni][0], bg[ni][1]);
            #pragma unroll
            for (int mi = 0; mi < 4; mi++)
                #pragma unroll
                for (int ni = 0; ni < 4; ni++)
                    mma_f16(cu[mi][ni], a[mi], bu[ni][0], bu[ni][1]);
        }
    }

    // epilogue: silu(g)*u -> fp16 plane
    const int gr = lane >> 2, tc = (lane & 3) * 2;
    __half* ph = shared ? &d_h1s[0][0] : &d_h1[e][0][0];

    #pragma unroll
    for (int mi = 0; mi < 4; mi++)
        #pragma unroll
        for (int ni = 0; ni < 4; ni++) {
            int ncol = n0 + wn * 32 + ni * 8 + tc;
            #pragma unroll
            for (int half = 0; half < 2; half++) {
                int m = m0 + wm * 64 + mi * 16 + gr + half * 8;
                float g0 = cg[mi][ni][half * 2],     u0 = cu[mi][ni][half * 2];
                float g1 = cg[mi][ni][half * 2 + 1], u1 = cu[mi][ni][half * 2 + 1];
                float o0 = (g0 / (1.f + expf(-g0))) * u0;
                float o1 = (g1 / (1.f + expf(-g1))) * u1;
                *(uint32_t*)(ph + (size_t)m * I_DIM + ncol) = pack2(o0, o1);
            }
        }
}

// ---------------------------------------------------------------------------
// GEMM2: 256 threads (8 warps = 2m x 4n), CTA tile M=128 x N=256 x BK=32.
// Warp tile 64m x 64n. Pure fp16 single-pass. Atomic scatter epilogue.
// Stage planes: A 0, B 10240 (20480B).
// ---------------------------------------------------------------------------
__global__ __launch_bounds__(256) void gemm2_mma(float* __restrict__ out)
{
    const int e = blockIdx.z;
    const bool shared = (e == N_EXP);
    const int ne = shared ? T_TOK : d_counts[e];
    const int m0 = blockIdx.y * 128;
    if (m0 >= ne) return;
    const int n0 = blockIdx.x * 256;

    extern __shared__ __align__(16) char dynsmem[];
    __shared__ int   toks[128];
    __shared__ float wgts[128];

    const int tid = threadIdx.x, lane = tid & 31, wid = tid >> 5;
    const int wm = wid >> 2, wn = wid & 3;
    const uint32_t sb = smem_u32(dynsmem);

    if (tid < 128) {
        int r = m0 + tid;
        if (shared) { toks[tid] = r; wgts[tid] = 1.f; }
        else {
            toks[tid] = (r < ne) ? d_tok[e][r] : 0;
            wgts[tid] = (r < ne) ? d_wgt[e][r] : 0.f;
        }
    }
    __syncthreads();

    const __half* ah1 = shared ? &d_h1s[0][0] : &d_h1[e][0][0];
    const size_t eoff = shared ? 0 : (size_t)e * H_DIM * I_DIM;
    const __half* dw = shared ? d_sd16 : d_dp16 + eoff;

    int aR[2], aCh[2];
    uint32_t aDst[2];
    #pragma unroll
    for (int i = 0; i < 2; i++) {
        int c = tid + 256 * i;
        aR[i] = c >> 2; aCh[i] = c & 3;
        aDst[i] = (uint32_t)(aR[i] * 80 + aCh[i] * 16);
    }
    int bR[4], bCh[4];
    uint32_t bDst[4];
    #pragma unroll
    for (int i = 0; i < 4; i++) {
        int c = tid + 256 * i;
        bR[i] = c >> 2; bCh[i] = c & 3;
        bDst[i] = (uint32_t)(10240 + bR[i] * 80 + bCh[i] * 16);
    }

    uint32_t rA[4];
    #pragma unroll
    for (int mi = 0; mi < 4; mi++)
        rA[mi] = ldrel(0u, wm * 64 + mi * 16, lane);
    uint32_t rB[4];
    #pragma unroll
    for (int j = 0; j < 4; j++)
        rB[j] = ldrel(10240u, wn * 64 + j * 16, lane);

    auto issue = [&](int kt) {
        const uint32_t st = sb + (uint32_t)(kt % N_STAGES) * STAGE_BYTES;
        const int k0 = kt * 32;
        #pragma unroll
        for (int i = 0; i < 2; i++) {
            const __half* src = ah1 + (size_t)(m0 + aR[i]) * I_DIM + k0 + aCh[i] * 8;
            CP_ASYNC16(st + aDst[i], src);
        }
        #pragma unroll
        for (int i = 0; i < 4; i++) {
            const __half* src = dw + (size_t)(n0 + bR[i]) * I_DIM + k0 + bCh[i] * 8;
            CP_ASYNC16(st + bDst[i], src);
        }
    };

    float cd[4][8][4] = {};

    issue(0); CP_COMMIT();
    issue(1); CP_COMMIT();
    issue(2); CP_COMMIT();

    const int NK = I_DIM / 32;
    #pragma unroll 1
    for (int kt = 0; kt < NK; ++kt) {
        CP_WAIT2();
        __syncthreads();
        if (kt + 3 < NK) issue(kt + 3);
        CP_COMMIT();

        const uint32_t cur = sb + (uint32_t)(kt % N_STAGES) * STAGE_BYTES;
        #pragma unroll
        for (int kk = 0; kk < 2; ++kk) {
            const uint32_t kb = cur + (uint32_t)(kk * 32);
            uint32_t a[4][4];
            #pragma unroll
            for (int mi = 0; mi < 4; mi++)
                ldm_x4(kb + rA[mi], a[mi]);
            uint32_t h[4][4];
            #pragma unroll
            for (int j = 0; j < 4; j++)
                ldm_x4(kb + rB[j], h[j]);
            uint32_t bh[8][2];
            #pragma unroll
            for (int j = 0; j < 4; j++) {
                bh[j*2][0]   = h[j][0]; bh[j*2][1]   = h[j][2];
                bh[j*2+1][0] = h[j][1]; bh[j*2+1][1] = h[j][3];
            }
            #pragma unroll
            for (int mi = 0; mi < 4; mi++)
                #pragma unroll
                for (int ni = 0; ni < 8; ni++)
                    mma_f16(cd[mi][ni], a[mi], bh[ni][0], bh[ni][1]);
        }
    }

    // epilogue: weighted atomic scatter (out pre-zeroed)
    const int gr = lane >> 2, tc = (lane & 3) * 2;
    #pragma unroll
    for (int mi = 0; mi < 4; mi++) {
        #pragma unroll
        for (int half = 0; half < 2; half++) {
            int mloc = wm * 64 + mi * 16 + gr + half * 8;
            if (m0 + mloc >= ne) continue;
            int   t = toks[mloc];
            float w = wgts[mloc];
            float* orow = out + (size_t)t * H_DIM;
            #pragma unroll
            for (int ni = 0; ni < 8; ni++) {
                int ncol = n0 + wn * 64 + ni * 8 + tc;
                atomicAdd(orow + ncol,     w * cd[mi][ni][half * 2]);
                atomicAdd(orow + ncol + 1, w * cd[mi][ni][half * 2 + 1]);
            }
        }
    }
}

// ---------------------------------------------------------------------------
// Launch — gemm1 is the 4th launch (ncu capture slot)
// ---------------------------------------------------------------------------
extern "C" void kernel_launch(void* const* d_in, const int* in_sizes, int n_in,
                              void* d_out, int out_size)
{
    const float* x  = (const float*)d_in[0];
    const float* gw = (const float*)d_in[1];
    const float* eb = (const float*)d_in[2];
    const float* gp = (const float*)d_in[3];
    const float* up = (const float*)d_in[4];
    const float* dp = (const float*)d_in[5];
    const float* sg = (const float*)d_in[6];
    const float* su = (const float*)d_in[7];
    const float* sd = (const float*)d_in[8];
    float* out = (float*)d_out;

    cudaFuncSetAttribute((const void*)gemm1_mma, cudaFuncAttributeMaxDynamicSharedMemorySize, SMEM_DYN);
    cudaFuncSetAttribute((const void*)gemm2_mma, cudaFuncAttributeMaxDynamicSharedMemorySize, SMEM_DYN);

    // 1: weights fp32->fp16
    split_weights_kernel<<<4096, 256>>>((const float4*)gp, (const float4*)up,
                                        (const float4*)dp, (const float4*)sg,
                                        (const float4*)su, (const float4*)sd);
    // 2: x fp32->fp16 (+ zero counts)
    split_x_kernel<<<1024, 256>>>((const float4*)x);
    // 3: routing
    route_kernel<<<T_TOK, 256>>>(x, gw, eb);
    // 4: GEMM1 (ncu capture slot)
    gemm1_mma<<<dim3(I_DIM / 128, T_TOK / 128, N_EXP + 1), 256, SMEM_DYN>>>();
    // 5: zero output (before gemm2's atomics)
    zero_out_kernel<<<1024, 256>>>((float4*)out, out_size / 4);
    // 6: GEMM2
    gemm2_mma<<<dim3(H_DIM / 256, T_TOK / 128, N_EXP + 1), 256, SMEM_DYN>>>(out);
}

// round 11
// speedup vs baseline: 2.4818x; 1.0401x over previous
#include <cuda_runtime.h>
#include <cuda_fp16.h>
#include <stdint.h>
#include <math.h>

#define T_TOK 2048
#define H_DIM 2048
#define I_DIM 1024
#define N_EXP 16
#define TOPK  4
#define NGRP  4
#define GSZ   4
#define SCALING 2.5f

// GEMM1 stage: A(10240) G(10240) U(10240) = 30720
// GEMM2 stage: A(10240) B(20480)          = 30720
#define STAGE_BYTES 30720u
#define N_STAGES    4
#define SMEM_DYN    (N_STAGES * STAGE_BYTES)   // 122880

// ---------------------------------------------------------------------------
// Scratch (device globals). Everything plain fp16.
// ---------------------------------------------------------------------------
__device__ int   d_counts[N_EXP];
__device__ int   d_tok[N_EXP][T_TOK];
__device__ float d_wgt[N_EXP][T_TOK];
__device__ __half d_h1 [N_EXP][T_TOK][I_DIM];
__device__ __half d_h1s[T_TOK][I_DIM];
__device__ __half d_x16[T_TOK * H_DIM];
__device__ __half d_gp16[N_EXP * I_DIM * H_DIM];
__device__ __half d_up16[N_EXP * I_DIM * H_DIM];
__device__ __half d_dp16[N_EXP * H_DIM * I_DIM];
__device__ __half d_sg16[I_DIM * H_DIM];
__device__ __half d_su16[I_DIM * H_DIM];
__device__ __half d_sd16[H_DIM * I_DIM];

// ---------------------------------------------------------------------------
// PTX helpers (baseline sm_80+ only)
// ---------------------------------------------------------------------------
__device__ __forceinline__ uint32_t smem_u32(const void* p) {
    uint32_t a;
    asm("{ .reg .u64 t; cvta.to.shared.u64 t, %1; cvt.u32.u64 %0, t; }"
        : "=r"(a) : "l"(p));
    return a;
}

__device__ __forceinline__ void ldm_x4(uint32_t addr, uint32_t r[4]) {
    asm volatile("ldmatrix.sync.aligned.m8n8.x4.shared.b16 {%0,%1,%2,%3}, [%4];"
                 : "=r"(r[0]), "=r"(r[1]), "=r"(r[2]), "=r"(r[3]) : "r"(addr));
}

__device__ __forceinline__ void mma_f16(float d[4], const uint32_t a[4],
                                        uint32_t b0, uint32_t b1) {
    asm volatile(
        "mma.sync.aligned.m16n8k16.row.col.f32.f16.f16.f32 "
        "{%0,%1,%2,%3}, {%4,%5,%6,%7}, {%8,%9}, {%0,%1,%2,%3};"
        : "+f"(d[0]), "+f"(d[1]), "+f"(d[2]), "+f"(d[3])
        : "r"(a[0]), "r"(a[1]), "r"(a[2]), "r"(a[3]), "r"(b0), "r"(b1));
}

#define CP_ASYNC16(dst, src) \
    asm volatile("cp.async.cg.shared.global [%0], [%1], 16;" \
                 :: "r"(dst), "l"(src) : "memory")
#define CP_COMMIT()  asm volatile("cp.async.commit_group;" ::: "memory")
#define CP_WAIT2()   asm volatile("cp.async.wait_group 2;" ::: "memory")

__device__ __forceinline__ uint32_t pack2(float f0, float f1) {
    __half h0 = __float2half_rn(f0);
    __half h1 = __float2half_rn(f1);
    return (uint32_t)__half_as_ushort(h0) | ((uint32_t)__half_as_ushort(h1) << 16);
}

// stage-relative ldmatrix offset within a padded [rows][40] fp16 plane
__device__ __forceinline__ uint32_t ldrel(uint32_t plane, int rbase, int lane) {
    int row = rbase + (lane & 15);
    int col = (lane >> 4) << 3;
    return plane + (uint32_t)((row * 40 + col) << 1);
}

// ---------------------------------------------------------------------------
// Convert kernels (fp32 -> fp16)
// ---------------------------------------------------------------------------
#define SEG_GP 8388608
#define SEG_UP 16777216
#define SEG_DP 25165824
#define SEG_SG 25690112
#define SEG_SU 26214400
#define SEG_SD 26738688

__global__ __launch_bounds__(256) void split_weights_kernel(
    const float4* __restrict__ gp, const float4* __restrict__ up,
    const float4* __restrict__ dp, const float4* __restrict__ sg,
    const float4* __restrict__ su, const float4* __restrict__ sd)
{
    int i = blockIdx.x * blockDim.x + threadIdx.x;
    const int stride = gridDim.x * blockDim.x;
    for (; i < SEG_SD; i += stride) {
        const float4* src; uint2* h16; int off;
        if (i < SEG_GP)      { src = gp; off = i;            h16 = (uint2*)d_gp16; }
        else if (i < SEG_UP) { src = up; off = i - SEG_GP;   h16 = (uint2*)d_up16; }
        else if (i < SEG_DP) { src = dp; off = i - SEG_UP;   h16 = (uint2*)d_dp16; }
        else if (i < SEG_SG) { src = sg; off = i - SEG_DP;   h16 = (uint2*)d_sg16; }
        else if (i < SEG_SU) { src = su; off = i - SEG_SG;   h16 = (uint2*)d_su16; }
        else                 { src = sd; off = i - SEG_SU;   h16 = (uint2*)d_sd16; }
        float4 f = src[off];
        uint2 h; h.x = pack2(f.x, f.y); h.y = pack2(f.z, f.w);
        h16[off] = h;
    }
}

__global__ __launch_bounds__(256) void split_x_kernel(const float4* __restrict__ x)
{
    if (blockIdx.x == 0 && threadIdx.x < N_EXP) d_counts[threadIdx.x] = 0;
    int i = blockIdx.x * blockDim.x + threadIdx.x;
    const int stride = gridDim.x * blockDim.x;
    const int n4 = T_TOK * H_DIM / 4;
    for (; i < n4; i += stride) {
        float4 f = x[i];
        uint2 h; h.x = pack2(f.x, f.y); h.y = pack2(f.z, f.w);
        ((uint2*)d_x16)[i] = h;
    }
}

__global__ __launch_bounds__(256) void zero_out_kernel(float4* __restrict__ out, int n4)
{
    int i = blockIdx.x * blockDim.x + threadIdx.x;
    int stride = gridDim.x * blockDim.x;
    float4 z = {0.f, 0.f, 0.f, 0.f};
    for (; i < n4; i += stride) out[i] = z;
}

// ---------------------------------------------------------------------------
// Routing (proven)
// ---------------------------------------------------------------------------
__global__ __launch_bounds__(256) void route_kernel(
    const float* __restrict__ x, const float* __restrict__ gw,
    const float* __restrict__ bias)
{
    __shared__ float xs[H_DIM];
    __shared__ float logits[N_EXP];
    const int t = blockIdx.x;
    const float* xr = x + (size_t)t * H_DIM;
    for (int i = threadIdx.x; i < H_DIM; i += blockDim.x) xs[i] = xr[i];
    __syncthreads();

    const int e = threadIdx.x >> 4, lane = threadIdx.x & 15;
    const float* g = gw + (size_t)e * H_DIM;
    float s = 0.f;
    for (int k = lane; k < H_DIM; k += 16) s += xs[k] * g[k];
    #pragma unroll
    for (int o = 8; o > 0; o >>= 1) s += __shfl_down_sync(0xffffffffu, s, o, 16);
    if (lane == 0) logits[e] = s;
    __syncthreads();

    if (threadIdx.x == 0) {
        float sc[N_EXP], bs[N_EXP];
        #pragma unroll
        for (int i = 0; i < N_EXP; i++) {
            sc[i] = 1.f / (1.f + expf(-logits[i]));
            bs[i] = sc[i] + bias[i];
        }
        float gsc[NGRP];
        #pragma unroll
        for (int gi = 0; gi < NGRP; gi++) {
            float m1 = -1e30f, m2 = -1e30f;
            #pragma unroll
            for (int j = 0; j < GSZ; j++) {
                float v = bs[gi * GSZ + j];
                if (v > m1) { m2 = m1; m1 = v; } else if (v > m2) { m2 = v; }
            }
            gsc[gi] = m1 + m2;
        }
        int g1 = 0;
        for (int gi = 1; gi < NGRP; gi++) if (gsc[gi] > gsc[g1]) g1 = gi;
        int g2 = -1;
        for (int gi = 0; gi < NGRP; gi++) {
            if (gi == g1) continue;
            if (g2 < 0 || gsc[gi] > gsc[g2]) g2 = gi;
        }
        bool allowed[N_EXP], used[N_EXP];
        #pragma unroll
        for (int i = 0; i < N_EXP; i++) {
            int gi = i / GSZ;
            allowed[i] = (gi == g1 || gi == g2);
            used[i] = false;
        }
        int sel[TOPK]; float wv[TOPK]; float wsum = 0.f;
        #pragma unroll
        for (int kk = 0; kk < TOPK; kk++) {
            int best = -1; float bv = -1e30f;
            for (int i = 0; i < N_EXP; i++) {
                if (!allowed[i] || used[i]) continue;
                if (best < 0 || bs[i] > bv) { best = i; bv = bs[i]; }
            }
            used[best] = true; sel[kk] = best; wv[kk] = sc[best]; wsum += sc[best];
        }
        const float inv = SCALING / (wsum + 1e-20f);
        #pragma unroll
        for (int kk = 0; kk < TOPK; kk++) {
            int ee = sel[kk];
            int slot = atomicAdd(&d_counts[ee], 1);
            d_tok[ee][slot] = t;
            d_wgt[ee][slot] = wv[kk] * inv;
        }
    }
}

// ---------------------------------------------------------------------------
// GEMM1: 512 threads (16 warps = 4m x 4n), CTA tile M=128 x N=128 x BK=32.
// Warp tile 32m x 32n, dual output (gate & up). Pointer-increment cp.async.
// Stage planes: A 0, G 10240, U 20480.
// ---------------------------------------------------------------------------
__global__ __launch_bounds__(512) void gemm1_mma()
{
    const int e = blockIdx.z;
    const bool shared = (e == N_EXP);
    const int ne = shared ? T_TOK : d_counts[e];
    const int m0 = blockIdx.y * 128;
    if (m0 >= ne) return;
    const int n0 = blockIdx.x * 128;

    extern __shared__ __align__(16) char dynsmem[];
    __shared__ int toks[128];

    const int tid = threadIdx.x, lane = tid & 31, wid = tid >> 5;
    const int wm = wid >> 2, wn = wid & 3;
    const uint32_t sb = smem_u32(dynsmem);

    if (tid < 128) {
        int r = m0 + tid;
        toks[tid] = shared ? r : (r < ne ? d_tok[e][r] : d_tok[e][0]);
    }
    __syncthreads();

    const size_t eoff = shared ? 0 : (size_t)e * I_DIM * H_DIM;
    const __half* gP = shared ? d_sg16 : d_gp16 + eoff;
    const __half* uP = shared ? d_su16 : d_up16 + eoff;

    // one 16B chunk per thread per plane: row = tid>>2, ch = tid&3
    const int cR = tid >> 2, cCh = tid & 3;
    const uint32_t dstA = (uint32_t)(cR * 80 + cCh * 16);
    const uint32_t dstG = dstA + 10240u;
    const uint32_t dstU = dstA + 20480u;
    // persistent source pointers, bumped 32 halves (64B) per k-tile
    const __half* xPtr = d_x16 + (size_t)toks[cR] * H_DIM + cCh * 8;
    const __half* gPtr = gP + (size_t)(n0 + cR) * H_DIM + cCh * 8;
    const __half* uPtr = uP + (size_t)(n0 + cR) * H_DIM + cCh * 8;

    uint32_t rA[2];
    #pragma unroll
    for (int mi = 0; mi < 2; mi++)
        rA[mi] = ldrel(0u, wm * 32 + mi * 16, lane);
    const uint32_t rG0 = ldrel(10240u, wn * 32,      lane);
    const uint32_t rG1 = ldrel(10240u, wn * 32 + 16, lane);
    const uint32_t rU0 = ldrel(20480u, wn * 32,      lane);
    const uint32_t rU1 = ldrel(20480u, wn * 32 + 16, lane);

    auto issue = [&](int kt) {
        const uint32_t st = sb + (uint32_t)(kt & 3) * STAGE_BYTES;
        CP_ASYNC16(st + dstA, xPtr); xPtr += 32;
        CP_ASYNC16(st + dstG, gPtr); gPtr += 32;
        CP_ASYNC16(st + dstU, uPtr); uPtr += 32;
    };

    float cg[2][4][4] = {}, cu[2][4][4] = {};

    issue(0); CP_COMMIT();
    issue(1); CP_COMMIT();
    issue(2); CP_COMMIT();

    const int NK = H_DIM / 32;
    #pragma unroll 1
    for (int kt = 0; kt < NK; ++kt) {
        CP_WAIT2();
        __syncthreads();
        if (kt + 3 < NK) issue(kt + 3);
        CP_COMMIT();

        const uint32_t cur = sb + (uint32_t)(kt & 3) * STAGE_BYTES;
        #pragma unroll
        for (int kk = 0; kk < 2; ++kk) {
            const uint32_t kb = cur + (uint32_t)(kk * 32);
            uint32_t a[2][4];
            #pragma unroll
            for (int mi = 0; mi < 2; mi++)
                ldm_x4(kb + rA[mi], a[mi]);
            uint32_t g0[4], g1[4], u0[4], u1[4];
            ldm_x4(kb + rG0, g0); ldm_x4(kb + rG1, g1);
            ldm_x4(kb + rU0, u0); ldm_x4(kb + rU1, u1);
            uint32_t bg[4][2] = {{g0[0],g0[2]},{g0[1],g0[3]},{g1[0],g1[2]},{g1[1],g1[3]}};
            uint32_t bu[4][2] = {{u0[0],u0[2]},{u0[1],u0[3]},{u1[0],u1[2]},{u1[1],u1[3]}};

            #pragma unroll
            for (int mi = 0; mi < 2; mi++)
                #pragma unroll
                for (int ni = 0; ni < 4; ni++)
                    mma_f16(cg[mi][ni], a[mi], bg[ni][0], bg[ni][1]);
            #pragma unroll
            for (int mi = 0; mi < 2; mi++)
                #pragma unroll
                for (int ni = 0; ni < 4; ni++)
                    mma_f16(cu[mi][ni], a[mi], bu[ni][0], bu[ni][1]);
        }
    }

    // epilogue: silu(g)*u -> fp16 plane
    const int gr = lane >> 2, tc = (lane & 3) * 2;
    __half* ph = shared ? &d_h1s[0][0] : &d_h1[e][0][0];

    #pragma unroll
    for (int mi = 0; mi < 2; mi++)
        #pragma unroll
        for (int ni = 0; ni < 4; ni++) {
            int ncol = n0 + wn * 32 + ni * 8 + tc;
            #pragma unroll
            for (int half = 0; half < 2; half++) {
                int m = m0 + wm * 32 + mi * 16 + gr + half * 8;
                float g0 = cg[mi][ni][half * 2],     u0 = cu[mi][ni][half * 2];
                float g1 = cg[mi][ni][half * 2 + 1], u1 = cu[mi][ni][half * 2 + 1];
                float o0 = (g0 / (1.f + expf(-g0))) * u0;
                float o1 = (g1 / (1.f + expf(-g1))) * u1;
                *(uint32_t*)(ph + (size_t)m * I_DIM + ncol) = pack2(o0, o1);
            }
        }
}

// ---------------------------------------------------------------------------
// GEMM2: 512 threads (16 warps = 4m x 4n), CTA tile M=128 x N=256 x BK=32.
// Warp tile 32m x 64n. Pointer-increment cp.async. Atomic scatter epilogue.
// Stage planes: A 0, B 10240 (20480B).
// ---------------------------------------------------------------------------
__global__ __launch_bounds__(512) void gemm2_mma(float* __restrict__ out)
{
    const int e = blockIdx.z;
    const bool shared = (e == N_EXP);
    const int ne = shared ? T_TOK : d_counts[e];
    const int m0 = blockIdx.y * 128;
    if (m0 >= ne) return;
    const int n0 = blockIdx.x * 256;

    extern __shared__ __align__(16) char dynsmem[];
    __shared__ int   toks[128];
    __shared__ float wgts[128];

    const int tid = threadIdx.x, lane = tid & 31, wid = tid >> 5;
    const int wm = wid >> 2, wn = wid & 3;
    const uint32_t sb = smem_u32(dynsmem);

    if (tid < 128) {
        int r = m0 + tid;
        if (shared) { toks[tid] = r; wgts[tid] = 1.f; }
        else {
            toks[tid] = (r < ne) ? d_tok[e][r] : 0;
            wgts[tid] = (r < ne) ? d_wgt[e][r] : 0.f;
        }
    }
    __syncthreads();

    const __half* ah1 = shared ? &d_h1s[0][0] : &d_h1[e][0][0];
    const size_t eoff = shared ? 0 : (size_t)e * H_DIM * I_DIM;
    const __half* dw = shared ? d_sd16 : d_dp16 + eoff;

    // A: 512 chunks -> 1/thr; B: 1024 chunks -> 2/thr
    const int aRr = tid >> 2, aCc = tid & 3;
    const uint32_t dstA = (uint32_t)(aRr * 80 + aCc * 16);
    const __half* aPtr = ah1 + (size_t)(m0 + aRr) * I_DIM + aCc * 8;

    const int b0R = tid >> 2,         b0C = tid & 3;
    const int b1R = (tid + 512) >> 2, b1C = tid & 3;
    const uint32_t dstB0 = (uint32_t)(10240 + b0R * 80 + b0C * 16);
    const uint32_t dstB1 = (uint32_t)(10240 + b1R * 80 + b1C * 16);
    const __half* bPtr0 = dw + (size_t)(n0 + b0R) * I_DIM + b0C * 8;
    const __half* bPtr1 = dw + (size_t)(n0 + b1R) * I_DIM + b1C * 8;

    uint32_t rA[2];
    #pragma unroll
    for (int mi = 0; mi < 2; mi++)
        rA[mi] = ldrel(0u, wm * 32 + mi * 16, lane);
    uint32_t rB[4];
    #pragma unroll
    for (int j = 0; j < 4; j++)
        rB[j] = ldrel(10240u, wn * 64 + j * 16, lane);

    auto issue = [&](int kt) {
        const uint32_t st = sb + (uint32_t)(kt & 3) * STAGE_BYTES;
        CP_ASYNC16(st + dstA,  aPtr);  aPtr  += 32;
        CP_ASYNC16(st + dstB0, bPtr0); bPtr0 += 32;
        CP_ASYNC16(st + dstB1, bPtr1); bPtr1 += 32;
    };

    float cd[2][8][4] = {};

    issue(0); CP_COMMIT();
    issue(1); CP_COMMIT();
    issue(2); CP_COMMIT();

    const int NK = I_DIM / 32;
    #pragma unroll 1
    for (int kt = 0; kt < NK; ++kt) {
        CP_WAIT2();
        __syncthreads();
        if (kt + 3 < NK) issue(kt + 3);
        CP_COMMIT();

        const uint32_t cur = sb + (uint32_t)(kt & 3) * STAGE_BYTES;
        #pragma unroll
        for (int kk = 0; kk < 2; ++kk) {
            const uint32_t kb = cur + (uint32_t)(kk * 32);
            uint32_t a[2][4];
            #pragma unroll
            for (int mi = 0; mi < 2; mi++)
                ldm_x4(kb + rA[mi], a[mi]);
            uint32_t h[4][4];
            #pragma unroll
            for (int j = 0; j < 4; j++)
                ldm_x4(kb + rB[j], h[j]);
            uint32_t bh[8][2];
            #pragma unroll
            for (int j = 0; j < 4; j++) {
                bh[j*2][0]   = h[j][0]; bh[j*2][1]   = h[j][2];
                bh[j*2+1][0] = h[j][1]; bh[j*2+1][1] = h[j][3];
            }
            #pragma unroll
            for (int mi = 0; mi < 2; mi++)
                #pragma unroll
                for (int ni = 0; ni < 8; ni++)
                    mma_f16(cd[mi][ni], a[mi], bh[ni][0], bh[ni][1]);
        }
    }

    // epilogue: weighted atomic scatter (out pre-zeroed)
    const int gr = lane >> 2, tc = (lane & 3) * 2;
    #pragma unroll
    for (int mi = 0; mi < 2; mi++) {
        #pragma unroll
        for (int half = 0; half < 2; half++) {
            int mloc = wm * 32 + mi * 16 + gr + half * 8;
            if (m0 + mloc >= ne) continue;
            int   t = toks[mloc];
            float w = wgts[mloc];
            float* orow = out + (size_t)t * H_DIM;
            #pragma unroll
            for (int ni = 0; ni < 8; ni++) {
                int ncol = n0 + wn * 64 + ni * 8 + tc;
                atomicAdd(orow + ncol,     w * cd[mi][ni][half * 2]);
                atomicAdd(orow + ncol + 1, w * cd[mi][ni][half * 2 + 1]);
            }
        }
    }
}

// ---------------------------------------------------------------------------
// Launch — gemm1 is the 4th launch (ncu capture slot)
// ---------------------------------------------------------------------------
extern "C" void kernel_launch(void* const* d_in, const int* in_sizes, int n_in,
                              void* d_out, int out_size)
{
    const float* x  = (const float*)d_in[0];
    const float* gw = (const float*)d_in[1];
    const float* eb = (const float*)d_in[2];
    const float* gp = (const float*)d_in[3];
    const float* up = (const float*)d_in[4];
    const float* dp = (const float*)d_in[5];
    const float* sg = (const float*)d_in[6];
    const float* su = (const float*)d_in[7];
    const float* sd = (const float*)d_in[8];
    float* out = (float*)d_out;

    cudaFuncSetAttribute((const void*)gemm1_mma, cudaFuncAttributeMaxDynamicSharedMemorySize, SMEM_DYN);
    cudaFuncSetAttribute((const void*)gemm2_mma, cudaFuncAttributeMaxDynamicSharedMemorySize, SMEM_DYN);

    split_weights_kernel<<<4096, 256>>>((const float4*)gp, (const float4*)up,
                                        (const float4*)dp, (const float4*)sg,
                                        (const float4*)su, (const float4*)sd);
    split_x_kernel<<<1024, 256>>>((const float4*)x);
    route_kernel<<<T_TOK, 256>>>(x, gw, eb);
    gemm1_mma<<<dim3(I_DIM / 128, T_TOK / 128, N_EXP + 1), 512, SMEM_DYN>>>();
    zero_out_kernel<<<1024, 256>>>((float4*)out, out_size / 4);
    gemm2_mma<<<dim3(H_DIM / 256, T_TOK / 128, N_EXP + 1), 512, SMEM_DYN>>>(out);
}

// round 12
// speedup vs baseline: 2.5910x; 1.0440x over previous
#include <cuda_runtime.h>
#include <cuda_fp16.h>
#include <stdint.h>
#include <math.h>

#define T_TOK 2048
#define H_DIM 2048
#define I_DIM 1024
#define N_EXP 16
#define TOPK  4
#define NGRP  4
#define GSZ   4
#define SCALING 2.5f

#define STAGE_BYTES 30720u
#define N_STAGES    4
#define SMEM_DYN    (N_STAGES * STAGE_BYTES)   // 122880

// ---------------------------------------------------------------------------
// Scratch (device globals). Everything plain fp16.
// ---------------------------------------------------------------------------
__device__ int   d_counts[N_EXP];
__device__ int   d_tok[N_EXP][T_TOK];
__device__ float d_wgt[N_EXP][T_TOK];
__device__ __half d_h1 [N_EXP][T_TOK][I_DIM];
__device__ __half d_h1s[T_TOK][I_DIM];
__device__ __half d_x16[T_TOK * H_DIM];
__device__ __half d_gp16[N_EXP * I_DIM * H_DIM];
__device__ __half d_up16[N_EXP * I_DIM * H_DIM];
__device__ __half d_dp16[N_EXP * H_DIM * I_DIM];
__device__ __half d_sg16[I_DIM * H_DIM];
__device__ __half d_su16[I_DIM * H_DIM];
__device__ __half d_sd16[H_DIM * I_DIM];

// ---------------------------------------------------------------------------
// PTX helpers (baseline sm_80+ only)
// ---------------------------------------------------------------------------
__device__ __forceinline__ uint32_t smem_u32(const void* p) {
    uint32_t a;
    asm("{ .reg .u64 t; cvta.to.shared.u64 t, %1; cvt.u32.u64 %0, t; }"
        : "=r"(a) : "l"(p));
    return a;
}

__device__ __forceinline__ void ldm_x4(uint32_t addr, uint32_t r[4]) {
    asm volatile("ldmatrix.sync.aligned.m8n8.x4.shared.b16 {%0,%1,%2,%3}, [%4];"
                 : "=r"(r[0]), "=r"(r[1]), "=r"(r[2]), "=r"(r[3]) : "r"(addr));
}

__device__ __forceinline__ void mma_f16(float d[4], const uint32_t a[4],
                                        uint32_t b0, uint32_t b1) {
    asm volatile(
        "mma.sync.aligned.m16n8k16.row.col.f32.f16.f16.f32 "
        "{%0,%1,%2,%3}, {%4,%5,%6,%7}, {%8,%9}, {%0,%1,%2,%3};"
        : "+f"(d[0]), "+f"(d[1]), "+f"(d[2]), "+f"(d[3])
        : "r"(a[0]), "r"(a[1]), "r"(a[2]), "r"(a[3]), "r"(b0), "r"(b1));
}

#define CP_ASYNC16(dst, src) \
    asm volatile("cp.async.cg.shared.global [%0], [%1], 16;" \
                 :: "r"(dst), "l"(src) : "memory")
#define CP_COMMIT()  asm volatile("cp.async.commit_group;" ::: "memory")
#define CP_WAIT1()   asm volatile("cp.async.wait_group 1;" ::: "memory")

__device__ __forceinline__ uint32_t pack2(float f0, float f1) {
    __half h0 = __float2half_rn(f0);
    __half h1 = __float2half_rn(f1);
    return (uint32_t)__half_as_ushort(h0) | ((uint32_t)__half_as_ushort(h1) << 16);
}

// stage-relative ldmatrix offset within a padded [rows][40] fp16 plane
__device__ __forceinline__ uint32_t ldrel(uint32_t plane, int rbase, int lane) {
    int row = rbase + (lane & 15);
    int col = (lane >> 4) << 3;
    return plane + (uint32_t)((row * 40 + col) << 1);
}

// ---------------------------------------------------------------------------
// Convert kernel (weights fp32 -> fp16)
// ---------------------------------------------------------------------------
#define SEG_GP 8388608
#define SEG_UP 16777216
#define SEG_DP 25165824
#define SEG_SG 25690112
#define SEG_SU 26214400
#define SEG_SD 26738688

__global__ __launch_bounds__(256) void split_weights_kernel(
    const float4* __restrict__ gp, const float4* __restrict__ up,
    const float4* __restrict__ dp, const float4* __restrict__ sg,
    const float4* __restrict__ su, const float4* __restrict__ sd)
{
    int i = blockIdx.x * blockDim.x + threadIdx.x;
    const int stride = gridDim.x * blockDim.x;
    for (; i < SEG_SD; i += stride) {
        const float4* src; uint2* h16; int off;
        if (i < SEG_GP)      { src = gp; off = i;            h16 = (uint2*)d_gp16; }
        else if (i < SEG_UP) { src = up; off = i - SEG_GP;   h16 = (uint2*)d_up16; }
        else if (i < SEG_DP) { src = dp; off = i - SEG_UP;   h16 = (uint2*)d_dp16; }
        else if (i < SEG_SG) { src = sg; off = i - SEG_DP;   h16 = (uint2*)d_sg16; }
        else if (i < SEG_SU) { src = su; off = i - SEG_SG;   h16 = (uint2*)d_su16; }
        else                 { src = sd; off = i - SEG_SU;   h16 = (uint2*)d_sd16; }
        float4 f = src[off];
        uint2 h; h.x = pack2(f.x, f.y); h.y = pack2(f.z, f.w);
        h16[off] = h;
    }
}

__global__ __launch_bounds__(256) void zero_out_kernel(float4* __restrict__ out, int n4)
{
    int i = blockIdx.x * blockDim.x + threadIdx.x;
    int stride = gridDim.x * blockDim.x;
    float4 z = {0.f, 0.f, 0.f, 0.f};
    for (; i < n4; i += stride) out[i] = z;
}

__global__ void zero_counts_kernel() {
    if (threadIdx.x < N_EXP) d_counts[threadIdx.x] = 0;
}

// ---------------------------------------------------------------------------
// Routing + x fp32->fp16 conversion (fused)
// ---------------------------------------------------------------------------
__global__ __launch_bounds__(256) void route_kernel(
    const float* __restrict__ x, const float* __restrict__ gw,
    const float* __restrict__ bias)
{
    __shared__ float xs[H_DIM];
    __shared__ float logits[N_EXP];
    const int t = blockIdx.x;
    const float* xr = x + (size_t)t * H_DIM;
    for (int i = threadIdx.x; i < H_DIM; i += blockDim.x) xs[i] = xr[i];
    __syncthreads();

    // emit fp16 copy of this token row (packed pairs)
    {
        uint32_t* dst = (uint32_t*)(d_x16 + (size_t)t * H_DIM);
        for (int i = threadIdx.x; i < H_DIM / 2; i += blockDim.x)
            dst[i] = pack2(xs[i * 2], xs[i * 2 + 1]);
    }

    const int e = threadIdx.x >> 4, lane = threadIdx.x & 15;
    const float* g = gw + (size_t)e * H_DIM;
    float s = 0.f;
    for (int k = lane; k < H_DIM; k += 16) s += xs[k] * g[k];
    #pragma unroll
    for (int o = 8; o > 0; o >>= 1) s += __shfl_down_sync(0xffffffffu, s, o, 16);
    if (lane == 0) logits[e] = s;
    __syncthreads();

    if (threadIdx.x == 0) {
        float sc[N_EXP], bs[N_EXP];
        #pragma unroll
        for (int i = 0; i < N_EXP; i++) {
            sc[i] = 1.f / (1.f + expf(-logits[i]));
            bs[i] = sc[i] + bias[i];
        }
        float gsc[NGRP];
        #pragma unroll
        for (int gi = 0; gi < NGRP; gi++) {
            float m1 = -1e30f, m2 = -1e30f;
            #pragma unroll
            for (int j = 0; j < GSZ; j++) {
                float v = bs[gi * GSZ + j];
                if (v > m1) { m2 = m1; m1 = v; } else if (v > m2) { m2 = v; }
            }
            gsc[gi] = m1 + m2;
        }
        int g1 = 0;
        for (int gi = 1; gi < NGRP; gi++) if (gsc[gi] > gsc[g1]) g1 = gi;
        int g2 = -1;
        for (int gi = 0; gi < NGRP; gi++) {
            if (gi == g1) continue;
            if (g2 < 0 || gsc[gi] > gsc[g2]) g2 = gi;
        }
        bool allowed[N_EXP], used[N_EXP];
        #pragma unroll
        for (int i = 0; i < N_EXP; i++) {
            int gi = i / GSZ;
            allowed[i] = (gi == g1 || gi == g2);
            used[i] = false;
        }
        int sel[TOPK]; float wv[TOPK]; float wsum = 0.f;
        #pragma unroll
        for (int kk = 0; kk < TOPK; kk++) {
            int best = -1; float bv = -1e30f;
            for (int i = 0; i < N_EXP; i++) {
                if (!allowed[i] || used[i]) continue;
                if (best < 0 || bs[i] > bv) { best = i; bv = bs[i]; }
            }
            used[best] = true; sel[kk] = best; wv[kk] = sc[best]; wsum += sc[best];
        }
        const float inv = SCALING / (wsum + 1e-20f);
        #pragma unroll
        for (int kk = 0; kk < TOPK; kk++) {
            int ee = sel[kk];
            int slot = atomicAdd(&d_counts[ee], 1);
            d_tok[ee][slot] = t;
            d_wgt[ee][slot] = wv[kk] * inv;
        }
    }
}

// ---------------------------------------------------------------------------
// GEMM1: 512 threads (16 warps = 4m x 4n), CTA tile M=128 x N=128 x BK=32.
// Warp tile 32m x 32n, dual output. Register-fragment double buffering:
// ldsm(buf^1) is issued before mma(buf), fully hiding LDSM latency.
// Stage planes: A 0, G 10240, U 20480.
// ---------------------------------------------------------------------------
__global__ __launch_bounds__(512) void gemm1_mma()
{
    const int e = blockIdx.z;
    const bool shared = (e == N_EXP);
    const int ne = shared ? T_TOK : d_counts[e];
    const int m0 = blockIdx.y * 128;
    if (m0 >= ne) return;
    const int n0 = blockIdx.x * 128;

    extern __shared__ __align__(16) char dynsmem[];
    __shared__ int toks[128];

    const int tid = threadIdx.x, lane = tid & 31, wid = tid >> 5;
    const int wm = wid >> 2, wn = wid & 3;
    const uint32_t sb = smem_u32(dynsmem);

    if (tid < 128) {
        int r = m0 + tid;
        toks[tid] = shared ? r : (r < ne ? d_tok[e][r] : d_tok[e][0]);
    }
    __syncthreads();

    const size_t eoff = shared ? 0 : (size_t)e * I_DIM * H_DIM;
    const __half* gP = shared ? d_sg16 : d_gp16 + eoff;
    const __half* uP = shared ? d_su16 : d_up16 + eoff;

    const int cR = tid >> 2, cCh = tid & 3;
    const uint32_t dstA = (uint32_t)(cR * 80 + cCh * 16);
    const uint32_t dstG = dstA + 10240u;
    const uint32_t dstU = dstA + 20480u;
    const __half* xPtr = d_x16 + (size_t)toks[cR] * H_DIM + cCh * 8;
    const __half* gPtr = gP + (size_t)(n0 + cR) * H_DIM + cCh * 8;
    const __half* uPtr = uP + (size_t)(n0 + cR) * H_DIM + cCh * 8;

    uint32_t rA[2];
    #pragma unroll
    for (int mi = 0; mi < 2; mi++)
        rA[mi] = ldrel(0u, wm * 32 + mi * 16, lane);
    const uint32_t rG0 = ldrel(10240u, wn * 32,      lane);
    const uint32_t rG1 = ldrel(10240u, wn * 32 + 16, lane);
    const uint32_t rU0 = ldrel(20480u, wn * 32,      lane);
    const uint32_t rU1 = ldrel(20480u, wn * 32 + 16, lane);

    auto issue = [&](int kt) {
        const uint32_t st = sb + (uint32_t)(kt & 3) * STAGE_BYTES;
        CP_ASYNC16(st + dstA, xPtr); xPtr += 32;
        CP_ASYNC16(st + dstG, gPtr); gPtr += 32;
        CP_ASYNC16(st + dstU, uPtr); uPtr += 32;
    };

    float cg[2][4][4] = {}, cu[2][4][4] = {};
    // fragment double buffers
    uint32_t fa[2][2][4], fg0[2][4], fg1[2][4], fu0[2][4], fu1[2][4];

    auto ldsm_set = [&](int b, uint32_t base) {
        ldm_x4(base + rA[0], fa[b][0]);
        ldm_x4(base + rA[1], fa[b][1]);
        ldm_x4(base + rG0, fg0[b]);
        ldm_x4(base + rG1, fg1[b]);
        ldm_x4(base + rU0, fu0[b]);
        ldm_x4(base + rU1, fu1[b]);
    };
    auto mma_set = [&](int b) {
        uint32_t bg[4][2] = {{fg0[b][0],fg0[b][2]},{fg0[b][1],fg0[b][3]},
                             {fg1[b][0],fg1[b][2]},{fg1[b][1],fg1[b][3]}};
        uint32_t bu[4][2] = {{fu0[b][0],fu0[b][2]},{fu0[b][1],fu0[b][3]},
                             {fu1[b][0],fu1[b][2]},{fu1[b][1],fu1[b][3]}};
        #pragma unroll
        for (int mi = 0; mi < 2; mi++)
            #pragma unroll
            for (int ni = 0; ni < 4; ni++)
                mma_f16(cg[mi][ni], fa[b][mi], bg[ni][0], bg[ni][1]);
        #pragma unroll
        for (int mi = 0; mi < 2; mi++)
            #pragma unroll
            for (int ni = 0; ni < 4; ni++)
                mma_f16(cu[mi][ni], fa[b][mi], bu[ni][0], bu[ni][1]);
    };

    issue(0); CP_COMMIT();
    issue(1); CP_COMMIT();
    issue(2); CP_COMMIT();

    const int NK = H_DIM / 32;
    #pragma unroll 1
    for (int kt = 0; kt < NK; ++kt) {
        CP_WAIT1();                       // stages <= kt+1 complete
        __syncthreads();                  // ... and visible CTA-wide
        if (kt + 3 < NK) issue(kt + 3);
        CP_COMMIT();

        const uint32_t cur = sb + (uint32_t)(kt & 3) * STAGE_BYTES;
        if (kt == 0) ldsm_set(0, cur);            // prime buf0 = (0, kk0)
        ldsm_set(1, cur + 32u);                    // prefetch (kt, kk1)
        mma_set(0);
        if (kt + 1 < NK) {                         // prefetch (kt+1, kk0)
            const uint32_t nxt = sb + (uint32_t)((kt + 1) & 3) * STAGE_BYTES;
            ldsm_set(0, nxt);
        }
        mma_set(1);
    }

    // epilogue: silu(g)*u -> fp16 plane
    const int gr = lane >> 2, tc = (lane & 3) * 2;
    __half* ph = shared ? &d_h1s[0][0] : &d_h1[e][0][0];

    #pragma unroll
    for (int mi = 0; mi < 2; mi++)
        #pragma unroll
        for (int ni = 0; ni < 4; ni++) {
            int ncol = n0 + wn * 32 + ni * 8 + tc;
            #pragma unroll
            for (int half = 0; half < 2; half++) {
                int m = m0 + wm * 32 + mi * 16 + gr + half * 8;
                float g0 = cg[mi][ni][half * 2],     u0 = cu[mi][ni][half * 2];
                float g1 = cg[mi][ni][half * 2 + 1], u1 = cu[mi][ni][half * 2 + 1];
                float o0 = (g0 / (1.f + expf(-g0))) * u0;
                float o1 = (g1 / (1.f + expf(-g1))) * u1;
                *(uint32_t*)(ph + (size_t)m * I_DIM + ncol) = pack2(o0, o1);
            }
        }
}

// ---------------------------------------------------------------------------
// GEMM2: 512 threads (16 warps = 4m x 4n), CTA tile M=128 x N=256 x BK=32.
// Warp tile 32m x 64n. Same fragment double-buffering. Atomic scatter.
// Stage planes: A 0, B 10240 (20480B).
// ---------------------------------------------------------------------------
__global__ __launch_bounds__(512) void gemm2_mma(float* __restrict__ out)
{
    const int e = blockIdx.z;
    const bool shared = (e == N_EXP);
    const int ne = shared ? T_TOK : d_counts[e];
    const int m0 = blockIdx.y * 128;
    if (m0 >= ne) return;
    const int n0 = blockIdx.x * 256;

    extern __shared__ __align__(16) char dynsmem[];
    __shared__ int   toks[128];
    __shared__ float wgts[128];

    const int tid = threadIdx.x, lane = tid & 31, wid = tid >> 5;
    const int wm = wid >> 2, wn = wid & 3;
    const uint32_t sb = smem_u32(dynsmem);

    if (tid < 128) {
        int r = m0 + tid;
        if (shared) { toks[tid] = r; wgts[tid] = 1.f; }
        else {
            toks[tid] = (r < ne) ? d_tok[e][r] : 0;
            wgts[tid] = (r < ne) ? d_wgt[e][r] : 0.f;
        }
    }
    __syncthreads();

    const __half* ah1 = shared ? &d_h1s[0][0] : &d_h1[e][0][0];
    const size_t eoff = shared ? 0 : (size_t)e * H_DIM * I_DIM;
    const __half* dw = shared ? d_sd16 : d_dp16 + eoff;

    const int aRr = tid >> 2, aCc = tid & 3;
    const uint32_t dstA = (uint32_t)(aRr * 80 + aCc * 16);
    const __half* aPtr = ah1 + (size_t)(m0 + aRr) * I_DIM + aCc * 8;

    const int b0R = tid >> 2,         b0C = tid & 3;
    const int b1R = (tid + 512) >> 2, b1C = tid & 3;
    const uint32_t dstB0 = (uint32_t)(10240 + b0R * 80 + b0C * 16);
    const uint32_t dstB1 = (uint32_t)(10240 + b1R * 80 + b1C * 16);
    const __half* bPtr0 = dw + (size_t)(n0 + b0R) * I_DIM + b0C * 8;
    const __half* bPtr1 = dw + (size_t)(n0 + b1R) * I_DIM + b1C * 8;

    uint32_t rA[2];
    #pragma unroll
    for (int mi = 0; mi < 2; mi++)
        rA[mi] = ldrel(0u, wm * 32 + mi * 16, lane);
    uint32_t rB[4];
    #pragma unroll
    for (int j = 0; j < 4; j++)
        rB[j] = ldrel(10240u, wn * 64 + j * 16, lane);

    auto issue = [&](int kt) {
        const uint32_t st = sb + (uint32_t)(kt & 3) * STAGE_BYTES;
        CP_ASYNC16(st + dstA,  aPtr);  aPtr  += 32;
        CP_ASYNC16(st + dstB0, bPtr0); bPtr0 += 32;
        CP_ASYNC16(st + dstB1, bPtr1); bPtr1 += 32;
    };

    float cd[2][8][4] = {};
    uint32_t fa[2][2][4], fb[2][4][4];

    auto ldsm_set = [&](int b, uint32_t base) {
        ldm_x4(base + rA[0], fa[b][0]);
        ldm_x4(base + rA[1], fa[b][1]);
        #pragma unroll
        for (int j = 0; j < 4; j++)
            ldm_x4(base + rB[j], fb[b][j]);
    };
    auto mma_set = [&](int b) {
        uint32_t bh[8][2];
        #pragma unroll
        for (int j = 0; j < 4; j++) {
            bh[j*2][0]   = fb[b][j][0]; bh[j*2][1]   = fb[b][j][2];
            bh[j*2+1][0] = fb[b][j][1]; bh[j*2+1][1] = fb[b][j][3];
        }
        #pragma unroll
        for (int mi = 0; mi < 2; mi++)
            #pragma unroll
            for (int ni = 0; ni < 8; ni++)
                mma_f16(cd[mi][ni], fa[b][mi], bh[ni][0], bh[ni][1]);
    };

    issue(0); CP_COMMIT();
    issue(1); CP_COMMIT();
    issue(2); CP_COMMIT();

    const int NK = I_DIM / 32;
    #pragma unroll 1
    for (int kt = 0; kt < NK; ++kt) {
        CP_WAIT1();
        __syncthreads();
        if (kt + 3 < NK) issue(kt + 3);
        CP_COMMIT();

        const uint32_t cur = sb + (uint32_t)(kt & 3) * STAGE_BYTES;
        if (kt == 0) ldsm_set(0, cur);
        ldsm_set(1, cur + 32u);
        mma_set(0);
        if (kt + 1 < NK) {
            const uint32_t nxt = sb + (uint32_t)((kt + 1) & 3) * STAGE_BYTES;
            ldsm_set(0, nxt);
        }
        mma_set(1);
    }

    // epilogue: weighted atomic scatter (out pre-zeroed)
    const int gr = lane >> 2, tc = (lane & 3) * 2;
    #pragma unroll
    for (int mi = 0; mi < 2; mi++) {
        #pragma unroll
        for (int half = 0; half < 2; half++) {
            int mloc = wm * 32 + mi * 16 + gr + half * 8;
            if (m0 + mloc >= ne) continue;
            int   t = toks[mloc];
            float w = wgts[mloc];
            float* orow = out + (size_t)t * H_DIM;
            #pragma unroll
            for (int ni = 0; ni < 8; ni++) {
                int ncol = n0 + wn * 64 + ni * 8 + tc;
                atomicAdd(orow + ncol,     w * cd[mi][ni][half * 2]);
                atomicAdd(orow + ncol + 1, w * cd[mi][ni][half * 2 + 1]);
            }
        }
    }
}

// ---------------------------------------------------------------------------
// Launch — gemm1 kept as the 4th launch (ncu capture slot)
// ---------------------------------------------------------------------------
extern "C" void kernel_launch(void* const* d_in, const int* in_sizes, int n_in,
                              void* d_out, int out_size)
{
    const float* x  = (const float*)d_in[0];
    const float* gw = (const float*)d_in[1];
    const float* eb = (const float*)d_in[2];
    const float* gp = (const float*)d_in[3];
    const float* up = (const float*)d_in[4];
    const float* dp = (const float*)d_in[5];
    const float* sg = (const float*)d_in[6];
    const float* su = (const float*)d_in[7];
    const float* sd = (const float*)d_in[8];
    float* out = (float*)d_out;

    cudaFuncSetAttribute((const void*)gemm1_mma, cudaFuncAttributeMaxDynamicSharedMemorySize, SMEM_DYN);
    cudaFuncSetAttribute((const void*)gemm2_mma, cudaFuncAttributeMaxDynamicSharedMemorySize, SMEM_DYN);

    split_weights_kernel<<<4096, 256>>>((const float4*)gp, (const float4*)up,
                                        (const float4*)dp, (const float4*)sg,
                                        (const float4*)su, (const float4*)sd);
    zero_counts_kernel<<<1, 32>>>();
    route_kernel<<<T_TOK, 256>>>(x, gw, eb);
    gemm1_mma<<<dim3(I_DIM / 128, T_TOK / 128, N_EXP + 1), 512, SMEM_DYN>>>();
    zero_out_kernel<<<1024, 256>>>((float4*)out, out_size / 4);
    gemm2_mma<<<dim3(H_DIM / 256, T_TOK / 128, N_EXP + 1), 512, SMEM_DYN>>>(out);
}

// round 13
// speedup vs baseline: 2.6631x; 1.0278x over previous
#include <cuda_runtime.h>
#include <cuda_fp16.h>
#include <stdint.h>
#include <math.h>

#define T_TOK 2048
#define H_DIM 2048
#define I_DIM 1024
#define N_EXP 16
#define TOPK  4
#define NGRP  4
#define GSZ   4
#define SCALING 2.5f

// stage: gemm1 A(10240)+G(5120)+U(5120) = 20480 ; gemm2 A(10240)+B(10240) = 20480
#define STAGE_BYTES 20480u
#define N_STAGES    4
#define SMEM_DYN    (N_STAGES * STAGE_BYTES)   // 81920 -> 2 CTAs/SM

// ---------------------------------------------------------------------------
// Scratch (device globals). Everything plain fp16.
// ---------------------------------------------------------------------------
__device__ int   d_counts[N_EXP];
__device__ int   d_tok[N_EXP][T_TOK];
__device__ float d_wgt[N_EXP][T_TOK];
__device__ __half d_h1 [N_EXP][T_TOK][I_DIM];
__device__ __half d_h1s[T_TOK][I_DIM];
__device__ __half d_x16[T_TOK * H_DIM];
__device__ __half d_gp16[N_EXP * I_DIM * H_DIM];
__device__ __half d_up16[N_EXP * I_DIM * H_DIM];
__device__ __half d_dp16[N_EXP * H_DIM * I_DIM];
__device__ __half d_sg16[I_DIM * H_DIM];
__device__ __half d_su16[I_DIM * H_DIM];
__device__ __half d_sd16[H_DIM * I_DIM];

// ---------------------------------------------------------------------------
// PTX helpers (baseline sm_80+ only)
// ---------------------------------------------------------------------------
__device__ __forceinline__ uint32_t smem_u32(const void* p) {
    uint32_t a;
    asm("{ .reg .u64 t; cvta.to.shared.u64 t, %1; cvt.u32.u64 %0, t; }"
        : "=r"(a) : "l"(p));
    return a;
}

__device__ __forceinline__ void ldm_x4(uint32_t addr, uint32_t r[4]) {
    asm volatile("ldmatrix.sync.aligned.m8n8.x4.shared.b16 {%0,%1,%2,%3}, [%4];"
                 : "=r"(r[0]), "=r"(r[1]), "=r"(r[2]), "=r"(r[3]) : "r"(addr));
}

__device__ __forceinline__ void mma_f16(float d[4], const uint32_t a[4],
                                        uint32_t b0, uint32_t b1) {
    asm volatile(
        "mma.sync.aligned.m16n8k16.row.col.f32.f16.f16.f32 "
        "{%0,%1,%2,%3}, {%4,%5,%6,%7}, {%8,%9}, {%0,%1,%2,%3};"
        : "+f"(d[0]), "+f"(d[1]), "+f"(d[2]), "+f"(d[3])
        : "r"(a[0]), "r"(a[1]), "r"(a[2]), "r"(a[3]), "r"(b0), "r"(b1));
}

#define CP_ASYNC16(dst, src) \
    asm volatile("cp.async.cg.shared.global [%0], [%1], 16;" \
                 :: "r"(dst), "l"(src) : "memory")
#define CP_COMMIT()  asm volatile("cp.async.commit_group;" ::: "memory")
#define CP_WAIT2()   asm volatile("cp.async.wait_group 2;" ::: "memory")

__device__ __forceinline__ uint32_t pack2(float f0, float f1) {
    __half h0 = __float2half_rn(f0);
    __half h1 = __float2half_rn(f1);
    return (uint32_t)__half_as_ushort(h0) | ((uint32_t)__half_as_ushort(h1) << 16);
}

// stage-relative ldmatrix offset within a padded [rows][40] fp16 plane
__device__ __forceinline__ uint32_t ldrel(uint32_t plane, int rbase, int lane) {
    int row = rbase + (lane & 15);
    int col = (lane >> 4) << 3;
    return plane + (uint32_t)((row * 40 + col) << 1);
}

// ---------------------------------------------------------------------------
// Convert kernel (weights fp32 -> fp16)
// ---------------------------------------------------------------------------
#define SEG_GP 8388608
#define SEG_UP 16777216
#define SEG_DP 25165824
#define SEG_SG 25690112
#define SEG_SU 26214400
#define SEG_SD 26738688

__global__ __launch_bounds__(256) void split_weights_kernel(
    const float4* __restrict__ gp, const float4* __restrict__ up,
    const float4* __restrict__ dp, const float4* __restrict__ sg,
    const float4* __restrict__ su, const float4* __restrict__ sd)
{
    int i = blockIdx.x * blockDim.x + threadIdx.x;
    const int stride = gridDim.x * blockDim.x;
    for (; i < SEG_SD; i += stride) {
        const float4* src; uint2* h16; int off;
        if (i < SEG_GP)      { src = gp; off = i;            h16 = (uint2*)d_gp16; }
        else if (i < SEG_UP) { src = up; off = i - SEG_GP;   h16 = (uint2*)d_up16; }
        else if (i < SEG_DP) { src = dp; off = i - SEG_UP;   h16 = (uint2*)d_dp16; }
        else if (i < SEG_SG) { src = sg; off = i - SEG_DP;   h16 = (uint2*)d_sg16; }
        else if (i < SEG_SU) { src = su; off = i - SEG_SG;   h16 = (uint2*)d_su16; }
        else                 { src = sd; off = i - SEG_SU;   h16 = (uint2*)d_sd16; }
        float4 f = src[off];
        uint2 h; h.x = pack2(f.x, f.y); h.y = pack2(f.z, f.w);
        h16[off] = h;
    }
}

__global__ __launch_bounds__(256) void zero_out_kernel(float4* __restrict__ out, int n4)
{
    int i = blockIdx.x * blockDim.x + threadIdx.x;
    int stride = gridDim.x * blockDim.x;
    float4 z = {0.f, 0.f, 0.f, 0.f};
    for (; i < n4; i += stride) out[i] = z;
}

__global__ void zero_counts_kernel() {
    if (threadIdx.x < N_EXP) d_counts[threadIdx.x] = 0;
}

// ---------------------------------------------------------------------------
// Routing + x fp32->fp16 conversion (fused)
// ---------------------------------------------------------------------------
__global__ __launch_bounds__(256) void route_kernel(
    const float* __restrict__ x, const float* __restrict__ gw,
    const float* __restrict__ bias)
{
    __shared__ float xs[H_DIM];
    __shared__ float logits[N_EXP];
    const int t = blockIdx.x;
    const float* xr = x + (size_t)t * H_DIM;
    for (int i = threadIdx.x; i < H_DIM; i += blockDim.x) xs[i] = xr[i];
    __syncthreads();

    {
        uint32_t* dst = (uint32_t*)(d_x16 + (size_t)t * H_DIM);
        for (int i = threadIdx.x; i < H_DIM / 2; i += blockDim.x)
            dst[i] = pack2(xs[i * 2], xs[i * 2 + 1]);
    }

    const int e = threadIdx.x >> 4, lane = threadIdx.x & 15;
    const float* g = gw + (size_t)e * H_DIM;
    float s = 0.f;
    for (int k = lane; k < H_DIM; k += 16) s += xs[k] * g[k];
    #pragma unroll
    for (int o = 8; o > 0; o >>= 1) s += __shfl_down_sync(0xffffffffu, s, o, 16);
    if (lane == 0) logits[e] = s;
    __syncthreads();

    if (threadIdx.x == 0) {
        float sc[N_EXP], bs[N_EXP];
        #pragma unroll
        for (int i = 0; i < N_EXP; i++) {
            sc[i] = 1.f / (1.f + expf(-logits[i]));
            bs[i] = sc[i] + bias[i];
        }
        float gsc[NGRP];
        #pragma unroll
        for (int gi = 0; gi < NGRP; gi++) {
            float m1 = -1e30f, m2 = -1e30f;
            #pragma unroll
            for (int j = 0; j < GSZ; j++) {
                float v = bs[gi * GSZ + j];
                if (v > m1) { m2 = m1; m1 = v; } else if (v > m2) { m2 = v; }
            }
            gsc[gi] = m1 + m2;
        }
        int g1 = 0;
        for (int gi = 1; gi < NGRP; gi++) if (gsc[gi] > gsc[g1]) g1 = gi;
        int g2 = -1;
        for (int gi = 0; gi < NGRP; gi++) {
            if (gi == g1) continue;
            if (g2 < 0 || gsc[gi] > gsc[g2]) g2 = gi;
        }
        bool allowed[N_EXP], used[N_EXP];
        #pragma unroll
        for (int i = 0; i < N_EXP; i++) {
            int gi = i / GSZ;
            allowed[i] = (gi == g1 || gi == g2);
            used[i] = false;
        }
        int sel[TOPK]; float wv[TOPK]; float wsum = 0.f;
        #pragma unroll
        for (int kk = 0; kk < TOPK; kk++) {
            int best = -1; float bv = -1e30f;
            for (int i = 0; i < N_EXP; i++) {
                if (!allowed[i] || used[i]) continue;
                if (best < 0 || bs[i] > bv) { best = i; bv = bs[i]; }
            }
            used[best] = true; sel[kk] = best; wv[kk] = sc[best]; wsum += sc[best];
        }
        const float inv = SCALING / (wsum + 1e-20f);
        #pragma unroll
        for (int kk = 0; kk < TOPK; kk++) {
            int ee = sel[kk];
            int slot = atomicAdd(&d_counts[ee], 1);
            d_tok[ee][slot] = t;
            d_wgt[ee][slot] = wv[kk] * inv;
        }
    }
}

// ---------------------------------------------------------------------------
// GEMM1: 256 threads (8 warps = 4m x 2n), CTA tile M=128 x N=64 x BK=32.
// Warp tile 32m x 32n, dual output (gate & up). 2 CTAs/SM.
// Stage planes: A 0, G 10240, U 15360.
// ---------------------------------------------------------------------------
__global__ __launch_bounds__(256, 2) void gemm1_mma()
{
    const int e = blockIdx.z;
    const bool shared = (e == N_EXP);
    const int ne = shared ? T_TOK : d_counts[e];
    const int m0 = blockIdx.y * 128;
    if (m0 >= ne) return;
    const int n0 = blockIdx.x * 64;

    extern __shared__ __align__(16) char dynsmem[];
    __shared__ int toks[128];

    const int tid = threadIdx.x, lane = tid & 31, wid = tid >> 5;
    const int wm = wid >> 1, wn = wid & 1;
    const uint32_t sb = smem_u32(dynsmem);

    if (tid < 128) {
        int r = m0 + tid;
        toks[tid] = shared ? r : (r < ne ? d_tok[e][r] : d_tok[e][0]);
    }
    __syncthreads();

    const size_t eoff = shared ? 0 : (size_t)e * I_DIM * H_DIM;
    const __half* gP = shared ? d_sg16 : d_gp16 + eoff;
    const __half* uP = shared ? d_su16 : d_up16 + eoff;

    // A: 512 chunks -> 2/thr; G/U: 256 chunks -> 1/thr each
    const int a0R = tid >> 2,          a0C = tid & 3;
    const int a1R = (tid + 256) >> 2,  a1C = tid & 3;
    const uint32_t dstA0 = (uint32_t)(a0R * 80 + a0C * 16);
    const uint32_t dstA1 = (uint32_t)(a1R * 80 + a1C * 16);
    const int bRr = tid >> 2, bCc = tid & 3;
    const uint32_t dstG = (uint32_t)(10240 + bRr * 80 + bCc * 16);
    const uint32_t dstU = dstG + 5120u;
    const __half* xPtr0 = d_x16 + (size_t)toks[a0R] * H_DIM + a0C * 8;
    const __half* xPtr1 = d_x16 + (size_t)toks[a1R] * H_DIM + a1C * 8;
    const __half* gPtr = gP + (size_t)(n0 + bRr) * H_DIM + bCc * 8;
    const __half* uPtr = uP + (size_t)(n0 + bRr) * H_DIM + bCc * 8;

    uint32_t rA[2], rG[2], rU[2];
    #pragma unroll
    for (int mi = 0; mi < 2; mi++)
        rA[mi] = ldrel(0u, wm * 32 + mi * 16, lane);
    #pragma unroll
    for (int j = 0; j < 2; j++) {
        rG[j] = ldrel(10240u, wn * 32 + j * 16, lane);
        rU[j] = ldrel(15360u, wn * 32 + j * 16, lane);
    }

    auto issue = [&](int kt) {
        const uint32_t st = sb + (uint32_t)(kt & 3) * STAGE_BYTES;
        CP_ASYNC16(st + dstA0, xPtr0); xPtr0 += 32;
        CP_ASYNC16(st + dstA1, xPtr1); xPtr1 += 32;
        CP_ASYNC16(st + dstG,  gPtr);  gPtr  += 32;
        CP_ASYNC16(st + dstU,  uPtr);  uPtr  += 32;
    };

    float cg[2][4][4] = {}, cu[2][4][4] = {};

    issue(0); CP_COMMIT();
    issue(1); CP_COMMIT();
    issue(2); CP_COMMIT();

    const int NK = H_DIM / 32;
    #pragma unroll 1
    for (int kt = 0; kt < NK; ++kt) {
        CP_WAIT2();
        __syncthreads();
        if (kt + 3 < NK) issue(kt + 3);
        CP_COMMIT();

        const uint32_t cur = sb + (uint32_t)(kt & 3) * STAGE_BYTES;
        #pragma unroll
        for (int kk = 0; kk < 2; ++kk) {
            const uint32_t kb = cur + (uint32_t)(kk * 32);
            uint32_t a[2][4], g0[4], g1[4], u0[4], u1[4];
            #pragma unroll
            for (int mi = 0; mi < 2; mi++)
                ldm_x4(kb + rA[mi], a[mi]);
            ldm_x4(kb + rG[0], g0); ldm_x4(kb + rG[1], g1);
            ldm_x4(kb + rU[0], u0); ldm_x4(kb + rU[1], u1);
            uint32_t bg[4][2] = {{g0[0],g0[2]},{g0[1],g0[3]},{g1[0],g1[2]},{g1[1],g1[3]}};
            uint32_t bu[4][2] = {{u0[0],u0[2]},{u0[1],u0[3]},{u1[0],u1[2]},{u1[1],u1[3]}};

            #pragma unroll
            for (int mi = 0; mi < 2; mi++)
                #pragma unroll
                for (int ni = 0; ni < 4; ni++)
                    mma_f16(cg[mi][ni], a[mi], bg[ni][0], bg[ni][1]);
            #pragma unroll
            for (int mi = 0; mi < 2; mi++)
                #pragma unroll
                for (int ni = 0; ni < 4; ni++)
                    mma_f16(cu[mi][ni], a[mi], bu[ni][0], bu[ni][1]);
        }
    }

    // epilogue: silu(g)*u -> fp16 plane
    const int gr = lane >> 2, tc = (lane & 3) * 2;
    __half* ph = shared ? &d_h1s[0][0] : &d_h1[e][0][0];

    #pragma unroll
    for (int mi = 0; mi < 2; mi++)
        #pragma unroll
        for (int ni = 0; ni < 4; ni++) {
            int ncol = n0 + wn * 32 + ni * 8 + tc;
            #pragma unroll
            for (int half = 0; half < 2; half++) {
                int m = m0 + wm * 32 + mi * 16 + gr + half * 8;
                float g0 = cg[mi][ni][half * 2],     u0 = cu[mi][ni][half * 2];
                float g1 = cg[mi][ni][half * 2 + 1], u1 = cu[mi][ni][half * 2 + 1];
                float o0 = (g0 / (1.f + expf(-g0))) * u0;
                float o1 = (g1 / (1.f + expf(-g1))) * u1;
                *(uint32_t*)(ph + (size_t)m * I_DIM + ncol) = pack2(o0, o1);
            }
        }
}

// ---------------------------------------------------------------------------
// GEMM2: 256 threads (8 warps = 4m x 2n), CTA tile M=128 x N=128 x BK=32.
// Warp tile 32m x 64n. 2 CTAs/SM. Atomic scatter epilogue.
// Stage planes: A 0, B 10240.
// ---------------------------------------------------------------------------
__global__ __launch_bounds__(256, 2) void gemm2_mma(float* __restrict__ out)
{
    const int e = blockIdx.z;
    const bool shared = (e == N_EXP);
    const int ne = shared ? T_TOK : d_counts[e];
    const int m0 = blockIdx.y * 128;
    if (m0 >= ne) return;
    const int n0 = blockIdx.x * 128;

    extern __shared__ __align__(16) char dynsmem[];
    __shared__ int   toks[128];
    __shared__ float wgts[128];

    const int tid = threadIdx.x, lane = tid & 31, wid = tid >> 5;
    const int wm = wid >> 1, wn = wid & 1;
    const uint32_t sb = smem_u32(dynsmem);

    if (tid < 128) {
        int r = m0 + tid;
        if (shared) { toks[tid] = r; wgts[tid] = 1.f; }
        else {
            toks[tid] = (r < ne) ? d_tok[e][r] : 0;
            wgts[tid] = (r < ne) ? d_wgt[e][r] : 0.f;
        }
    }
    __syncthreads();

    const __half* ah1 = shared ? &d_h1s[0][0] : &d_h1[e][0][0];
    const size_t eoff = shared ? 0 : (size_t)e * H_DIM * I_DIM;
    const __half* dw = shared ? d_sd16 : d_dp16 + eoff;

    // A: 512 chunks -> 2/thr; B: 512 chunks -> 2/thr
    const int a0R = tid >> 2,         a0C = tid & 3;
    const int a1R = (tid + 256) >> 2, a1C = tid & 3;
    const uint32_t dstA0 = (uint32_t)(a0R * 80 + a0C * 16);
    const uint32_t dstA1 = (uint32_t)(a1R * 80 + a1C * 16);
    const uint32_t dstB0 = dstA0 + 10240u;
    const uint32_t dstB1 = dstA1 + 10240u;
    const __half* aPtr0 = ah1 + (size_t)(m0 + a0R) * I_DIM + a0C * 8;
    const __half* aPtr1 = ah1 + (size_t)(m0 + a1R) * I_DIM + a1C * 8;
    const __half* bPtr0 = dw + (size_t)(n0 + a0R) * I_DIM + a0C * 8;
    const __half* bPtr1 = dw + (size_t)(n0 + a1R) * I_DIM + a1C * 8;

    uint32_t rA[2], rB[4];
    #pragma unroll
    for (int mi = 0; mi < 2; mi++)
        rA[mi] = ldrel(0u, wm * 32 + mi * 16, lane);
    #pragma unroll
    for (int j = 0; j < 4; j++)
        rB[j] = ldrel(10240u, wn * 64 + j * 16, lane);

    auto issue = [&](int kt) {
        const uint32_t st = sb + (uint32_t)(kt & 3) * STAGE_BYTES;
        CP_ASYNC16(st + dstA0, aPtr0); aPtr0 += 32;
        CP_ASYNC16(st + dstA1, aPtr1); aPtr1 += 32;
        CP_ASYNC16(st + dstB0, bPtr0); bPtr0 += 32;
        CP_ASYNC16(st + dstB1, bPtr1); bPtr1 += 32;
    };

    float cd[2][8][4] = {};

    issue(0); CP_COMMIT();
    issue(1); CP_COMMIT();
    issue(2); CP_COMMIT();

    const int NK = I_DIM / 32;
    #pragma unroll 1
    for (int kt = 0; kt < NK; ++kt) {
        CP_WAIT2();
        __syncthreads();
        if (kt + 3 < NK) issue(kt + 3);
        CP_COMMIT();

        const uint32_t cur = sb + (uint32_t)(kt & 3) * STAGE_BYTES;
        #pragma unroll
        for (int kk = 0; kk < 2; ++kk) {
            const uint32_t kb = cur + (uint32_t)(kk * 32);
            uint32_t a[2][4], h[4][4];
            #pragma unroll
            for (int mi = 0; mi < 2; mi++)
                ldm_x4(kb + rA[mi], a[mi]);
            #pragma unroll
            for (int j = 0; j < 4; j++)
                ldm_x4(kb + rB[j], h[j]);
            uint32_t bh[8][2];
            #pragma unroll
            for (int j = 0; j < 4; j++) {
                bh[j*2][0]   = h[j][0]; bh[j*2][1]   = h[j][2];
                bh[j*2+1][0] = h[j][1]; bh[j*2+1][1] = h[j][3];
            }
            #pragma unroll
            for (int mi = 0; mi < 2; mi++)
                #pragma unroll
                for (int ni = 0; ni < 8; ni++)
                    mma_f16(cd[mi][ni], a[mi], bh[ni][0], bh[ni][1]);
        }
    }

    // epilogue: weighted atomic scatter (out pre-zeroed)
    const int gr = lane >> 2, tc = (lane & 3) * 2;
    #pragma unroll
    for (int mi = 0; mi < 2; mi++) {
        #pragma unroll
        for (int half = 0; half < 2; half++) {
            int mloc = wm * 32 + mi * 16 + gr + half * 8;
            if (m0 + mloc >= ne) continue;
            int   t = toks[mloc];
            float w = wgts[mloc];
            float* orow = out + (size_t)t * H_DIM;
            #pragma unroll
            for (int ni = 0; ni < 8; ni++) {
                int ncol = n0 + wn * 64 + ni * 8 + tc;
                atomicAdd(orow + ncol,     w * cd[mi][ni][half * 2]);
                atomicAdd(orow + ncol + 1, w * cd[mi][ni][half * 2 + 1]);
            }
        }
    }
}

// ---------------------------------------------------------------------------
// Launch — gemm1 kept as the 4th launch (ncu capture slot)
// ---------------------------------------------------------------------------
extern "C" void kernel_launch(void* const* d_in, const int* in_sizes, int n_in,
                              void* d_out, int out_size)
{
    const float* x  = (const float*)d_in[0];
    const float* gw = (const float*)d_in[1];
    const float* eb = (const float*)d_in[2];
    const float* gp = (const float*)d_in[3];
    const float* up = (const float*)d_in[4];
    const float* dp = (const float*)d_in[5];
    const float* sg = (const float*)d_in[6];
    const float* su = (const float*)d_in[7];
    const float* sd = (const float*)d_in[8];
    float* out = (float*)d_out;

    cudaFuncSetAttribute((const void*)gemm1_mma, cudaFuncAttributeMaxDynamicSharedMemorySize, SMEM_DYN);
    cudaFuncSetAttribute((const void*)gemm2_mma, cudaFuncAttributeMaxDynamicSharedMemorySize, SMEM_DYN);

    split_weights_kernel<<<4096, 256>>>((const float4*)gp, (const float4*)up,
                                        (const float4*)dp, (const float4*)sg,
                                        (const float4*)su, (const float4*)sd);
    zero_counts_kernel<<<1, 32>>>();
    route_kernel<<<T_TOK, 256>>>(x, gw, eb);
    gemm1_mma<<<dim3(I_DIM / 64, T_TOK / 128, N_EXP + 1), 256, SMEM_DYN>>>();
    zero_out_kernel<<<1024, 256>>>((float4*)out, out_size / 4);
    gemm2_mma<<<dim3(H_DIM / 128, T_TOK / 128, N_EXP + 1), 256, SMEM_DYN>>>(out);
}

// round 14
// speedup vs baseline: 2.7099x; 1.0176x over previous
#include <cuda_runtime.h>
#include <cuda_fp16.h>
#include <stdint.h>
#include <math.h>

#define T_TOK 2048
#define H_DIM 2048
#define I_DIM 1024
#define N_EXP 16
#define TOPK  4
#define NGRP  4
#define GSZ   4
#define SCALING 2.5f

#define STAGE_BYTES 20480u
#define N_STAGES    4
#define SMEM_DYN    (N_STAGES * STAGE_BYTES)   // 81920 -> 2 CTAs/SM

// ---------------------------------------------------------------------------
// Scratch (device globals). Everything plain fp16.
// ---------------------------------------------------------------------------
__device__ int   d_counts[N_EXP];
__device__ int   d_tok[N_EXP][T_TOK];
__device__ float d_wgt[N_EXP][T_TOK];
__device__ __half d_h1 [N_EXP][T_TOK][I_DIM];
__device__ __half d_h1s[T_TOK][I_DIM];
__device__ __half d_x16[T_TOK * H_DIM];
__device__ __half d_gp16[N_EXP * I_DIM * H_DIM];
__device__ __half d_up16[N_EXP * I_DIM * H_DIM];
__device__ __half d_dp16[N_EXP * H_DIM * I_DIM];
__device__ __half d_sg16[I_DIM * H_DIM];
__device__ __half d_su16[I_DIM * H_DIM];
__device__ __half d_sd16[H_DIM * I_DIM];

// ---------------------------------------------------------------------------
// PTX helpers (baseline sm_80+ only)
// ---------------------------------------------------------------------------
__device__ __forceinline__ uint32_t smem_u32(const void* p) {
    uint32_t a;
    asm("{ .reg .u64 t; cvta.to.shared.u64 t, %1; cvt.u32.u64 %0, t; }"
        : "=r"(a) : "l"(p));
    return a;
}

__device__ __forceinline__ void ldm_x4(uint32_t addr, uint32_t r[4]) {
    asm volatile("ldmatrix.sync.aligned.m8n8.x4.shared.b16 {%0,%1,%2,%3}, [%4];"
                 : "=r"(r[0]), "=r"(r[1]), "=r"(r[2]), "=r"(r[3]) : "r"(addr));
}

__device__ __forceinline__ void mma_f16(float d[4], const uint32_t a[4],
                                        uint32_t b0, uint32_t b1) {
    asm volatile(
        "mma.sync.aligned.m16n8k16.row.col.f32.f16.f16.f32 "
        "{%0,%1,%2,%3}, {%4,%5,%6,%7}, {%8,%9}, {%0,%1,%2,%3};"
        : "+f"(d[0]), "+f"(d[1]), "+f"(d[2]), "+f"(d[3])
        : "r"(a[0]), "r"(a[1]), "r"(a[2]), "r"(a[3]), "r"(b0), "r"(b1));
}

#define CP_ASYNC16(dst, src) \
    asm volatile("cp.async.cg.shared.global [%0], [%1], 16;" \
                 :: "r"(dst), "l"(src) : "memory")
#define CP_COMMIT()  asm volatile("cp.async.commit_group;" ::: "memory")
#define CP_WAIT2()   asm volatile("cp.async.wait_group 2;" ::: "memory")

__device__ __forceinline__ uint32_t pack2(float f0, float f1) {
    __half h0 = __float2half_rn(f0);
    __half h1 = __float2half_rn(f1);
    return (uint32_t)__half_as_ushort(h0) | ((uint32_t)__half_as_ushort(h1) << 16);
}

__device__ __forceinline__ uint32_t ldrel(uint32_t plane, int rbase, int lane) {
    int row = rbase + (lane & 15);
    int col = (lane >> 4) << 3;
    return plane + (uint32_t)((row * 40 + col) << 1);
}

// ---------------------------------------------------------------------------
// Weight conversion, split in two for stream overlap
//   GU: gate_proj + up_proj + shared_gate + shared_up  (17.8M float4)
//   DN: down_proj + shared_down                        ( 8.9M float4)
// ---------------------------------------------------------------------------
#define GU_GP 8388608
#define GU_UP 16777216
#define GU_SG 17301504
#define GU_SU 17825792

__global__ __launch_bounds__(256) void split_gu_kernel(
    const float4* __restrict__ gp, const float4* __restrict__ up,
    const float4* __restrict__ sg, const float4* __restrict__ su)
{
    int i = blockIdx.x * blockDim.x + threadIdx.x;
    const int stride = gridDim.x * blockDim.x;
    for (; i < GU_SU; i += stride) {
        const float4* src; uint2* h16; int off;
        if (i < GU_GP)      { src = gp; off = i;          h16 = (uint2*)d_gp16; }
        else if (i < GU_UP) { src = up; off = i - GU_GP;  h16 = (uint2*)d_up16; }
        else if (i < GU_SG) { src = sg; off = i - GU_UP;  h16 = (uint2*)d_sg16; }
        else                { src = su; off = i - GU_SG;  h16 = (uint2*)d_su16; }
        float4 f = src[off];
        uint2 h; h.x = pack2(f.x, f.y); h.y = pack2(f.z, f.w);
        h16[off] = h;
    }
}

#define DN_DP 8388608
#define DN_SD 8912896

__global__ __launch_bounds__(256) void split_dn_kernel(
    const float4* __restrict__ dp, const float4* __restrict__ sd)
{
    int i = blockIdx.x * blockDim.x + threadIdx.x;
    const int stride = gridDim.x * blockDim.x;
    for (; i < DN_SD; i += stride) {
        const float4* src; uint2* h16; int off;
        if (i < DN_DP) { src = dp; off = i;          h16 = (uint2*)d_dp16; }
        else           { src = sd; off = i - DN_DP;  h16 = (uint2*)d_sd16; }
        float4 f = src[off];
        uint2 h; h.x = pack2(f.x, f.y); h.y = pack2(f.z, f.w);
        h16[off] = h;
    }
}

__global__ __launch_bounds__(256) void zero_out_kernel(float4* __restrict__ out, int n4)
{
    int i = blockIdx.x * blockDim.x + threadIdx.x;
    int stride = gridDim.x * blockDim.x;
    float4 z = {0.f, 0.f, 0.f, 0.f};
    for (; i < n4; i += stride) out[i] = z;
}

__global__ void zero_counts_kernel() {
    if (threadIdx.x < N_EXP) d_counts[threadIdx.x] = 0;
}

// ---------------------------------------------------------------------------
// Routing + x fp32->fp16 conversion (fused)
// ---------------------------------------------------------------------------
__global__ __launch_bounds__(256) void route_kernel(
    const float* __restrict__ x, const float* __restrict__ gw,
    const float* __restrict__ bias)
{
    __shared__ float xs[H_DIM];
    __shared__ float logits[N_EXP];
    const int t = blockIdx.x;
    const float* xr = x + (size_t)t * H_DIM;
    for (int i = threadIdx.x; i < H_DIM; i += blockDim.x) xs[i] = xr[i];
    __syncthreads();

    {
        uint32_t* dst = (uint32_t*)(d_x16 + (size_t)t * H_DIM);
        for (int i = threadIdx.x; i < H_DIM / 2; i += blockDim.x)
            dst[i] = pack2(xs[i * 2], xs[i * 2 + 1]);
    }

    const int e = threadIdx.x >> 4, lane = threadIdx.x & 15;
    const float* g = gw + (size_t)e * H_DIM;
    float s = 0.f;
    for (int k = lane; k < H_DIM; k += 16) s += xs[k] * g[k];
    #pragma unroll
    for (int o = 8; o > 0; o >>= 1) s += __shfl_down_sync(0xffffffffu, s, o, 16);
    if (lane == 0) logits[e] = s;
    __syncthreads();

    if (threadIdx.x == 0) {
        float sc[N_EXP], bs[N_EXP];
        #pragma unroll
        for (int i = 0; i < N_EXP; i++) {
            sc[i] = 1.f / (1.f + expf(-logits[i]));
            bs[i] = sc[i] + bias[i];
        }
        float gsc[NGRP];
        #pragma unroll
        for (int gi = 0; gi < NGRP; gi++) {
            float m1 = -1e30f, m2 = -1e30f;
            #pragma unroll
            for (int j = 0; j < GSZ; j++) {
                float v = bs[gi * GSZ + j];
                if (v > m1) { m2 = m1; m1 = v; } else if (v > m2) { m2 = v; }
            }
            gsc[gi] = m1 + m2;
        }
        int g1 = 0;
        for (int gi = 1; gi < NGRP; gi++) if (gsc[gi] > gsc[g1]) g1 = gi;
        int g2 = -1;
        for (int gi = 0; gi < NGRP; gi++) {
            if (gi == g1) continue;
            if (g2 < 0 || gsc[gi] > gsc[g2]) g2 = gi;
        }
        bool allowed[N_EXP], used[N_EXP];
        #pragma unroll
        for (int i = 0; i < N_EXP; i++) {
            int gi = i / GSZ;
            allowed[i] = (gi == g1 || gi == g2);
            used[i] = false;
        }
        int sel[TOPK]; float wv[TOPK]; float wsum = 0.f;
        #pragma unroll
        for (int kk = 0; kk < TOPK; kk++) {
            int best = -1; float bv = -1e30f;
            for (int i = 0; i < N_EXP; i++) {
                if (!allowed[i] || used[i]) continue;
                if (best < 0 || bs[i] > bv) { best = i; bv = bs[i]; }
            }
            used[best] = true; sel[kk] = best; wv[kk] = sc[best]; wsum += sc[best];
        }
        const float inv = SCALING / (wsum + 1e-20f);
        #pragma unroll
        for (int kk = 0; kk < TOPK; kk++) {
            int ee = sel[kk];
            int slot = atomicAdd(&d_counts[ee], 1);
            d_tok[ee][slot] = t;
            d_wgt[ee][slot] = wv[kk] * inv;
        }
    }
}

// ---------------------------------------------------------------------------
// GEMM1: 256 threads (8 warps = 4m x 2n), CTA tile M=128 x N=64 x BK=32.
// Warp tile 32m x 32n, dual output. 2 CTAs/SM. (unchanged from R13)
// Stage planes: A 0, G 10240, U 15360.
// ---------------------------------------------------------------------------
__global__ __launch_bounds__(256, 2) void gemm1_mma()
{
    const int e = blockIdx.z;
    const bool shared = (e == N_EXP);
    const int ne = shared ? T_TOK : d_counts[e];
    const int m0 = blockIdx.y * 128;
    if (m0 >= ne) return;
    const int n0 = blockIdx.x * 64;

    extern __shared__ __align__(16) char dynsmem[];
    __shared__ int toks[128];

    const int tid = threadIdx.x, lane = tid & 31, wid = tid >> 5;
    const int wm = wid >> 1, wn = wid & 1;
    const uint32_t sb = smem_u32(dynsmem);

    if (tid < 128) {
        int r = m0 + tid;
        toks[tid] = shared ? r : (r < ne ? d_tok[e][r] : d_tok[e][0]);
    }
    __syncthreads();

    const size_t eoff = shared ? 0 : (size_t)e * I_DIM * H_DIM;
    const __half* gP = shared ? d_sg16 : d_gp16 + eoff;
    const __half* uP = shared ? d_su16 : d_up16 + eoff;

    const int a0R = tid >> 2,          a0C = tid & 3;
    const int a1R = (tid + 256) >> 2,  a1C = tid & 3;
    const uint32_t dstA0 = (uint32_t)(a0R * 80 + a0C * 16);
    const uint32_t dstA1 = (uint32_t)(a1R * 80 + a1C * 16);
    const int bRr = tid >> 2, bCc = tid & 3;
    const uint32_t dstG = (uint32_t)(10240 + bRr * 80 + bCc * 16);
    const uint32_t dstU = dstG + 5120u;
    const __half* xPtr0 = d_x16 + (size_t)toks[a0R] * H_DIM + a0C * 8;
    const __half* xPtr1 = d_x16 + (size_t)toks[a1R] * H_DIM + a1C * 8;
    const __half* gPtr = gP + (size_t)(n0 + bRr) * H_DIM + bCc * 8;
    const __half* uPtr = uP + (size_t)(n0 + bRr) * H_DIM + bCc * 8;

    uint32_t rA[2], rG[2], rU[2];
    #pragma unroll
    for (int mi = 0; mi < 2; mi++)
        rA[mi] = ldrel(0u, wm * 32 + mi * 16, lane);
    #pragma unroll
    for (int j = 0; j < 2; j++) {
        rG[j] = ldrel(10240u, wn * 32 + j * 16, lane);
        rU[j] = ldrel(15360u, wn * 32 + j * 16, lane);
    }

    auto issue = [&](int kt) {
        const uint32_t st = sb + (uint32_t)(kt & 3) * STAGE_BYTES;
        CP_ASYNC16(st + dstA0, xPtr0); xPtr0 += 32;
        CP_ASYNC16(st + dstA1, xPtr1); xPtr1 += 32;
        CP_ASYNC16(st + dstG,  gPtr);  gPtr  += 32;
        CP_ASYNC16(st + dstU,  uPtr);  uPtr  += 32;
    };

    float cg[2][4][4] = {}, cu[2][4][4] = {};

    issue(0); CP_COMMIT();
    issue(1); CP_COMMIT();
    issue(2); CP_COMMIT();

    const int NK = H_DIM / 32;
    #pragma unroll 1
    for (int kt = 0; kt < NK; ++kt) {
        CP_WAIT2();
        __syncthreads();
        if (kt + 3 < NK) issue(kt + 3);
        CP_COMMIT();

        const uint32_t cur = sb + (uint32_t)(kt & 3) * STAGE_BYTES;
        #pragma unroll
        for (int kk = 0; kk < 2; ++kk) {
            const uint32_t kb = cur + (uint32_t)(kk * 32);
            uint32_t a[2][4], g0[4], g1[4], u0[4], u1[4];
            #pragma unroll
            for (int mi = 0; mi < 2; mi++)
                ldm_x4(kb + rA[mi], a[mi]);
            ldm_x4(kb + rG[0], g0); ldm_x4(kb + rG[1], g1);
            ldm_x4(kb + rU[0], u0); ldm_x4(kb + rU[1], u1);
            uint32_t bg[4][2] = {{g0[0],g0[2]},{g0[1],g0[3]},{g1[0],g1[2]},{g1[1],g1[3]}};
            uint32_t bu[4][2] = {{u0[0],u0[2]},{u0[1],u0[3]},{u1[0],u1[2]},{u1[1],u1[3]}};

            #pragma unroll
            for (int mi = 0; mi < 2; mi++)
                #pragma unroll
                for (int ni = 0; ni < 4; ni++)
                    mma_f16(cg[mi][ni], a[mi], bg[ni][0], bg[ni][1]);
            #pragma unroll
            for (int mi = 0; mi < 2; mi++)
                #pragma unroll
                for (int ni = 0; ni < 4; ni++)
                    mma_f16(cu[mi][ni], a[mi], bu[ni][0], bu[ni][1]);
        }
    }

    const int gr = lane >> 2, tc = (lane & 3) * 2;
    __half* ph = shared ? &d_h1s[0][0] : &d_h1[e][0][0];

    #pragma unroll
    for (int mi = 0; mi < 2; mi++)
        #pragma unroll
        for (int ni = 0; ni < 4; ni++) {
            int ncol = n0 + wn * 32 + ni * 8 + tc;
            #pragma unroll
            for (int half = 0; half < 2; half++) {
                int m = m0 + wm * 32 + mi * 16 + gr + half * 8;
                float g0 = cg[mi][ni][half * 2],     u0 = cu[mi][ni][half * 2];
                float g1 = cg[mi][ni][half * 2 + 1], u1 = cu[mi][ni][half * 2 + 1];
                float o0 = (g0 / (1.f + expf(-g0))) * u0;
                float o1 = (g1 / (1.f + expf(-g1))) * u1;
                *(uint32_t*)(ph + (size_t)m * I_DIM + ncol) = pack2(o0, o1);
            }
        }
}

// ---------------------------------------------------------------------------
// GEMM2: 256 threads (8 warps = 4m x 2n), CTA tile M=128 x N=128 x BK=32.
// Warp tile 32m x 64n. 2 CTAs/SM. Atomic scatter. (unchanged from R13)
// Stage planes: A 0, B 10240.
// ---------------------------------------------------------------------------
__global__ __launch_bounds__(256, 2) void gemm2_mma(float* __restrict__ out)
{
    const int e = blockIdx.z;
    const bool shared = (e == N_EXP);
    const int ne = shared ? T_TOK : d_counts[e];
    const int m0 = blockIdx.y * 128;
    if (m0 >= ne) return;
    const int n0 = blockIdx.x * 128;

    extern __shared__ __align__(16) char dynsmem[];
    __shared__ int   toks[128];
    __shared__ float wgts[128];

    const int tid = threadIdx.x, lane = tid & 31, wid = tid >> 5;
    const int wm = wid >> 1, wn = wid & 1;
    const uint32_t sb = smem_u32(dynsmem);

    if (tid < 128) {
        int r = m0 + tid;
        if (shared) { toks[tid] = r; wgts[tid] = 1.f; }
        else {
            toks[tid] = (r < ne) ? d_tok[e][r] : 0;
            wgts[tid] = (r < ne) ? d_wgt[e][r] : 0.f;
        }
    }
    __syncthreads();

    const __half* ah1 = shared ? &d_h1s[0][0] : &d_h1[e][0][0];
    const size_t eoff = shared ? 0 : (size_t)e * H_DIM * I_DIM;
    const __half* dw = shared ? d_sd16 : d_dp16 + eoff;

    const int a0R = tid >> 2,         a0C = tid & 3;
    const int a1R = (tid + 256) >> 2, a1C = tid & 3;
    const uint32_t dstA0 = (uint32_t)(a0R * 80 + a0C * 16);
    const uint32_t dstA1 = (uint32_t)(a1R * 80 + a1C * 16);
    const uint32_t dstB0 = dstA0 + 10240u;
    const uint32_t dstB1 = dstA1 + 10240u;
    const __half* aPtr0 = ah1 + (size_t)(m0 + a0R) * I_DIM + a0C * 8;
    const __half* aPtr1 = ah1 + (size_t)(m0 + a1R) * I_DIM + a1C * 8;
    const __half* bPtr0 = dw + (size_t)(n0 + a0R) * I_DIM + a0C * 8;
    const __half* bPtr1 = dw + (size_t)(n0 + a1R) * I_DIM + a1C * 8;

    uint32_t rA[2], rB[4];
    #pragma unroll
    for (int mi = 0; mi < 2; mi++)
        rA[mi] = ldrel(0u, wm * 32 + mi * 16, lane);
    #pragma unroll
    for (int j = 0; j < 4; j++)
        rB[j] = ldrel(10240u, wn * 64 + j * 16, lane);

    auto issue = [&](int kt) {
        const uint32_t st = sb + (uint32_t)(kt & 3) * STAGE_BYTES;
        CP_ASYNC16(st + dstA0, aPtr0); aPtr0 += 32;
        CP_ASYNC16(st + dstA1, aPtr1); aPtr1 += 32;
        CP_ASYNC16(st + dstB0, bPtr0); bPtr0 += 32;
        CP_ASYNC16(st + dstB1, bPtr1); bPtr1 += 32;
    };

    float cd[2][8][4] = {};

    issue(0); CP_COMMIT();
    issue(1); CP_COMMIT();
    issue(2); CP_COMMIT();

    const int NK = I_DIM / 32;
    #pragma unroll 1
    for (int kt = 0; kt < NK; ++kt) {
        CP_WAIT2();
        __syncthreads();
        if (kt + 3 < NK) issue(kt + 3);
        CP_COMMIT();

        const uint32_t cur = sb + (uint32_t)(kt & 3) * STAGE_BYTES;
        #pragma unroll
        for (int kk = 0; kk < 2; ++kk) {
            const uint32_t kb = cur + (uint32_t)(kk * 32);
            uint32_t a[2][4], h[4][4];
            #pragma unroll
            for (int mi = 0; mi < 2; mi++)
                ldm_x4(kb + rA[mi], a[mi]);
            #pragma unroll
            for (int j = 0; j < 4; j++)
                ldm_x4(kb + rB[j], h[j]);
            uint32_t bh[8][2];
            #pragma unroll
            for (int j = 0; j < 4; j++) {
                bh[j*2][0]   = h[j][0]; bh[j*2][1]   = h[j][2];
                bh[j*2+1][0] = h[j][1]; bh[j*2+1][1] = h[j][3];
            }
            #pragma unroll
            for (int mi = 0; mi < 2; mi++)
                #pragma unroll
                for (int ni = 0; ni < 8; ni++)
                    mma_f16(cd[mi][ni], a[mi], bh[ni][0], bh[ni][1]);
        }
    }

    const int gr = lane >> 2, tc = (lane & 3) * 2;
    #pragma unroll
    for (int mi = 0; mi < 2; mi++) {
        #pragma unroll
        for (int half = 0; half < 2; half++) {
            int mloc = wm * 32 + mi * 16 + gr + half * 8;
            if (m0 + mloc >= ne) continue;
            int   t = toks[mloc];
            float w = wgts[mloc];
            float* orow = out + (size_t)t * H_DIM;
            #pragma unroll
            for (int ni = 0; ni < 8; ni++) {
                int ncol = n0 + wn * 64 + ni * 8 + tc;
                atomicAdd(orow + ncol,     w * cd[mi][ni][half * 2]);
                atomicAdd(orow + ncol + 1, w * cd[mi][ni][half * 2 + 1]);
            }
        }
    }
}

// ---------------------------------------------------------------------------
// Launch — multi-stream fork/join (graph-capturable):
//   default: zero_counts -> route ----------\
//   s1:      split_gu -----------------------+--> gemm1 (default)
//   s2 (after split_gu): split_dn, zero_out -+--> gemm2 (default, after gemm1)
// split_dn + zero_out overlap with compute-bound gemm1.
// ---------------------------------------------------------------------------
extern "C" void kernel_launch(void* const* d_in, const int* in_sizes, int n_in,
                              void* d_out, int out_size)
{
    const float* x  = (const float*)d_in[0];
    const float* gw = (const float*)d_in[1];
    const float* eb = (const float*)d_in[2];
    const float* gp = (const float*)d_in[3];
    const float* up = (const float*)d_in[4];
    const float* dp = (const float*)d_in[5];
    const float* sg = (const float*)d_in[6];
    const float* su = (const float*)d_in[7];
    const float* sd = (const float*)d_in[8];
    float* out = (float*)d_out;

    static cudaStream_t s1, s2;
    static cudaEvent_t eFork, eGU, eDown;
    static bool init = false;
    if (!init) {
        cudaFuncSetAttribute((const void*)gemm1_mma, cudaFuncAttributeMaxDynamicSharedMemorySize, SMEM_DYN);
        cudaFuncSetAttribute((const void*)gemm2_mma, cudaFuncAttributeMaxDynamicSharedMemorySize, SMEM_DYN);
        cudaStreamCreateWithFlags(&s1, cudaStreamNonBlocking);
        cudaStreamCreateWithFlags(&s2, cudaStreamNonBlocking);
        cudaEventCreateWithFlags(&eFork, cudaEventDisableTiming);
        cudaEventCreateWithFlags(&eGU,   cudaEventDisableTiming);
        cudaEventCreateWithFlags(&eDown, cudaEventDisableTiming);
        init = true;
    }

    // default stream: counters, then fork point
    zero_counts_kernel<<<1, 32>>>();
    cudaEventRecord(eFork, 0);

    // s1: gate/up weight conversion (concurrent with route below)
    cudaStreamWaitEvent(s1, eFork, 0);
    split_gu_kernel<<<3072, 256, 0, s1>>>((const float4*)gp, (const float4*)up,
                                          (const float4*)sg, (const float4*)su);
    cudaEventRecord(eGU, s1);

    // default: routing (+x conversion) concurrent with split_gu
    route_kernel<<<T_TOK, 256>>>(x, gw, eb);

    // default: gemm1 after both route (stream order) and split_gu (event)
    cudaStreamWaitEvent(0, eGU, 0);
    gemm1_mma<<<dim3(I_DIM / 64, T_TOK / 128, N_EXP + 1), 256, SMEM_DYN>>>();

    // s2: down conversion + output zeroing, hidden under gemm1
    cudaStreamWaitEvent(s2, eGU, 0);
    split_dn_kernel<<<2048, 256, 0, s2>>>((const float4*)dp, (const float4*)sd);
    zero_out_kernel<<<1024, 256, 0, s2>>>((float4*)out, out_size / 4);
    cudaEventRecord(eDown, s2);

    // default: gemm2 after gemm1 (stream order) and s2 work (event)
    cudaStreamWaitEvent(0, eDown, 0);
    gemm2_mma<<<dim3(H_DIM / 128, T_TOK / 128, N_EXP + 1), 256, SMEM_DYN>>>(out);
}

// round 16
// speedup vs baseline: 2.7885x; 1.0290x over previous
#include <cuda_runtime.h>
#include <cuda_fp16.h>
#include <stdint.h>
#include <math.h>

#define T_TOK 2048
#define H_DIM 2048
#define I_DIM 1024
#define N_EXP 16
#define TOPK  4
#define NGRP  4
#define GSZ   4
#define SCALING 2.5f

#define STAGE_BYTES 20480u
#define N_STAGES    4
#define SMEM_DYN    (N_STAGES * STAGE_BYTES)   // 81920 -> 2 CTAs/SM

// ---------------------------------------------------------------------------
// Scratch (device globals). Everything plain fp16.
// ---------------------------------------------------------------------------
__device__ int   d_counts[N_EXP];
__device__ int   d_tok[N_EXP][T_TOK];
__device__ float d_wgt[N_EXP][T_TOK];
__device__ __half d_h1 [N_EXP][T_TOK][I_DIM];
__device__ __half d_h1s[T_TOK][I_DIM];
__device__ __half d_x16[T_TOK * H_DIM];
__device__ __half d_gp16[N_EXP * I_DIM * H_DIM];
__device__ __half d_up16[N_EXP * I_DIM * H_DIM];
__device__ __half d_dp16[N_EXP * H_DIM * I_DIM];
__device__ __half d_sg16[I_DIM * H_DIM];
__device__ __half d_su16[I_DIM * H_DIM];
__device__ __half d_sd16[H_DIM * I_DIM];

// ---------------------------------------------------------------------------
// PTX helpers (baseline sm_80+ only)
// ---------------------------------------------------------------------------
__device__ __forceinline__ uint32_t smem_u32(const void* p) {
    uint32_t a;
    asm("{ .reg .u64 t; cvta.to.shared.u64 t, %1; cvt.u32.u64 %0, t; }"
        : "=r"(a) : "l"(p));
    return a;
}

__device__ __forceinline__ void ldm_x4(uint32_t addr, uint32_t r[4]) {
    asm volatile("ldmatrix.sync.aligned.m8n8.x4.shared.b16 {%0,%1,%2,%3}, [%4];"
                 : "=r"(r[0]), "=r"(r[1]), "=r"(r[2]), "=r"(r[3]) : "r"(addr));
}

__device__ __forceinline__ void mma_f16(float d[4], const uint32_t a[4],
                                        uint32_t b0, uint32_t b1) {
    asm volatile(
        "mma.sync.aligned.m16n8k16.row.col.f32.f16.f16.f32 "
        "{%0,%1,%2,%3}, {%4,%5,%6,%7}, {%8,%9}, {%0,%1,%2,%3};"
        : "+f"(d[0]), "+f"(d[1]), "+f"(d[2]), "+f"(d[3])
        : "r"(a[0]), "r"(a[1]), "r"(a[2]), "r"(a[3]), "r"(b0), "r"(b1));
}

#define CP_ASYNC16(dst, src) \
    asm volatile("cp.async.cg.shared.global [%0], [%1], 16;" \
                 :: "r"(dst), "l"(src) : "memory")
#define CP_COMMIT()  asm volatile("cp.async.commit_group;" ::: "memory")
#define CP_WAIT2()   asm volatile("cp.async.wait_group 2;" ::: "memory")

__device__ __forceinline__ uint32_t pack2(float f0, float f1) {
    __half h0 = __float2half_rn(f0);
    __half h1 = __float2half_rn(f1);
    return (uint32_t)__half_as_ushort(h0) | ((uint32_t)__half_as_ushort(h1) << 16);
}

__device__ __forceinline__ uint32_t ldrel(uint32_t plane, int rbase, int lane) {
    int row = rbase + (lane & 15);
    int col = (lane >> 4) << 3;
    return plane + (uint32_t)((row * 40 + col) << 1);
}

// ---------------------------------------------------------------------------
// Weight conversion kernels (two-phase for pipelining)
//   first: shared gate/up + experts 0-3 gate/up  (5 matrices' worth)
//   rest:  experts 4-15 gate/up
// ---------------------------------------------------------------------------
#define EXP_F4   524288              // float4 per expert matrix (I*H/4)
#define G0_F4    (4 * EXP_F4)        // experts 0-3, one projection

__global__ __launch_bounds__(256) void split_first_kernel(
    const float4* __restrict__ sg, const float4* __restrict__ su,
    const float4* __restrict__ gp, const float4* __restrict__ up)
{
    int i = blockIdx.x * blockDim.x + threadIdx.x;
    const int stride = gridDim.x * blockDim.x;
    const int total = 2 * EXP_F4 + 2 * G0_F4;
    for (; i < total; i += stride) {
        const float4* src; uint2* h16; int off;
        if (i < EXP_F4)              { src = sg; off = i;                     h16 = (uint2*)d_sg16; }
        else if (i < 2 * EXP_F4)     { src = su; off = i - EXP_F4;            h16 = (uint2*)d_su16; }
        else if (i < 2*EXP_F4+G0_F4) { src = gp; off = i - 2 * EXP_F4;        h16 = (uint2*)d_gp16; }
        else                         { src = up; off = i - 2 * EXP_F4 - G0_F4; h16 = (uint2*)d_up16; }
        float4 f = src[off];
        uint2 h; h.x = pack2(f.x, f.y); h.y = pack2(f.z, f.w);
        h16[off] = h;
    }
}

__global__ __launch_bounds__(256) void split_rest_kernel(
    const float4* __restrict__ gp, const float4* __restrict__ up)
{
    int i = blockIdx.x * blockDim.x + threadIdx.x;
    const int stride = gridDim.x * blockDim.x;
    const int per = 12 * EXP_F4;             // experts 4..15, one projection
    for (; i < 2 * per; i += stride) {
        const float4* src; uint2* h16; int off;
        if (i < per) { src = gp; off = G0_F4 + i;       h16 = (uint2*)d_gp16; }
        else         { src = up; off = G0_F4 + i - per; h16 = (uint2*)d_up16; }
        float4 f = src[off];
        uint2 h; h.x = pack2(f.x, f.y); h.y = pack2(f.z, f.w);
        h16[off] = h;
    }
}

#define DN_DP 8388608
#define DN_SD 8912896

__global__ __launch_bounds__(256) void split_dn_kernel(
    const float4* __restrict__ dp, const float4* __restrict__ sd)
{
    int i = blockIdx.x * blockDim.x + threadIdx.x;
    const int stride = gridDim.x * blockDim.x;
    for (; i < DN_SD; i += stride) {
        const float4* src; uint2* h16; int off;
        if (i < DN_DP) { src = dp; off = i;          h16 = (uint2*)d_dp16; }
        else           { src = sd; off = i - DN_DP;  h16 = (uint2*)d_sd16; }
        float4 f = src[off];
        uint2 h; h.x = pack2(f.x, f.y); h.y = pack2(f.z, f.w);
        h16[off] = h;
    }
}

__global__ __launch_bounds__(256) void zero_out_kernel(float4* __restrict__ out, int n4)
{
    int i = blockIdx.x * blockDim.x + threadIdx.x;
    int stride = gridDim.x * blockDim.x;
    float4 z = {0.f, 0.f, 0.f, 0.f};
    for (; i < n4; i += stride) out[i] = z;
}

__global__ void zero_counts_kernel() {
    if (threadIdx.x < N_EXP) d_counts[threadIdx.x] = 0;
}

// ---------------------------------------------------------------------------
// Routing + x fp32->fp16 conversion (fused, proven)
// ---------------------------------------------------------------------------
__global__ __launch_bounds__(256) void route_kernel(
    const float* __restrict__ x, const float* __restrict__ gw,
    const float* __restrict__ bias)
{
    __shared__ float xs[H_DIM];
    __shared__ float logits[N_EXP];
    const int t = blockIdx.x;
    const float* xr = x + (size_t)t * H_DIM;
    for (int i = threadIdx.x; i < H_DIM; i += blockDim.x) xs[i] = xr[i];
    __syncthreads();

    {
        uint32_t* dst = (uint32_t*)(d_x16 + (size_t)t * H_DIM);
        for (int i = threadIdx.x; i < H_DIM / 2; i += blockDim.x)
            dst[i] = pack2(xs[i * 2], xs[i * 2 + 1]);
    }

    const int e = threadIdx.x >> 4, lane = threadIdx.x & 15;
    const float* g = gw + (size_t)e * H_DIM;
    float s = 0.f;
    for (int k = lane; k < H_DIM; k += 16) s += xs[k] * g[k];
    #pragma unroll
    for (int o = 8; o > 0; o >>= 1) s += __shfl_down_sync(0xffffffffu, s, o, 16);
    if (lane == 0) logits[e] = s;
    __syncthreads();

    if (threadIdx.x == 0) {
        float sc[N_EXP], bs[N_EXP];
        #pragma unroll
        for (int i = 0; i < N_EXP; i++) {
            sc[i] = 1.f / (1.f + expf(-logits[i]));
            bs[i] = sc[i] + bias[i];
        }
        float gsc[NGRP];
        #pragma unroll
        for (int gi = 0; gi < NGRP; gi++) {
            float m1 = -1e30f, m2 = -1e30f;
            #pragma unroll
            for (int j = 0; j < GSZ; j++) {
                float v = bs[gi * GSZ + j];
                if (v > m1) { m2 = m1; m1 = v; } else if (v > m2) { m2 = v; }
            }
            gsc[gi] = m1 + m2;
        }
        int g1 = 0;
        for (int gi = 1; gi < NGRP; gi++) if (gsc[gi] > gsc[g1]) g1 = gi;
        int g2 = -1;
        for (int gi = 0; gi < NGRP; gi++) {
            if (gi == g1) continue;
            if (g2 < 0 || gsc[gi] > gsc[g2]) g2 = gi;
        }
        bool allowed[N_EXP], used[N_EXP];
        #pragma unroll
        for (int i = 0; i < N_EXP; i++) {
            int gi = i / GSZ;
            allowed[i] = (gi == g1 || gi == g2);
            used[i] = false;
        }
        int sel[TOPK]; float wv[TOPK]; float wsum = 0.f;
        #pragma unroll
        for (int kk = 0; kk < TOPK; kk++) {
            int best = -1; float bv = -1e30f;
            for (int i = 0; i < N_EXP; i++) {
                if (!allowed[i] || used[i]) continue;
                if (best < 0 || bs[i] > bv) { best = i; bv = bs[i]; }
            }
            used[best] = true; sel[kk] = best; wv[kk] = sc[best]; wsum += sc[best];
        }
        const float inv = SCALING / (wsum + 1e-20f);
        #pragma unroll
        for (int kk = 0; kk < TOPK; kk++) {
            int ee = sel[kk];
            int slot = atomicAdd(&d_counts[ee], 1);
            d_tok[ee][slot] = t;
            d_wgt[ee][slot] = wv[kk] * inv;
        }
    }
}

// ---------------------------------------------------------------------------
// GEMM1: 256 threads (8 warps = 4m x 2n), CTA tile M=128 x N=64 x BK=32.
// Warp tile 32m x 32n, dual output. 2 CTAs/SM. e = e_base + blockIdx.z
// (e_base=0, z=5 covers experts 0-3 + z==4 -> remapped to shared=16).
// Stage planes: A 0, G 10240, U 15360.
// ---------------------------------------------------------------------------
__global__ __launch_bounds__(256, 2) void gemm1_mma(int e_base, int shared_z)
{
    int e = e_base + blockIdx.z;
    if ((int)blockIdx.z == shared_z) e = N_EXP;
    const bool shared = (e == N_EXP);
    const int ne = shared ? T_TOK : d_counts[e];
    const int m0 = blockIdx.y * 128;
    if (m0 >= ne) return;
    const int n0 = blockIdx.x * 64;

    extern __shared__ __align__(16) char dynsmem[];
    __shared__ int toks[128];

    const int tid = threadIdx.x, lane = tid & 31, wid = tid >> 5;
    const int wm = wid >> 1, wn = wid & 1;
    const uint32_t sb = smem_u32(dynsmem);

    if (tid < 128) {
        int r = m0 + tid;
        toks[tid] = shared ? r : (r < ne ? d_tok[e][r] : d_tok[e][0]);
    }
    __syncthreads();

    const size_t eoff = shared ? 0 : (size_t)e * I_DIM * H_DIM;
    const __half* gP = shared ? d_sg16 : d_gp16 + eoff;
    const __half* uP = shared ? d_su16 : d_up16 + eoff;

    const int a0R = tid >> 2,          a0C = tid & 3;
    const int a1R = (tid + 256) >> 2,  a1C = tid & 3;
    const uint32_t dstA0 = (uint32_t)(a0R * 80 + a0C * 16);
    const uint32_t dstA1 = (uint32_t)(a1R * 80 + a1C * 16);
    const int bRr = tid >> 2, bCc = tid & 3;
    const uint32_t dstG = (uint32_t)(10240 + bRr * 80 + bCc * 16);
    const uint32_t dstU = dstG + 5120u;
    const __half* xPtr0 = d_x16 + (size_t)toks[a0R] * H_DIM + a0C * 8;
    const __half* xPtr1 = d_x16 + (size_t)toks[a1R] * H_DIM + a1C * 8;
    const __half* gPtr = gP + (size_t)(n0 + bRr) * H_DIM + bCc * 8;
    const __half* uPtr = uP + (size_t)(n0 + bRr) * H_DIM + bCc * 8;

    uint32_t rA[2], rG[2], rU[2];
    #pragma unroll
    for (int mi = 0; mi < 2; mi++)
        rA[mi] = ldrel(0u, wm * 32 + mi * 16, lane);
    #pragma unroll
    for (int j = 0; j < 2; j++) {
        rG[j] = ldrel(10240u, wn * 32 + j * 16, lane);
        rU[j] = ldrel(15360u, wn * 32 + j * 16, lane);
    }

    auto issue = [&](int kt) {
        const uint32_t st = sb + (uint32_t)(kt & 3) * STAGE_BYTES;
        CP_ASYNC16(st + dstA0, xPtr0); xPtr0 += 32;
        CP_ASYNC16(st + dstA1, xPtr1); xPtr1 += 32;
        CP_ASYNC16(st + dstG,  gPtr);  gPtr  += 32;
        CP_ASYNC16(st + dstU,  uPtr);  uPtr  += 32;
    };

    float cg[2][4][4] = {}, cu[2][4][4] = {};

    issue(0); CP_COMMIT();
    issue(1); CP_COMMIT();
    issue(2); CP_COMMIT();

    const int NK = H_DIM / 32;
    #pragma unroll 1
    for (int kt = 0; kt < NK; ++kt) {
        CP_WAIT2();
        __syncthreads();
        if (kt + 3 < NK) issue(kt + 3);
        CP_COMMIT();

        const uint32_t cur = sb + (uint32_t)(kt & 3) * STAGE_BYTES;
        #pragma unroll
        for (int kk = 0; kk < 2; ++kk) {
            const uint32_t kb = cur + (uint32_t)(kk * 32);
            uint32_t a[2][4], g0[4], g1[4], u0[4], u1[4];
            #pragma unroll
            for (int mi = 0; mi < 2; mi++)
                ldm_x4(kb + rA[mi], a[mi]);
            ldm_x4(kb + rG[0], g0); ldm_x4(kb + rG[1], g1);
            ldm_x4(kb + rU[0], u0); ldm_x4(kb + rU[1], u1);
            uint32_t bg[4][2] = {{g0[0],g0[2]},{g0[1],g0[3]},{g1[0],g1[2]},{g1[1],g1[3]}};
            uint32_t bu[4][2] = {{u0[0],u0[2]},{u0[1],u0[3]},{u1[0],u1[2]},{u1[1],u1[3]}};

            #pragma unroll
            for (int mi = 0; mi < 2; mi++)
                #pragma unroll
                for (int ni = 0; ni < 4; ni++)
                    mma_f16(cg[mi][ni], a[mi], bg[ni][0], bg[ni][1]);
            #pragma unroll
            for (int mi = 0; mi < 2; mi++)
                #pragma unroll
                for (int ni = 0; ni < 4; ni++)
                    mma_f16(cu[mi][ni], a[mi], bu[ni][0], bu[ni][1]);
        }
    }

    const int gr = lane >> 2, tc = (lane & 3) * 2;
    __half* ph = shared ? &d_h1s[0][0] : &d_h1[e][0][0];

    #pragma unroll
    for (int mi = 0; mi < 2; mi++)
        #pragma unroll
        for (int ni = 0; ni < 4; ni++) {
            int ncol = n0 + wn * 32 + ni * 8 + tc;
            #pragma unroll
            for (int half = 0; half < 2; half++) {
                int m = m0 + wm * 32 + mi * 16 + gr + half * 8;
                float g0 = cg[mi][ni][half * 2],     u0 = cu[mi][ni][half * 2];
                float g1 = cg[mi][ni][half * 2 + 1], u1 = cu[mi][ni][half * 2 + 1];
                float o0 = (g0 / (1.f + expf(-g0))) * u0;
                float o1 = (g1 / (1.f + expf(-g1))) * u1;
                *(uint32_t*)(ph + (size_t)m * I_DIM + ncol) = pack2(o0, o1);
            }
        }
}

// ---------------------------------------------------------------------------
// GEMM2: 256 threads (8 warps = 4m x 2n), CTA tile M=128 x N=128 x BK=32.
// Warp tile 32m x 64n. 2 CTAs/SM. Atomic scatter. (unchanged)
// ---------------------------------------------------------------------------
__global__ __launch_bounds__(256, 2) void gemm2_mma(float* __restrict__ out)
{
    const int e = blockIdx.z;
    const bool shared = (e == N_EXP);
    const int ne = shared ? T_TOK : d_counts[e];
    const int m0 = blockIdx.y * 128;
    if (m0 >= ne) return;
    const int n0 = blockIdx.x * 128;

    extern __shared__ __align__(16) char dynsmem[];
    __shared__ int   toks[128];
    __shared__ float wgts[128];

    const int tid = threadIdx.x, lane = tid & 31, wid = tid >> 5;
    const int wm = wid >> 1, wn = wid & 1;
    const uint32_t sb = smem_u32(dynsmem);

    if (tid < 128) {
        int r = m0 + tid;
        if (shared) { toks[tid] = r; wgts[tid] = 1.f; }
        else {
            toks[tid] = (r < ne) ? d_tok[e][r] : 0;
            wgts[tid] = (r < ne) ? d_wgt[e][r] : 0.f;
        }
    }
    __syncthreads();

    const __half* ah1 = shared ? &d_h1s[0][0] : &d_h1[e][0][0];
    const size_t eoff = shared ? 0 : (size_t)e * H_DIM * I_DIM;
    const __half* dw = shared ? d_sd16 : d_dp16 + eoff;

    const int a0R = tid >> 2,         a0C = tid & 3;
    const int a1R = (tid + 256) >> 2, a1C = tid & 3;
    const uint32_t dstA0 = (uint32_t)(a0R * 80 + a0C * 16);
    const uint32_t dstA1 = (uint32_t)(a1R * 80 + a1C * 16);
    const uint32_t dstB0 = dstA0 + 10240u;
    const uint32_t dstB1 = dstA1 + 10240u;
    const __half* aPtr0 = ah1 + (size_t)(m0 + a0R) * I_DIM + a0C * 8;
    const __half* aPtr1 = ah1 + (size_t)(m0 + a1R) * I_DIM + a1C * 8;
    const __half* bPtr0 = dw + (size_t)(n0 + a0R) * I_DIM + a0C * 8;
    const __half* bPtr1 = dw + (size_t)(n0 + a1R) * I_DIM + a1C * 8;

    uint32_t rA[2], rB[4];
    #pragma unroll
    for (int mi = 0; mi < 2; mi++)
        rA[mi] = ldrel(0u, wm * 32 + mi * 16, lane);
    #pragma unroll
    for (int j = 0; j < 4; j++)
        rB[j] = ldrel(10240u, wn * 64 + j * 16, lane);

    auto issue = [&](int kt) {
        const uint32_t st = sb + (uint32_t)(kt & 3) * STAGE_BYTES;
        CP_ASYNC16(st + dstA0, aPtr0); aPtr0 += 32;
        CP_ASYNC16(st + dstA1, aPtr1); aPtr1 += 32;
        CP_ASYNC16(st + dstB0, bPtr0); bPtr0 += 32;
        CP_ASYNC16(st + dstB1, bPtr1); bPtr1 += 32;
    };

    float cd[2][8][4] = {};

    issue(0); CP_COMMIT();
    issue(1); CP_COMMIT();
    issue(2); CP_COMMIT();

    const int NK = I_DIM / 32;
    #pragma unroll 1
    for (int kt = 0; kt < NK; ++kt) {
        CP_WAIT2();
        __syncthreads();
        if (kt + 3 < NK) issue(kt + 3);
        CP_COMMIT();

        const uint32_t cur = sb + (uint32_t)(kt & 3) * STAGE_BYTES;
        #pragma unroll
        for (int kk = 0; kk < 2; ++kk) {
            const uint32_t kb = cur + (uint32_t)(kk * 32);
            uint32_t a[2][4], h[4][4];
            #pragma unroll
            for (int mi = 0; mi < 2; mi++)
                ldm_x4(kb + rA[mi], a[mi]);
            #pragma unroll
            for (int j = 0; j < 4; j++)
                ldm_x4(kb + rB[j], h[j]);
            uint32_t bh[8][2];
            #pragma unroll
            for (int j = 0; j < 4; j++) {
                bh[j*2][0]   = h[j][0]; bh[j*2][1]   = h[j][2];
                bh[j*2+1][0] = h[j][1]; bh[j*2+1][1] = h[j][3];
            }
            #pragma unroll
            for (int mi = 0; mi < 2; mi++)
                #pragma unroll
                for (int ni = 0; ni < 8; ni++)
                    mma_f16(cd[mi][ni], a[mi], bh[ni][0], bh[ni][1]);
        }
    }

    const int gr = lane >> 2, tc = (lane & 3) * 2;
    #pragma unroll
    for (int mi = 0; mi < 2; mi++) {
        #pragma unroll
        for (int half = 0; half < 2; half++) {
            int mloc = wm * 32 + mi * 16 + gr + half * 8;
            if (m0 + mloc >= ne) continue;
            int   t = toks[mloc];
            float w = wgts[mloc];
            float* orow = out + (size_t)t * H_DIM;
            #pragma unroll
            for (int ni = 0; ni < 8; ni++) {
                int ncol = n0 + wn * 64 + ni * 8 + tc;
                atomicAdd(orow + ncol,     w * cd[mi][ni][half * 2]);
                atomicAdd(orow + ncol + 1, w * cd[mi][ni][half * 2 + 1]);
            }
        }
    }
}

// ---------------------------------------------------------------------------
// Launch — 2 streams + 4 events (within R14's proven resource budget):
//   s1: split_first (shared + experts 0-3) [eG0] -> split_rest [eGU]
//   default: zero_counts [eFork] -> route -> wait(eG0) -> gemm1 chunkA
//            -> wait(eGU) -> gemm1 chunkB -> wait(eDown) -> gemm2
//   s2: wait(eGU) -> split_dn -> zero_out [eDown]   (hidden under chunkB)
// ---------------------------------------------------------------------------
extern "C" void kernel_launch(void* const* d_in, const int* in_sizes, int n_in,
                              void* d_out, int out_size)
{
    const float* x  = (const float*)d_in[0];
    const float* gw = (const float*)d_in[1];
    const float* eb = (const float*)d_in[2];
    const float* gp = (const float*)d_in[3];
    const float* up = (const float*)d_in[4];
    const float* dp = (const float*)d_in[5];
    const float* sg = (const float*)d_in[6];
    const float* su = (const float*)d_in[7];
    const float* sd = (const float*)d_in[8];
    float* out = (float*)d_out;

    static cudaStream_t s1, s2;
    static cudaEvent_t eFork, eG0, eGU, eDown;
    static bool init = false;
    if (!init) {
        cudaFuncSetAttribute((const void*)gemm1_mma, cudaFuncAttributeMaxDynamicSharedMemorySize, SMEM_DYN);
        cudaFuncSetAttribute((const void*)gemm2_mma, cudaFuncAttributeMaxDynamicSharedMemorySize, SMEM_DYN);
        cudaStreamCreateWithFlags(&s1, cudaStreamNonBlocking);
        cudaStreamCreateWithFlags(&s2, cudaStreamNonBlocking);
        cudaEventCreateWithFlags(&eFork, cudaEventDisableTiming);
        cudaEventCreateWithFlags(&eG0,   cudaEventDisableTiming);
        cudaEventCreateWithFlags(&eGU,   cudaEventDisableTiming);
        cudaEventCreateWithFlags(&eDown, cudaEventDisableTiming);
        init = true;
    }

    // default: counters, fork
    zero_counts_kernel<<<1, 32>>>();
    cudaEventRecord(eFork, 0);

    // s1: two-phase gate/up conversion
    cudaStreamWaitEvent(s1, eFork, 0);
    split_first_kernel<<<1536, 256, 0, s1>>>((const float4*)sg, (const float4*)su,
                                             (const float4*)gp, (const float4*)up);
    cudaEventRecord(eG0, s1);
    split_rest_kernel<<<3072, 256, 0, s1>>>((const float4*)gp, (const float4*)up);
    cudaEventRecord(eGU, s1);

    // default: routing (+x conversion), concurrent with split_first
    route_kernel<<<T_TOK, 256>>>(x, gw, eb);

    // default: gemm1 chunk A (experts 0-3 + shared) after split_first
    cudaStreamWaitEvent(0, eG0, 0);
    gemm1_mma<<<dim3(I_DIM / 64, T_TOK / 128, 5), 256, SMEM_DYN>>>(0, 4);

    // default: gemm1 chunk B (experts 4-15) after split_rest
    cudaStreamWaitEvent(0, eGU, 0);
    gemm1_mma<<<dim3(I_DIM / 64, T_TOK / 128, 12), 256, SMEM_DYN>>>(4, -1);

    // s2: down conversion + output zeroing, hidden under gemm1 chunk B
    cudaStreamWaitEvent(s2, eGU, 0);
    split_dn_kernel<<<2048, 256, 0, s2>>>((const float4*)dp, (const float4*)sd);
    zero_out_kernel<<<1024, 256, 0, s2>>>((float4*)out, out_size / 4);
    cudaEventRecord(eDown, s2);

    // default: gemm2 after gemm1 chunks (stream order) and s2 (event)
    cudaStreamWaitEvent(0, eDown, 0);
    gemm2_mma<<<dim3(H_DIM / 128, T_TOK / 128, N_EXP + 1), 256, SMEM_DYN>>>(out);
}